// round 10
// baseline (speedup 1.0000x reference)
#include <cuda_runtime.h>
#include <cuda_fp16.h>
#include <math.h>
#include <stdint.h>

// Problem constants
#define BB 4
#define LL 1024
#define DD 1024
#define HH 16
#define DK 64
#define MTOT (BB * LL)          // 4096
#define NBL  (BB * LL)          // 4096
#define RS3  (3 * DD)           // 3072

// ---------------- scratch (static device memory; no allocations) -------------
__device__ float g_meanpart[16 * DD];
__device__ float g_partial[160];
__device__ float g_Gpart[8 * DD * DD];    // syrk split-K=8 partials
__device__ float g_Opart[2 * MTOT * DD];  // out-proj split-K=2 partials
__device__ float g_bqkv[3 * DD];

__device__ __align__(16) __half g_QKVh[MTOT * RS3];
__device__ __align__(16) __half g_QKVl[MTOT * RS3];
__device__ __align__(16) __half g_xh[MTOT * DD];
__device__ __align__(16) __half g_xl[MTOT * DD];
__device__ __align__(16) __half g_Mh[MTOT * DD];
__device__ __align__(16) __half g_Ml[MTOT * DD];
__device__ __align__(16) __half g_Mth[DD * NBL];
__device__ __align__(16) __half g_Mtl[DD * NBL];
__device__ __align__(16) __half g_Wqkvh[3 * DD * DD];
__device__ __align__(16) __half g_Woh[DD * DD];

// ---------------- small PTX helpers ------------------------------------------
__device__ __forceinline__ uint32_t smem_u32(const void* p) {
    uint32_t a;
    asm("{ .reg .u64 t; cvta.to.shared.u64 t, %1; cvt.u32.u64 %0, t; }"
        : "=r"(a) : "l"(p));
    return a;
}

__device__ __forceinline__ void cp_async16(uint32_t saddr, const void* gptr) {
    asm volatile("cp.async.ca.shared.global [%0], [%1], 16;"
                 :: "r"(saddr), "l"(gptr));
}
__device__ __forceinline__ void cp_commit() {
    asm volatile("cp.async.commit_group;" ::: "memory");
}
template <int N>
__device__ __forceinline__ void cp_wait() {
    asm volatile("cp.async.wait_group %0;" :: "n"(N) : "memory");
}

__device__ __forceinline__ void ldm_x4(uint32_t (&r)[4], uint32_t addr) {
    asm volatile("ldmatrix.sync.aligned.m8n8.x4.shared.b16 {%0,%1,%2,%3}, [%4];"
                 : "=r"(r[0]), "=r"(r[1]), "=r"(r[2]), "=r"(r[3]) : "r"(addr));
}
__device__ __forceinline__ void ldm_x4_trans(uint32_t (&r)[4], uint32_t addr) {
    asm volatile("ldmatrix.sync.aligned.m8n8.x4.trans.shared.b16 {%0,%1,%2,%3}, [%4];"
                 : "=r"(r[0]), "=r"(r[1]), "=r"(r[2]), "=r"(r[3]) : "r"(addr));
}

__device__ __forceinline__ void mma16816(float (&c)[4], const uint32_t (&a)[4],
                                         uint32_t b0, uint32_t b1) {
    asm volatile(
        "mma.sync.aligned.m16n8k16.row.col.f32.f16.f16.f32 "
        "{%0,%1,%2,%3}, {%4,%5,%6,%7}, {%8,%9}, {%0,%1,%2,%3};"
        : "+f"(c[0]), "+f"(c[1]), "+f"(c[2]), "+f"(c[3])
        : "r"(a[0]), "r"(a[1]), "r"(a[2]), "r"(a[3]), "r"(b0), "r"(b1));
}

__device__ __forceinline__ uint32_t pack_h2(__half x, __half y) {
    __half2 h = __halves2half2(x, y);
    return *(uint32_t*)&h;
}

struct __align__(8) half4 { __half a, b, c, d; };

// ---------------- prep mega-kernel: x split + weight rounds + bias concat ----
__global__ __launch_bounds__(256) void prep_kernel(
    const float* __restrict__ x,
    const float* __restrict__ Wq, const float* __restrict__ Wk,
    const float* __restrict__ Wv, const float* __restrict__ Wo,
    const float* __restrict__ bq, const float* __restrict__ bk,
    const float* __restrict__ bv,
    __half* __restrict__ xh, __half* __restrict__ xl,
    __half* __restrict__ Wqkvh, __half* __restrict__ Woh,
    float* __restrict__ bqkv)
{
    int t = blockIdx.x;
    int tid = threadIdx.x;
    if (t < 4096) {
        int i = t * 256 + tid;
        float4 v = ((const float4*)x)[i];
        __half h0 = __float2half_rn(v.x);
        __half h1 = __float2half_rn(v.y);
        __half h2 = __float2half_rn(v.z);
        __half h3 = __float2half_rn(v.w);
        half4 hv = {h0, h1, h2, h3};
        half4 lv = {__float2half_rn(v.x - __half2float(h0)),
                    __float2half_rn(v.y - __half2float(h1)),
                    __float2half_rn(v.z - __half2float(h2)),
                    __float2half_rn(v.w - __half2float(h3))};
        ((half4*)xh)[i] = hv;
        ((half4*)xl)[i] = lv;
    } else if (t < 8192) {
        int wsel = (t - 4096) >> 10;
        int blk = (t - 4096) & 1023;
        const float* src = (wsel == 0) ? Wq : (wsel == 1) ? Wk
                         : (wsel == 2) ? Wv : Wo;
        __half* dst = (wsel < 3) ? (Wqkvh + (size_t)wsel * DD * DD) : Woh;
        int i = blk * 256 + tid;
        float4 v = ((const float4*)src)[i];
        half4 hv = {__float2half_rn(v.x), __float2half_rn(v.y),
                    __float2half_rn(v.z), __float2half_rn(v.w)};
        ((half4*)dst)[i] = hv;
    } else {
        int i = (t - 8192) * 256 + tid;
        if (i < RS3) {
            const float* src = (i < DD) ? bq : (i < 2 * DD) ? bk : bv;
            bqkv[i] = src[i & (DD - 1)];
        }
    }
}

// ---------------- GEMM body ---------------------------------------------------
#define GPITCH 144
#define GTILE  (128 * GPITCH)
#define GBUF   (2 * GTILE)
#define GSMEM  (3 * GBUF)       // 110592 B

__device__ __forceinline__ void gemm_body(
    const __half* __restrict__ Ah, const __half* __restrict__ Al,
    const __half* __restrict__ Bh, const float* __restrict__ bias,
    float* __restrict__ C, float* __restrict__ Cpart,
    __half* __restrict__ Ch, __half* __restrict__ Cl,
    float qscale, int qcols,
    int lda, int Ksl, int N, int M,
    int bx, int by, int split, int nsplit, char* smem)
{
    const uint32_t sbase = smem_u32(smem);
    const int tid = threadIdx.x;
    const int lane = tid & 31;
    const int wid = tid >> 5;
    const int wm = wid >> 2;
    const int wn = wid & 3;

    const __half* pA[2] = {Ah, Al};
    const int Kc = Ksl >> 6;
    const int total = 2 * Kc;

    float c[4][4][4];
#pragma unroll
    for (int i = 0; i < 4; i++)
#pragma unroll
        for (int j = 0; j < 4; j++)
#pragma unroll
            for (int f = 0; f < 4; f++) c[i][j][f] = 0.0f;

    auto load_chunk = [&](int g, int buf) {
        int p = (g >= Kc) ? 1 : 0;
        int kk = g - p * Kc;
        const __half* Abase = pA[p] + (size_t)by * 128 * lda + split * Ksl + kk * 64;
        const __half* Bbase = Bh + (size_t)bx * 128 * lda + split * Ksl + kk * 64;
        uint32_t aS = sbase + buf * GBUF;
        uint32_t bS = aS + GTILE;
#pragma unroll
        for (int j = 0; j < 4; j++) {
            int lin = tid + j * 256;
            int row = lin >> 3;
            int seg = lin & 7;
            cp_async16(aS + row * GPITCH + seg * 16,
                       Abase + (size_t)row * lda + seg * 8);
            cp_async16(bS + row * GPITCH + seg * 16,
                       Bbase + (size_t)row * lda + seg * 8);
        }
        cp_commit();
    };

    load_chunk(0, 0);
    load_chunk(1, 1);

    int buf = 0;
    for (int g = 0; g < total; g++) {
        if (g == total - 1) cp_wait<0>(); else cp_wait<1>();
        __syncthreads();
        if (g + 2 < total) {
            int nb = buf + 2; if (nb >= 3) nb -= 3;
            load_chunk(g + 2, nb);
        }

        const uint32_t aS = sbase + buf * GBUF;
        const uint32_t bS = aS + GTILE;
#pragma unroll
        for (int s = 0; s < 4; s++) {
            uint32_t a[4][4];
#pragma unroll
            for (int i = 0; i < 4; i++) {
                int row = wm * 64 + i * 16 + (lane & 15);
                ldm_x4(a[i], aS + row * GPITCH + s * 32 + ((lane >> 4) * 16));
            }
            uint32_t b[2][4];
#pragma unroll
            for (int j = 0; j < 2; j++) {
                int row = wn * 32 + j * 16 + ((lane >> 4) << 3) + (lane & 7);
                int off = ((lane >> 3) & 1) * 16;
                ldm_x4(b[j], bS + row * GPITCH + s * 32 + off);
            }
#pragma unroll
            for (int i = 0; i < 4; i++) {
#pragma unroll
                for (int j = 0; j < 2; j++) {
                    mma16816(c[i][2 * j], a[i], b[j][0], b[j][1]);
                    mma16816(c[i][2 * j + 1], a[i], b[j][2], b[j][3]);
                }
            }
        }
        if (++buf == 3) buf = 0;
    }

    const bool addb = (bias != nullptr) && (nsplit == 1);
#pragma unroll
    for (int i = 0; i < 4; i++) {
        int r0 = by * 128 + wm * 64 + i * 16 + (lane >> 2);
#pragma unroll
        for (int nt = 0; nt < 4; nt++) {
            int col = bx * 128 + wn * 32 + nt * 8 + (lane & 3) * 2;
            float bx0 = 0.0f, bx1 = 0.0f;
            if (addb) { bx0 = bias[col]; bx1 = bias[col + 1]; }
            float a0 = c[i][nt][0] + bx0, a1 = c[i][nt][1] + bx1;
            float a2 = c[i][nt][2] + bx0, a3 = c[i][nt][3] + bx1;
            if (Ch) {
                float sc = (col < qcols) ? qscale : 1.0f;
                a0 *= sc; a1 *= sc; a2 *= sc; a3 *= sc;
                __half h0 = __float2half_rn(a0), h1 = __float2half_rn(a1);
                __half h2 = __float2half_rn(a2), h3 = __float2half_rn(a3);
                *(__half2*)(Ch + (size_t)r0 * N + col) = __halves2half2(h0, h1);
                *(__half2*)(Ch + (size_t)(r0 + 8) * N + col) = __halves2half2(h2, h3);
                *(__half2*)(Cl + (size_t)r0 * N + col) =
                    __halves2half2(__float2half_rn(a0 - __half2float(h0)),
                                   __float2half_rn(a1 - __half2float(h1)));
                *(__half2*)(Cl + (size_t)(r0 + 8) * N + col) =
                    __halves2half2(__float2half_rn(a2 - __half2float(h2)),
                                   __float2half_rn(a3 - __half2float(h3)));
            } else {
                float* dst = (nsplit == 1) ? C : (Cpart + (size_t)split * M * N);
                float2 v0 = {a0, a1}, v1 = {a2, a3};
                *(float2*)(dst + (size_t)r0 * N + col) = v0;
                *(float2*)(dst + (size_t)(r0 + 8) * N + col) = v1;
            }
        }
    }
}

// ---------------- QKV GEMM kernel --------------------------------------------
__global__ __launch_bounds__(256, 2) void gemm2(
    const __half* __restrict__ Ah, const __half* __restrict__ Al,
    const __half* __restrict__ Bh, const float* __restrict__ bias,
    __half* __restrict__ Ch, __half* __restrict__ Cl,
    float qscale, int qcols, int lda, int Ksl, int N)
{
    extern __shared__ __align__(16) char smem[];
    gemm_body(Ah, Al, Bh, bias, nullptr, nullptr, Ch, Cl, qscale, qcols,
              lda, Ksl, N, gridDim.y * 128,
              blockIdx.x, blockIdx.y, 0, 1, smem);
}

// ---------------- fused mid: out-proj sk2 + symmetric SYRK sk8 + colmean -----
// grid: 512 out-proj | 288 syrk (36 tri-tiles x 8 splits) | 64 colmean = 864
__global__ __launch_bounds__(256, 2) void fused_mid(
    const __half* __restrict__ Mh, const __half* __restrict__ Ml,
    const __half* __restrict__ Woh,
    float* __restrict__ Opart,
    const __half* __restrict__ Mth, const __half* __restrict__ Mtl,
    float* __restrict__ Gpart, float* __restrict__ meanpart)
{
    extern __shared__ __align__(16) char smem[];
    int t = blockIdx.x;
    if (t < 512) {
        // out projection split-K=2
        gemm_body(Mh, Ml, Woh, nullptr, nullptr, Opart, nullptr, nullptr,
                  1.0f, 0, DD, DD / 2, DD, MTOT,
                  t & 7, (t >> 3) & 31, t >> 8, 2, smem);
    } else if (t < 800) {
        int t2 = t - 512;
        int split = t2 / 36;
        int pair = t2 % 36;
        int ti = 0, s = pair;
        while (s >= 8 - ti) { s -= 8 - ti; ti++; }
        int tj = ti + s;
        gemm_body(Mth, Mtl, Mth, nullptr, nullptr, Gpart, nullptr, nullptr,
                  1.0f, 0, NBL, NBL / 8, DD, DD,
                  tj, ti, split, 8, smem);
    } else {
        int idx = t - 800;
        int col = (idx & 3) * 256 + threadIdx.x;
        int seg = idx >> 2;
        float s = 0.0f;
        size_t base = (size_t)seg * 256 * DD + col;
#pragma unroll 4
        for (int r = 0; r < 256; r++) {
            size_t o = base + (size_t)r * DD;
            s += __half2float(Mh[o]) + __half2float(Ml[o]);
        }
        meanpart[seg * DD + col] = s;
    }
}

// ---------------- fused fin: out reduce+bias | decov tiles -------------------
// grid: 4096 out-reduce | 144 decov (36 pairs x 4 row-quarters)
__global__ __launch_bounds__(256) void fused_fin(
    const float* __restrict__ Opart, const float* __restrict__ bo,
    float* __restrict__ out,
    const float* __restrict__ Gpart, const float* __restrict__ meanpart,
    float* __restrict__ partial)
{
    __shared__ float smrow[32];
    __shared__ float smcol[128];
    __shared__ float red[256];
    int t = blockIdx.x;
    if (t < 4096) {
        int i = t * 256 + threadIdx.x;          // float4 idx over MTOT*DD/4
        float4 s = ((const float4*)Opart)[i];
        float4 v = ((const float4*)(Opart + (size_t)MTOT * DD))[i];
        s.x += v.x; s.y += v.y; s.z += v.z; s.w += v.w;
        int col = (i * 4) & (DD - 1);
        float4 bv = *(const float4*)(bo + col);
        s.x += bv.x; s.y += bv.y; s.z += bv.z; s.w += bv.w;
        ((float4*)out)[i] = s;
        return;
    }
    // decov tile
    int bt = t - 4096;          // 0..143
    int pair = bt % 36;
    int q = bt / 36;
    int ti = 0, s0 = pair;
    while (s0 >= 8 - ti) { s0 -= 8 - ti; ti++; }
    int tj = ti + s0;
    const float w = (ti == tj) ? 1.0f : 2.0f;
    const float invN = 1.0f / (float)NBL;

    // compute needed means inline from meanpart
    if (threadIdx.x < 160) {
        bool isRow = threadIdx.x < 32;
        int col = isRow ? (ti * 128 + q * 32 + threadIdx.x)
                        : (tj * 128 + threadIdx.x - 32);
        float ms = 0.0f;
#pragma unroll
        for (int seg = 0; seg < 16; seg++) ms += meanpart[seg * DD + col];
        ms *= invN;
        if (isRow) smrow[threadIdx.x] = ms;
        else smcol[threadIdx.x - 32] = ms;
    }
    __syncthreads();

    int row = ti * 128 + q * 32 + (threadIdx.x >> 3);
    int c0 = tj * 128 + (threadIdx.x & 7) * 16;
    float mi = smrow[threadIdx.x >> 3];
    float acc = 0.0f;
    size_t base = (size_t)row * DD + c0;
#pragma unroll
    for (int c4 = 0; c4 < 4; c4++) {
        int col = c0 + c4 * 4;
        float4 g = *(const float4*)(Gpart + base + c4 * 4);
#pragma unroll
        for (int p = 1; p < 8; p++) {
            float4 v = *(const float4*)(Gpart + (size_t)p * DD * DD + base + c4 * 4);
            g.x += v.x; g.y += v.y; g.z += v.z; g.w += v.w;
        }
        int lc = col - tj * 128;
        float cx = g.x * invN - mi * smcol[lc];
        float cy = g.y * invN - mi * smcol[lc + 1];
        float cz = g.z * invN - mi * smcol[lc + 2];
        float cw = g.w * invN - mi * smcol[lc + 3];
        if (row == col) cx = 0.0f;
        if (row == col + 1) cy = 0.0f;
        if (row == col + 2) cz = 0.0f;
        if (row == col + 3) cw = 0.0f;
        acc += cx * cx + cy * cy + cz * cz + cw * cw;
    }
    red[threadIdx.x] = acc * w;
    __syncthreads();
    for (int off = 128; off > 0; off >>= 1) {
        if (threadIdx.x < off) red[threadIdx.x] += red[threadIdx.x + off];
        __syncthreads();
    }
    if (threadIdx.x == 0) partial[bt] = red[0];
}

__global__ void decov_final(const float* __restrict__ partial, float* __restrict__ out)
{
    if (threadIdx.x == 0) {
        float t = 0.0f;
        for (int i = 0; i < 144; i++) t += partial[i];
        out[0] = 0.5f * t;
    }
}

// ---------------- Attention: flash + mma.sync, fp16 inputs, cp.async ring ----
#define AP 72
#define APB 144
#define KTB (64 * APB)
#define ASTG (3 * KTB)
#define ASMEM (3 * ASTG)        // 82944 B

__global__ __launch_bounds__(256, 2) void attn_mma(
    const __half* __restrict__ QKVh, const __half* __restrict__ QKVl,
    __half* __restrict__ Oh, __half* __restrict__ Ol)
{
    extern __shared__ __align__(16) char smem[];
    const uint32_t sbase = smem_u32(smem);

    const int tid = threadIdx.x;
    const int lane = tid & 31;
    const int w = tid >> 5;
    const int q0 = blockIdx.x * 128;
    const int h = blockIdx.y;
    const int b = blockIdx.z;

    uint32_t Qah[4][4], Qal[4][4];
    {
        int r0 = b * LL + q0 + w * 16 + (lane >> 2);
        int cb = h * DK + (lane & 3) * 2;
#pragma unroll
        for (int s = 0; s < 4; s++)
#pragma unroll
            for (int t2 = 0; t2 < 4; t2++) {
                size_t off = (size_t)(r0 + (t2 & 1) * 8) * RS3 + cb + s * 16 + (t2 >> 1) * 8;
                Qah[s][t2] = *(const uint32_t*)(QKVh + off);
                Qal[s][t2] = *(const uint32_t*)(QKVl + off);
            }
    }

    auto load_tile = [&](int kt, int stg) {
        uint32_t sb = sbase + stg * ASTG;
#pragma unroll
        for (int it = 0; it < 2; it++) {
            int lin = tid + it * 256;
            int row = lin >> 3;
            int seg = lin & 7;
            size_t goff = (size_t)(b * LL + kt + row) * RS3 + DD + h * DK + seg * 8;
            cp_async16(sb + row * APB + seg * 16, QKVh + goff);
            cp_async16(sb + KTB + row * APB + seg * 16, QKVl + goff);
            cp_async16(sb + 2 * KTB + row * APB + seg * 16, QKVh + goff + DD);
        }
        cp_commit();
    };

    float m0 = -1e30f, m1 = -1e30f, l0 = 0.0f, l1 = 0.0f;
    float co[8][4];
#pragma unroll
    for (int j = 0; j < 8; j++)
#pragma unroll
        for (int f = 0; f < 4; f++) co[j][f] = 0.0f;

    load_tile(0, 0);
    load_tile(64, 1);

    int buf = 0;
    for (int g = 0; g < 16; g++) {
        if (g == 15) cp_wait<0>(); else cp_wait<1>();
        __syncthreads();
        if (g + 2 < 16) {
            int nb = buf + 2; if (nb >= 3) nb -= 3;
            load_tile((g + 2) * 64, nb);
        }
        const uint32_t khs = sbase + buf * ASTG;
        const uint32_t kls = khs + KTB;
        const uint32_t vhs = khs + 2 * KTB;

        float sc[8][4];
#pragma unroll
        for (int j = 0; j < 8; j++)
#pragma unroll
            for (int f = 0; f < 4; f++) sc[j][f] = 0.0f;

#pragma unroll
        for (int s = 0; s < 4; s++) {
#pragma unroll
            for (int j = 0; j < 4; j++) {
                uint32_t roff = (j * 16 + ((lane >> 4) << 3) + (lane & 7)) * APB
                              + s * 32 + ((lane >> 3) & 1) * 16;
                uint32_t bh[4], bl[4];
                ldm_x4(bh, khs + roff);
                ldm_x4(bl, kls + roff);
                mma16816(sc[2 * j],     Qah[s], bh[0], bh[1]);
                mma16816(sc[2 * j + 1], Qah[s], bh[2], bh[3]);
                mma16816(sc[2 * j],     Qal[s], bh[0], bh[1]);
                mma16816(sc[2 * j + 1], Qal[s], bh[2], bh[3]);
                mma16816(sc[2 * j],     Qah[s], bl[0], bl[1]);
                mma16816(sc[2 * j + 1], Qah[s], bl[2], bl[3]);
            }
        }

        float t0 = -1e30f, t1 = -1e30f;
#pragma unroll
        for (int j = 0; j < 8; j++) {
            t0 = fmaxf(t0, fmaxf(sc[j][0], sc[j][1]));
            t1 = fmaxf(t1, fmaxf(sc[j][2], sc[j][3]));
        }
        t0 = fmaxf(t0, __shfl_xor_sync(0xffffffffu, t0, 1));
        t0 = fmaxf(t0, __shfl_xor_sync(0xffffffffu, t0, 2));
        t1 = fmaxf(t1, __shfl_xor_sync(0xffffffffu, t1, 1));
        t1 = fmaxf(t1, __shfl_xor_sync(0xffffffffu, t1, 2));
        float mn0 = fmaxf(m0, t0), mn1 = fmaxf(m1, t1);
        float f0 = __expf(m0 - mn0), f1 = __expf(m1 - mn1);
        float rs0 = 0.0f, rs1 = 0.0f;
#pragma unroll
        for (int j = 0; j < 8; j++) {
            sc[j][0] = __expf(sc[j][0] - mn0);
            sc[j][1] = __expf(sc[j][1] - mn0);
            sc[j][2] = __expf(sc[j][2] - mn1);
            sc[j][3] = __expf(sc[j][3] - mn1);
            rs0 += sc[j][0] + sc[j][1];
            rs1 += sc[j][2] + sc[j][3];
        }
        rs0 += __shfl_xor_sync(0xffffffffu, rs0, 1);
        rs0 += __shfl_xor_sync(0xffffffffu, rs0, 2);
        rs1 += __shfl_xor_sync(0xffffffffu, rs1, 1);
        rs1 += __shfl_xor_sync(0xffffffffu, rs1, 2);
        l0 = l0 * f0 + rs0;
        l1 = l1 * f1 + rs1;
        m0 = mn0; m1 = mn1;
#pragma unroll
        for (int j = 0; j < 8; j++) {
            co[j][0] *= f0; co[j][1] *= f0;
            co[j][2] *= f1; co[j][3] *= f1;
        }

#pragma unroll
        for (int s = 0; s < 4; s++) {
            uint32_t pah[4], pal[4];
#pragma unroll
            for (int t2 = 0; t2 < 4; t2++) {
                int bk = 2 * s + (t2 >> 1);
                float p0 = sc[bk][(t2 & 1) * 2];
                float p1 = sc[bk][(t2 & 1) * 2 + 1];
                __half h0 = __float2half_rn(p0), h1 = __float2half_rn(p1);
                pah[t2] = pack_h2(h0, h1);
                pal[t2] = pack_h2(__float2half_rn(p0 - __half2float(h0)),
                                  __float2half_rn(p1 - __half2float(h1)));
            }
#pragma unroll
            for (int j = 0; j < 4; j++) {
                uint32_t roff = (s * 16 + ((lane >> 3) & 1) * 8 + (lane & 7)) * APB
                              + (j * 16 + ((lane >> 4) & 1) * 8) * 2;
                uint32_t vbh[4];
                ldm_x4_trans(vbh, vhs + roff);
                mma16816(co[2 * j],     pah, vbh[0], vbh[1]);
                mma16816(co[2 * j + 1], pah, vbh[2], vbh[3]);
                mma16816(co[2 * j],     pal, vbh[0], vbh[1]);
                mma16816(co[2 * j + 1], pal, vbh[2], vbh[3]);
            }
        }
        if (++buf == 3) buf = 0;
    }

    float inv0 = 1.0f / l0, inv1 = 1.0f / l1;
    int grow = q0 + w * 16 + (lane >> 2);
    size_t base0 = (size_t)(b * LL + grow) * DD + h * DK;
    size_t base1 = base0 + (size_t)8 * DD;
#pragma unroll
    for (int j = 0; j < 8; j++) {
        int col = j * 8 + (lane & 3) * 2;
        float a0 = co[j][0] * inv0, a1 = co[j][1] * inv0;
        float a2 = co[j][2] * inv1, a3 = co[j][3] * inv1;
        __half h0 = __float2half_rn(a0), h1 = __float2half_rn(a1);
        __half h2 = __float2half_rn(a2), h3 = __float2half_rn(a3);
        *(__half2*)(Oh + base0 + col) = __halves2half2(h0, h1);
        *(__half2*)(Oh + base1 + col) = __halves2half2(h2, h3);
        *(__half2*)(Ol + base0 + col) =
            __halves2half2(__float2half_rn(a0 - __half2float(h0)),
                           __float2half_rn(a1 - __half2float(h1)));
        *(__half2*)(Ol + base1 + col) =
            __halves2half2(__float2half_rn(a2 - __half2float(h2)),
                           __float2half_rn(a3 - __half2float(h3)));
    }
}

// ---------------- transpose + split: (Mh+Ml)[NBL][DD] -> T[DD][NBL] ----------
__global__ __launch_bounds__(256) void transpose_split_fp16(
    const __half* __restrict__ Msh, const __half* __restrict__ Msl,
    __half* __restrict__ Th, __half* __restrict__ Tl)
{
    __shared__ float tile[32][33];
    int bx = blockIdx.x;
    int by = blockIdx.y;
    int tx = threadIdx.x;
    int ty = threadIdx.y;
#pragma unroll
    for (int j = 0; j < 32; j += 8) {
        size_t off = (size_t)(by * 32 + ty + j) * DD + bx * 32 + tx;
        tile[ty + j][tx] = __half2float(Msh[off]) + __half2float(Msl[off]);
    }
    __syncthreads();
#pragma unroll
    for (int j = 0; j < 32; j += 8) {
        float v = tile[tx][ty + j];
        __half h = __float2half_rn(v);
        __half l = __float2half_rn(v - __half2float(h));
        size_t off = (size_t)(bx * 32 + ty + j) * NBL + by * 32 + tx;
        Th[off] = h;
        Tl[off] = l;
    }
}

// ---------------- launch ------------------------------------------------------
extern "C" void kernel_launch(void* const* d_in, const int* in_sizes, int n_in,
                              void* d_out, int out_size)
{
    const float* x  = (const float*)d_in[0];
    const float* Wq = (const float*)d_in[1];
    const float* bq = (const float*)d_in[2];
    const float* Wk = (const float*)d_in[3];
    const float* bk = (const float*)d_in[4];
    const float* Wv = (const float*)d_in[5];
    const float* bv = (const float*)d_in[6];
    const float* Wo = (const float*)d_in[7];
    const float* bo = (const float*)d_in[8];
    float* out = (float*)d_out;

    float *meanpartp, *partp, *Gpart, *Opart, *bqkv;
    cudaGetSymbolAddress((void**)&meanpartp, g_meanpart);
    cudaGetSymbolAddress((void**)&partp, g_partial);
    cudaGetSymbolAddress((void**)&Gpart, g_Gpart);
    cudaGetSymbolAddress((void**)&Opart, g_Opart);
    cudaGetSymbolAddress((void**)&bqkv, g_bqkv);

    __half *QKVh, *QKVl, *xh, *xl, *Mh, *Ml, *Mth, *Mtl, *Wqkvh, *Woh;
    cudaGetSymbolAddress((void**)&QKVh, g_QKVh);
    cudaGetSymbolAddress((void**)&QKVl, g_QKVl);
    cudaGetSymbolAddress((void**)&xh, g_xh);
    cudaGetSymbolAddress((void**)&xl, g_xl);
    cudaGetSymbolAddress((void**)&Mh, g_Mh);
    cudaGetSymbolAddress((void**)&Ml, g_Ml);
    cudaGetSymbolAddress((void**)&Mth, g_Mth);
    cudaGetSymbolAddress((void**)&Mtl, g_Mtl);
    cudaGetSymbolAddress((void**)&Wqkvh, g_Wqkvh);
    cudaGetSymbolAddress((void**)&Woh, g_Woh);

    cudaFuncSetAttribute(gemm2, cudaFuncAttributeMaxDynamicSharedMemorySize,
                         GSMEM);
    cudaFuncSetAttribute(fused_mid, cudaFuncAttributeMaxDynamicSharedMemorySize,
                         GSMEM);
    cudaFuncSetAttribute(attn_mma, cudaFuncAttributeMaxDynamicSharedMemorySize,
                         ASMEM);

    // 1. prep
    prep_kernel<<<8204, 256>>>(x, Wq, Wk, Wv, Wo, bq, bk, bv,
                               xh, xl, Wqkvh, Woh, bqkv);

    // 2. fused QKV projection
    dim3 gQKV(RS3 / 128, MTOT / 128, 1);
    gemm2<<<gQKV, 256, GSMEM>>>(xh, xl, Wqkvh, bqkv,
                                QKVh, QKVl, 0.125f, DD, DD, DD, RS3);

    // 3. attention
    dim3 gAttn(LL / 128, HH, BB);
    attn_mma<<<gAttn, 256, ASMEM>>>(QKVh, QKVl, Mh, Ml);

    // 4. transposed split of M
    transpose_split_fp16<<<dim3(DD / 32, NBL / 32), dim3(32, 8)>>>(Mh, Ml, Mth, Mtl);

    // 5. fused: out-proj sk2 (512) + SYRK sk8 (288) + colmean-part (64)
    fused_mid<<<864, 256, GSMEM>>>(Mh, Ml, Woh, Opart,
                                   Mth, Mtl, Gpart, meanpartp);

    // 6. fused: out reduce+bias (4096) + decov tiles (144)
    fused_fin<<<4240, 256>>>(Opart, bo, out, Gpart, meanpartp, partp);

    // 7. final scalar
    decov_final<<<1, 32>>>(partp, out + (out_size - 1));
}

// round 11
// speedup vs baseline: 1.0243x; 1.0243x over previous
#include <cuda_runtime.h>
#include <cuda_fp16.h>
#include <math.h>
#include <stdint.h>

// Problem constants
#define BB 4
#define LL 1024
#define DD 1024
#define HH 16
#define DK 64
#define MTOT (BB * LL)          // 4096
#define NBL  (BB * LL)          // 4096
#define RS3  (3 * DD)           // 3072

// ---------------- scratch (static device memory; no allocations) -------------
__device__ float g_meanpart[16 * DD];
__device__ float g_partial[160];
__device__ float g_Gpart[8 * DD * DD];    // syrk split-K=8 partials
__device__ float g_bqkv[3 * DD];

__device__ __align__(16) __half g_QKVh[MTOT * RS3];
__device__ __align__(16) __half g_QKVl[MTOT * RS3];
__device__ __align__(16) __half g_xh[MTOT * DD];
__device__ __align__(16) __half g_xl[MTOT * DD];
__device__ __align__(16) __half g_Mh[MTOT * DD];
__device__ __align__(16) __half g_Ml[MTOT * DD];
__device__ __align__(16) __half g_Mth[DD * NBL];
__device__ __align__(16) __half g_Mtl[DD * NBL];
__device__ __align__(16) __half g_Wqkvh[3 * DD * DD];
__device__ __align__(16) __half g_Woh[DD * DD];

// ---------------- small PTX helpers ------------------------------------------
__device__ __forceinline__ uint32_t smem_u32(const void* p) {
    uint32_t a;
    asm("{ .reg .u64 t; cvta.to.shared.u64 t, %1; cvt.u32.u64 %0, t; }"
        : "=r"(a) : "l"(p));
    return a;
}

__device__ __forceinline__ void cp_async16(uint32_t saddr, const void* gptr) {
    asm volatile("cp.async.ca.shared.global [%0], [%1], 16;"
                 :: "r"(saddr), "l"(gptr));
}
__device__ __forceinline__ void cp_commit() {
    asm volatile("cp.async.commit_group;" ::: "memory");
}
template <int N>
__device__ __forceinline__ void cp_wait() {
    asm volatile("cp.async.wait_group %0;" :: "n"(N) : "memory");
}

__device__ __forceinline__ void ldm_x4(uint32_t (&r)[4], uint32_t addr) {
    asm volatile("ldmatrix.sync.aligned.m8n8.x4.shared.b16 {%0,%1,%2,%3}, [%4];"
                 : "=r"(r[0]), "=r"(r[1]), "=r"(r[2]), "=r"(r[3]) : "r"(addr));
}
__device__ __forceinline__ void ldm_x4_trans(uint32_t (&r)[4], uint32_t addr) {
    asm volatile("ldmatrix.sync.aligned.m8n8.x4.trans.shared.b16 {%0,%1,%2,%3}, [%4];"
                 : "=r"(r[0]), "=r"(r[1]), "=r"(r[2]), "=r"(r[3]) : "r"(addr));
}

__device__ __forceinline__ void mma16816(float (&c)[4], const uint32_t (&a)[4],
                                         uint32_t b0, uint32_t b1) {
    asm volatile(
        "mma.sync.aligned.m16n8k16.row.col.f32.f16.f16.f32 "
        "{%0,%1,%2,%3}, {%4,%5,%6,%7}, {%8,%9}, {%0,%1,%2,%3};"
        : "+f"(c[0]), "+f"(c[1]), "+f"(c[2]), "+f"(c[3])
        : "r"(a[0]), "r"(a[1]), "r"(a[2]), "r"(a[3]), "r"(b0), "r"(b1));
}

__device__ __forceinline__ uint32_t pack_h2(__half x, __half y) {
    __half2 h = __halves2half2(x, y);
    return *(uint32_t*)&h;
}

struct __align__(8) half4 { __half a, b, c, d; };

// ---------------- prep mega-kernel: x split + weight rounds + bias concat ----
__global__ __launch_bounds__(256) void prep_kernel(
    const float* __restrict__ x,
    const float* __restrict__ Wq, const float* __restrict__ Wk,
    const float* __restrict__ Wv, const float* __restrict__ Wo,
    const float* __restrict__ bq, const float* __restrict__ bk,
    const float* __restrict__ bv,
    __half* __restrict__ xh, __half* __restrict__ xl,
    __half* __restrict__ Wqkvh, __half* __restrict__ Woh,
    float* __restrict__ bqkv)
{
    int t = blockIdx.x;
    int tid = threadIdx.x;
    if (t < 4096) {
        int i = t * 256 + tid;
        float4 v = ((const float4*)x)[i];
        __half h0 = __float2half_rn(v.x);
        __half h1 = __float2half_rn(v.y);
        __half h2 = __float2half_rn(v.z);
        __half h3 = __float2half_rn(v.w);
        half4 hv = {h0, h1, h2, h3};
        half4 lv = {__float2half_rn(v.x - __half2float(h0)),
                    __float2half_rn(v.y - __half2float(h1)),
                    __float2half_rn(v.z - __half2float(h2)),
                    __float2half_rn(v.w - __half2float(h3))};
        ((half4*)xh)[i] = hv;
        ((half4*)xl)[i] = lv;
    } else if (t < 8192) {
        int wsel = (t - 4096) >> 10;
        int blk = (t - 4096) & 1023;
        const float* src = (wsel == 0) ? Wq : (wsel == 1) ? Wk
                         : (wsel == 2) ? Wv : Wo;
        __half* dst = (wsel < 3) ? (Wqkvh + (size_t)wsel * DD * DD) : Woh;
        int i = blk * 256 + tid;
        float4 v = ((const float4*)src)[i];
        half4 hv = {__float2half_rn(v.x), __float2half_rn(v.y),
                    __float2half_rn(v.z), __float2half_rn(v.w)};
        ((half4*)dst)[i] = hv;
    } else {
        int i = (t - 8192) * 256 + tid;
        if (i < RS3) {
            const float* src = (i < DD) ? bq : (i < 2 * DD) ? bk : bv;
            bqkv[i] = src[i & (DD - 1)];
        }
    }
}

// ---------------- GEMM body ---------------------------------------------------
#define GPITCH 144
#define GTILE  (128 * GPITCH)
#define GBUF   (2 * GTILE)
#define GSMEM  (3 * GBUF)       // 110592 B

__device__ __forceinline__ void gemm_body(
    const __half* __restrict__ Ah, const __half* __restrict__ Al,
    const __half* __restrict__ Bh, const float* __restrict__ bias,
    float* __restrict__ C, float* __restrict__ Cpart,
    __half* __restrict__ Ch, __half* __restrict__ Cl,
    float qscale, int qcols,
    int lda, int Ksl, int N, int M,
    int bx, int by, int split, int nsplit, char* smem)
{
    const uint32_t sbase = smem_u32(smem);
    const int tid = threadIdx.x;
    const int lane = tid & 31;
    const int wid = tid >> 5;
    const int wm = wid >> 2;
    const int wn = wid & 3;

    const __half* pA[2] = {Ah, Al};
    const int Kc = Ksl >> 6;
    const int total = 2 * Kc;

    float c[4][4][4];
#pragma unroll
    for (int i = 0; i < 4; i++)
#pragma unroll
        for (int j = 0; j < 4; j++)
#pragma unroll
            for (int f = 0; f < 4; f++) c[i][j][f] = 0.0f;

    auto load_chunk = [&](int g, int buf) {
        int p = (g >= Kc) ? 1 : 0;
        int kk = g - p * Kc;
        const __half* Abase = pA[p] + (size_t)by * 128 * lda + split * Ksl + kk * 64;
        const __half* Bbase = Bh + (size_t)bx * 128 * lda + split * Ksl + kk * 64;
        uint32_t aS = sbase + buf * GBUF;
        uint32_t bS = aS + GTILE;
#pragma unroll
        for (int j = 0; j < 4; j++) {
            int lin = tid + j * 256;
            int row = lin >> 3;
            int seg = lin & 7;
            cp_async16(aS + row * GPITCH + seg * 16,
                       Abase + (size_t)row * lda + seg * 8);
            cp_async16(bS + row * GPITCH + seg * 16,
                       Bbase + (size_t)row * lda + seg * 8);
        }
        cp_commit();
    };

    load_chunk(0, 0);
    load_chunk(1, 1);

    int buf = 0;
    for (int g = 0; g < total; g++) {
        if (g == total - 1) cp_wait<0>(); else cp_wait<1>();
        __syncthreads();
        if (g + 2 < total) {
            int nb = buf + 2; if (nb >= 3) nb -= 3;
            load_chunk(g + 2, nb);
        }

        const uint32_t aS = sbase + buf * GBUF;
        const uint32_t bS = aS + GTILE;
#pragma unroll
        for (int s = 0; s < 4; s++) {
            uint32_t a[4][4];
#pragma unroll
            for (int i = 0; i < 4; i++) {
                int row = wm * 64 + i * 16 + (lane & 15);
                ldm_x4(a[i], aS + row * GPITCH + s * 32 + ((lane >> 4) * 16));
            }
            uint32_t b[2][4];
#pragma unroll
            for (int j = 0; j < 2; j++) {
                int row = wn * 32 + j * 16 + ((lane >> 4) << 3) + (lane & 7);
                int off = ((lane >> 3) & 1) * 16;
                ldm_x4(b[j], bS + row * GPITCH + s * 32 + off);
            }
#pragma unroll
            for (int i = 0; i < 4; i++) {
#pragma unroll
                for (int j = 0; j < 2; j++) {
                    mma16816(c[i][2 * j], a[i], b[j][0], b[j][1]);
                    mma16816(c[i][2 * j + 1], a[i], b[j][2], b[j][3]);
                }
            }
        }
        if (++buf == 3) buf = 0;
    }

    const bool addb = (bias != nullptr) && (nsplit == 1);
#pragma unroll
    for (int i = 0; i < 4; i++) {
        int r0 = by * 128 + wm * 64 + i * 16 + (lane >> 2);
#pragma unroll
        for (int nt = 0; nt < 4; nt++) {
            int col = bx * 128 + wn * 32 + nt * 8 + (lane & 3) * 2;
            float bx0 = 0.0f, bx1 = 0.0f;
            if (addb) { bx0 = bias[col]; bx1 = bias[col + 1]; }
            float a0 = c[i][nt][0] + bx0, a1 = c[i][nt][1] + bx1;
            float a2 = c[i][nt][2] + bx0, a3 = c[i][nt][3] + bx1;
            if (Ch) {
                float sc = (col < qcols) ? qscale : 1.0f;
                a0 *= sc; a1 *= sc; a2 *= sc; a3 *= sc;
                __half h0 = __float2half_rn(a0), h1 = __float2half_rn(a1);
                __half h2 = __float2half_rn(a2), h3 = __float2half_rn(a3);
                *(__half2*)(Ch + (size_t)r0 * N + col) = __halves2half2(h0, h1);
                *(__half2*)(Ch + (size_t)(r0 + 8) * N + col) = __halves2half2(h2, h3);
                *(__half2*)(Cl + (size_t)r0 * N + col) =
                    __halves2half2(__float2half_rn(a0 - __half2float(h0)),
                                   __float2half_rn(a1 - __half2float(h1)));
                *(__half2*)(Cl + (size_t)(r0 + 8) * N + col) =
                    __halves2half2(__float2half_rn(a2 - __half2float(h2)),
                                   __float2half_rn(a3 - __half2float(h3)));
            } else {
                float* dst = (nsplit == 1) ? C : (Cpart + (size_t)split * M * N);
                float2 v0 = {a0, a1}, v1 = {a2, a3};
                *(float2*)(dst + (size_t)r0 * N + col) = v0;
                *(float2*)(dst + (size_t)(r0 + 8) * N + col) = v1;
            }
        }
    }
}

// ---------------- QKV GEMM kernel --------------------------------------------
__global__ __launch_bounds__(256, 2) void gemm2(
    const __half* __restrict__ Ah, const __half* __restrict__ Al,
    const __half* __restrict__ Bh, const float* __restrict__ bias,
    __half* __restrict__ Ch, __half* __restrict__ Cl,
    float qscale, int qcols, int lda, int Ksl, int N)
{
    extern __shared__ __align__(16) char smem[];
    gemm_body(Ah, Al, Bh, bias, nullptr, nullptr, Ch, Cl, qscale, qcols,
              lda, Ksl, N, gridDim.y * 128,
              blockIdx.x, blockIdx.y, 0, 1, smem);
}

// ---------------- fused mid: out-proj + symmetric SYRK sk8 + colmean ---------
// grid: 256 out-proj | 288 syrk (36 tri-tiles x 8 splits) | 64 colmean = 608
__global__ __launch_bounds__(256, 2) void fused_mid(
    const __half* __restrict__ Mh, const __half* __restrict__ Ml,
    const __half* __restrict__ Woh, const float* __restrict__ bo,
    float* __restrict__ out,
    const __half* __restrict__ Mth, const __half* __restrict__ Mtl,
    float* __restrict__ Gpart, float* __restrict__ meanpart)
{
    extern __shared__ __align__(16) char smem[];
    int t = blockIdx.x;
    if (t < 256) {
        // out projection (unsplit, direct write + bias)
        gemm_body(Mh, Ml, Woh, bo, out, nullptr, nullptr, nullptr, 1.0f, 0,
                  DD, DD, DD, MTOT, t & 7, t >> 3, 0, 1, smem);
    } else if (t < 544) {
        int t2 = t - 256;
        int split = t2 / 36;
        int pair = t2 % 36;
        int ti = 0, s = pair;
        while (s >= 8 - ti) { s -= 8 - ti; ti++; }
        int tj = ti + s;
        gemm_body(Mth, Mtl, Mth, nullptr, nullptr, Gpart, nullptr, nullptr,
                  1.0f, 0, NBL, NBL / 8, DD, DD,
                  tj, ti, split, 8, smem);
    } else {
        int idx = t - 544;
        int col = (idx & 3) * 256 + threadIdx.x;
        int seg = idx >> 2;
        float s = 0.0f;
        size_t base = (size_t)seg * 256 * DD + col;
#pragma unroll 4
        for (int r = 0; r < 256; r++) {
            size_t o = base + (size_t)r * DD;
            s += __half2float(Mh[o]) + __half2float(Ml[o]);
        }
        meanpart[seg * DD + col] = s;
    }
}

// ---------------- decov per-tile: reduce 8 Gpart slices + cov + square -------
// grid 144: 36 tri-tile pairs x 4 row-quarters. Means computed inline.
__global__ __launch_bounds__(256) void decov_tiles(
    const float* __restrict__ Gpart, const float* __restrict__ meanpart,
    float* __restrict__ partial)
{
    __shared__ float smrow[32];
    __shared__ float smcol[128];
    __shared__ float red[256];
    int pair = blockIdx.x % 36;
    int q = blockIdx.x / 36;
    int ti = 0, s0 = pair;
    while (s0 >= 8 - ti) { s0 -= 8 - ti; ti++; }
    int tj = ti + s0;
    const float w = (ti == tj) ? 1.0f : 2.0f;
    const float invN = 1.0f / (float)NBL;

    if (threadIdx.x < 160) {
        bool isRow = threadIdx.x < 32;
        int col = isRow ? (ti * 128 + q * 32 + threadIdx.x)
                        : (tj * 128 + threadIdx.x - 32);
        float ms = 0.0f;
#pragma unroll
        for (int seg = 0; seg < 16; seg++) ms += meanpart[seg * DD + col];
        ms *= invN;
        if (isRow) smrow[threadIdx.x] = ms;
        else smcol[threadIdx.x - 32] = ms;
    }
    __syncthreads();

    int row = ti * 128 + q * 32 + (threadIdx.x >> 3);
    int c0 = tj * 128 + (threadIdx.x & 7) * 16;
    float mi = smrow[threadIdx.x >> 3];
    float acc = 0.0f;
    size_t base = (size_t)row * DD + c0;
#pragma unroll
    for (int c4 = 0; c4 < 4; c4++) {
        int col = c0 + c4 * 4;
        float4 g = *(const float4*)(Gpart + base + c4 * 4);
#pragma unroll
        for (int p = 1; p < 8; p++) {
            float4 v = *(const float4*)(Gpart + (size_t)p * DD * DD + base + c4 * 4);
            g.x += v.x; g.y += v.y; g.z += v.z; g.w += v.w;
        }
        int lc = col - tj * 128;
        float cx = g.x * invN - mi * smcol[lc];
        float cy = g.y * invN - mi * smcol[lc + 1];
        float cz = g.z * invN - mi * smcol[lc + 2];
        float cw = g.w * invN - mi * smcol[lc + 3];
        if (row == col) cx = 0.0f;
        if (row == col + 1) cy = 0.0f;
        if (row == col + 2) cz = 0.0f;
        if (row == col + 3) cw = 0.0f;
        acc += cx * cx + cy * cy + cz * cz + cw * cw;
    }
    red[threadIdx.x] = acc * w;
    __syncthreads();
    for (int off = 128; off > 0; off >>= 1) {
        if (threadIdx.x < off) red[threadIdx.x] += red[threadIdx.x + off];
        __syncthreads();
    }
    if (threadIdx.x == 0) partial[blockIdx.x] = red[0];
}

__global__ void decov_final(const float* __restrict__ partial, float* __restrict__ out)
{
    if (threadIdx.x == 0) {
        float t = 0.0f;
        for (int i = 0; i < 144; i++) t += partial[i];
        out[0] = 0.5f * t;
    }
}

// ---------------- Attention: flash + mma.sync, fp16 inputs, cp.async ring ----
#define AP 72
#define APB 144
#define KTB (64 * APB)
#define ASTG (3 * KTB)
#define ASMEM (3 * ASTG)        // 82944 B

__global__ __launch_bounds__(256, 2) void attn_mma(
    const __half* __restrict__ QKVh, const __half* __restrict__ QKVl,
    __half* __restrict__ Oh, __half* __restrict__ Ol)
{
    extern __shared__ __align__(16) char smem[];
    const uint32_t sbase = smem_u32(smem);

    const int tid = threadIdx.x;
    const int lane = tid & 31;
    const int w = tid >> 5;
    const int q0 = blockIdx.x * 128;
    const int h = blockIdx.y;
    const int b = blockIdx.z;

    uint32_t Qah[4][4], Qal[4][4];
    {
        int r0 = b * LL + q0 + w * 16 + (lane >> 2);
        int cb = h * DK + (lane & 3) * 2;
#pragma unroll
        for (int s = 0; s < 4; s++)
#pragma unroll
            for (int t2 = 0; t2 < 4; t2++) {
                size_t off = (size_t)(r0 + (t2 & 1) * 8) * RS3 + cb + s * 16 + (t2 >> 1) * 8;
                Qah[s][t2] = *(const uint32_t*)(QKVh + off);
                Qal[s][t2] = *(const uint32_t*)(QKVl + off);
            }
    }

    auto load_tile = [&](int kt, int stg) {
        uint32_t sb = sbase + stg * ASTG;
#pragma unroll
        for (int it = 0; it < 2; it++) {
            int lin = tid + it * 256;
            int row = lin >> 3;
            int seg = lin & 7;
            size_t goff = (size_t)(b * LL + kt + row) * RS3 + DD + h * DK + seg * 8;
            cp_async16(sb + row * APB + seg * 16, QKVh + goff);
            cp_async16(sb + KTB + row * APB + seg * 16, QKVl + goff);
            cp_async16(sb + 2 * KTB + row * APB + seg * 16, QKVh + goff + DD);
        }
        cp_commit();
    };

    float m0 = -1e30f, m1 = -1e30f, l0 = 0.0f, l1 = 0.0f;
    float co[8][4];
#pragma unroll
    for (int j = 0; j < 8; j++)
#pragma unroll
        for (int f = 0; f < 4; f++) co[j][f] = 0.0f;

    load_tile(0, 0);
    load_tile(64, 1);

    int buf = 0;
    for (int g = 0; g < 16; g++) {
        if (g == 15) cp_wait<0>(); else cp_wait<1>();
        __syncthreads();
        if (g + 2 < 16) {
            int nb = buf + 2; if (nb >= 3) nb -= 3;
            load_tile((g + 2) * 64, nb);
        }
        const uint32_t khs = sbase + buf * ASTG;
        const uint32_t kls = khs + KTB;
        const uint32_t vhs = khs + 2 * KTB;

        float sc[8][4];
#pragma unroll
        for (int j = 0; j < 8; j++)
#pragma unroll
            for (int f = 0; f < 4; f++) sc[j][f] = 0.0f;

#pragma unroll
        for (int s = 0; s < 4; s++) {
#pragma unroll
            for (int j = 0; j < 4; j++) {
                uint32_t roff = (j * 16 + ((lane >> 4) << 3) + (lane & 7)) * APB
                              + s * 32 + ((lane >> 3) & 1) * 16;
                uint32_t bh[4], bl[4];
                ldm_x4(bh, khs + roff);
                ldm_x4(bl, kls + roff);
                mma16816(sc[2 * j],     Qah[s], bh[0], bh[1]);
                mma16816(sc[2 * j + 1], Qah[s], bh[2], bh[3]);
                mma16816(sc[2 * j],     Qal[s], bh[0], bh[1]);
                mma16816(sc[2 * j + 1], Qal[s], bh[2], bh[3]);
                mma16816(sc[2 * j],     Qah[s], bl[0], bl[1]);
                mma16816(sc[2 * j + 1], Qah[s], bl[2], bl[3]);
            }
        }

        float t0 = -1e30f, t1 = -1e30f;
#pragma unroll
        for (int j = 0; j < 8; j++) {
            t0 = fmaxf(t0, fmaxf(sc[j][0], sc[j][1]));
            t1 = fmaxf(t1, fmaxf(sc[j][2], sc[j][3]));
        }
        t0 = fmaxf(t0, __shfl_xor_sync(0xffffffffu, t0, 1));
        t0 = fmaxf(t0, __shfl_xor_sync(0xffffffffu, t0, 2));
        t1 = fmaxf(t1, __shfl_xor_sync(0xffffffffu, t1, 1));
        t1 = fmaxf(t1, __shfl_xor_sync(0xffffffffu, t1, 2));
        float mn0 = fmaxf(m0, t0), mn1 = fmaxf(m1, t1);
        float f0 = __expf(m0 - mn0), f1 = __expf(m1 - mn1);
        float rs0 = 0.0f, rs1 = 0.0f;
#pragma unroll
        for (int j = 0; j < 8; j++) {
            sc[j][0] = __expf(sc[j][0] - mn0);
            sc[j][1] = __expf(sc[j][1] - mn0);
            sc[j][2] = __expf(sc[j][2] - mn1);
            sc[j][3] = __expf(sc[j][3] - mn1);
            rs0 += sc[j][0] + sc[j][1];
            rs1 += sc[j][2] + sc[j][3];
        }
        rs0 += __shfl_xor_sync(0xffffffffu, rs0, 1);
        rs0 += __shfl_xor_sync(0xffffffffu, rs0, 2);
        rs1 += __shfl_xor_sync(0xffffffffu, rs1, 1);
        rs1 += __shfl_xor_sync(0xffffffffu, rs1, 2);
        l0 = l0 * f0 + rs0;
        l1 = l1 * f1 + rs1;
        m0 = mn0; m1 = mn1;
#pragma unroll
        for (int j = 0; j < 8; j++) {
            co[j][0] *= f0; co[j][1] *= f0;
            co[j][2] *= f1; co[j][3] *= f1;
        }

#pragma unroll
        for (int s = 0; s < 4; s++) {
            uint32_t pah[4], pal[4];
#pragma unroll
            for (int t2 = 0; t2 < 4; t2++) {
                int bk = 2 * s + (t2 >> 1);
                float p0 = sc[bk][(t2 & 1) * 2];
                float p1 = sc[bk][(t2 & 1) * 2 + 1];
                __half h0 = __float2half_rn(p0), h1 = __float2half_rn(p1);
                pah[t2] = pack_h2(h0, h1);
                pal[t2] = pack_h2(__float2half_rn(p0 - __half2float(h0)),
                                  __float2half_rn(p1 - __half2float(h1)));
            }
#pragma unroll
            for (int j = 0; j < 4; j++) {
                uint32_t roff = (s * 16 + ((lane >> 3) & 1) * 8 + (lane & 7)) * APB
                              + (j * 16 + ((lane >> 4) & 1) * 8) * 2;
                uint32_t vbh[4];
                ldm_x4_trans(vbh, vhs + roff);
                mma16816(co[2 * j],     pah, vbh[0], vbh[1]);
                mma16816(co[2 * j + 1], pah, vbh[2], vbh[3]);
                mma16816(co[2 * j],     pal, vbh[0], vbh[1]);
                mma16816(co[2 * j + 1], pal, vbh[2], vbh[3]);
            }
        }
        if (++buf == 3) buf = 0;
    }

    float inv0 = 1.0f / l0, inv1 = 1.0f / l1;
    int grow = q0 + w * 16 + (lane >> 2);
    size_t base0 = (size_t)(b * LL + grow) * DD + h * DK;
    size_t base1 = base0 + (size_t)8 * DD;
#pragma unroll
    for (int j = 0; j < 8; j++) {
        int col = j * 8 + (lane & 3) * 2;
        float a0 = co[j][0] * inv0, a1 = co[j][1] * inv0;
        float a2 = co[j][2] * inv1, a3 = co[j][3] * inv1;
        __half h0 = __float2half_rn(a0), h1 = __float2half_rn(a1);
        __half h2 = __float2half_rn(a2), h3 = __float2half_rn(a3);
        *(__half2*)(Oh + base0 + col) = __halves2half2(h0, h1);
        *(__half2*)(Oh + base1 + col) = __halves2half2(h2, h3);
        *(__half2*)(Ol + base0 + col) =
            __halves2half2(__float2half_rn(a0 - __half2float(h0)),
                           __float2half_rn(a1 - __half2float(h1)));
        *(__half2*)(Ol + base1 + col) =
            __halves2half2(__float2half_rn(a2 - __half2float(h2)),
                           __float2half_rn(a3 - __half2float(h3)));
    }
}

// ---------------- transpose + split: (Mh+Ml)[NBL][DD] -> T[DD][NBL] ----------
__global__ __launch_bounds__(256) void transpose_split_fp16(
    const __half* __restrict__ Msh, const __half* __restrict__ Msl,
    __half* __restrict__ Th, __half* __restrict__ Tl)
{
    __shared__ float tile[32][33];
    int bx = blockIdx.x;
    int by = blockIdx.y;
    int tx = threadIdx.x;
    int ty = threadIdx.y;
#pragma unroll
    for (int j = 0; j < 32; j += 8) {
        size_t off = (size_t)(by * 32 + ty + j) * DD + bx * 32 + tx;
        tile[ty + j][tx] = __half2float(Msh[off]) + __half2float(Msl[off]);
    }
    __syncthreads();
#pragma unroll
    for (int j = 0; j < 32; j += 8) {
        float v = tile[tx][ty + j];
        __half h = __float2half_rn(v);
        __half l = __float2half_rn(v - __half2float(h));
        size_t off = (size_t)(bx * 32 + ty + j) * NBL + by * 32 + tx;
        Th[off] = h;
        Tl[off] = l;
    }
}

// ---------------- launch ------------------------------------------------------
extern "C" void kernel_launch(void* const* d_in, const int* in_sizes, int n_in,
                              void* d_out, int out_size)
{
    const float* x  = (const float*)d_in[0];
    const float* Wq = (const float*)d_in[1];
    const float* bq = (const float*)d_in[2];
    const float* Wk = (const float*)d_in[3];
    const float* bk = (const float*)d_in[4];
    const float* Wv = (const float*)d_in[5];
    const float* bv = (const float*)d_in[6];
    const float* Wo = (const float*)d_in[7];
    const float* bo = (const float*)d_in[8];
    float* out = (float*)d_out;

    float *meanpartp, *partp, *Gpart, *bqkv;
    cudaGetSymbolAddress((void**)&meanpartp, g_meanpart);
    cudaGetSymbolAddress((void**)&partp, g_partial);
    cudaGetSymbolAddress((void**)&Gpart, g_Gpart);
    cudaGetSymbolAddress((void**)&bqkv, g_bqkv);

    __half *QKVh, *QKVl, *xh, *xl, *Mh, *Ml, *Mth, *Mtl, *Wqkvh, *Woh;
    cudaGetSymbolAddress((void**)&QKVh, g_QKVh);
    cudaGetSymbolAddress((void**)&QKVl, g_QKVl);
    cudaGetSymbolAddress((void**)&xh, g_xh);
    cudaGetSymbolAddress((void**)&xl, g_xl);
    cudaGetSymbolAddress((void**)&Mh, g_Mh);
    cudaGetSymbolAddress((void**)&Ml, g_Ml);
    cudaGetSymbolAddress((void**)&Mth, g_Mth);
    cudaGetSymbolAddress((void**)&Mtl, g_Mtl);
    cudaGetSymbolAddress((void**)&Wqkvh, g_Wqkvh);
    cudaGetSymbolAddress((void**)&Woh, g_Woh);

    cudaFuncSetAttribute(gemm2, cudaFuncAttributeMaxDynamicSharedMemorySize,
                         GSMEM);
    cudaFuncSetAttribute(fused_mid, cudaFuncAttributeMaxDynamicSharedMemorySize,
                         GSMEM);
    cudaFuncSetAttribute(attn_mma, cudaFuncAttributeMaxDynamicSharedMemorySize,
                         ASMEM);

    // 1. prep
    prep_kernel<<<8204, 256>>>(x, Wq, Wk, Wv, Wo, bq, bk, bv,
                               xh, xl, Wqkvh, Woh, bqkv);

    // 2. fused QKV projection
    dim3 gQKV(RS3 / 128, MTOT / 128, 1);
    gemm2<<<gQKV, 256, GSMEM>>>(xh, xl, Wqkvh, bqkv,
                                QKVh, QKVl, 0.125f, DD, DD, DD, RS3);

    // 3. attention
    dim3 gAttn(LL / 128, HH, BB);
    attn_mma<<<gAttn, 256, ASMEM>>>(QKVh, QKVl, Mh, Ml);

    // 4. transposed split of M
    transpose_split_fp16<<<dim3(DD / 32, NBL / 32), dim3(32, 8)>>>(Mh, Ml, Mth, Mtl);

    // 5. fused: out-proj (256) + SYRK sk8 (288) + colmean-part (64)
    fused_mid<<<608, 256, GSMEM>>>(Mh, Ml, Woh, bo, out,
                                   Mth, Mtl, Gpart, meanpartp);

    // 6. decov tiles (reduce 8 Gpart slices + inline means + cov + square)
    decov_tiles<<<144, 256>>>(Gpart, meanpartp, partp);

    // 7. final scalar
    decov_final<<<1, 32>>>(partp, out + (out_size - 1));
}

// round 12
// speedup vs baseline: 1.0680x; 1.0426x over previous
#include <cuda_runtime.h>
#include <cuda_fp16.h>
#include <math.h>
#include <stdint.h>

// Problem constants
#define BB 4
#define LL 1024
#define DD 1024
#define HH 16
#define DK 64
#define MTOT (BB * LL)          // 4096
#define NBL  (BB * LL)          // 4096
#define RS3  (3 * DD)           // 3072

// ---------------- scratch (static device memory; no allocations) -------------
__device__ float g_meanpart[16 * DD];
__device__ float g_partial[160];
__device__ float g_Gpart[4 * DD * DD];    // syrk split-K=4 partials
__device__ float g_bqkv[3 * DD];

__device__ __align__(16) __half g_QKVh[MTOT * RS3];
__device__ __align__(16) __half g_QKVl[MTOT * RS3];
__device__ __align__(16) __half g_xh[MTOT * DD];
__device__ __align__(16) __half g_xl[MTOT * DD];
__device__ __align__(16) __half g_Mh[MTOT * DD];
__device__ __align__(16) __half g_Ml[MTOT * DD];
__device__ __align__(16) __half g_Mth[DD * NBL];
__device__ __align__(16) __half g_Mtl[DD * NBL];
__device__ __align__(16) __half g_Wqkvh[3 * DD * DD];
__device__ __align__(16) __half g_Woh[DD * DD];

// ---------------- small PTX helpers ------------------------------------------
__device__ __forceinline__ uint32_t smem_u32(const void* p) {
    uint32_t a;
    asm("{ .reg .u64 t; cvta.to.shared.u64 t, %1; cvt.u32.u64 %0, t; }"
        : "=r"(a) : "l"(p));
    return a;
}

__device__ __forceinline__ void cp_async16(uint32_t saddr, const void* gptr) {
    asm volatile("cp.async.ca.shared.global [%0], [%1], 16;"
                 :: "r"(saddr), "l"(gptr));
}
__device__ __forceinline__ void cp_commit() {
    asm volatile("cp.async.commit_group;" ::: "memory");
}
template <int N>
__device__ __forceinline__ void cp_wait() {
    asm volatile("cp.async.wait_group %0;" :: "n"(N) : "memory");
}

__device__ __forceinline__ void ldm_x4(uint32_t (&r)[4], uint32_t addr) {
    asm volatile("ldmatrix.sync.aligned.m8n8.x4.shared.b16 {%0,%1,%2,%3}, [%4];"
                 : "=r"(r[0]), "=r"(r[1]), "=r"(r[2]), "=r"(r[3]) : "r"(addr));
}
__device__ __forceinline__ void ldm_x4_trans(uint32_t (&r)[4], uint32_t addr) {
    asm volatile("ldmatrix.sync.aligned.m8n8.x4.trans.shared.b16 {%0,%1,%2,%3}, [%4];"
                 : "=r"(r[0]), "=r"(r[1]), "=r"(r[2]), "=r"(r[3]) : "r"(addr));
}

__device__ __forceinline__ void mma16816(float (&c)[4], const uint32_t (&a)[4],
                                         uint32_t b0, uint32_t b1) {
    asm volatile(
        "mma.sync.aligned.m16n8k16.row.col.f32.f16.f16.f32 "
        "{%0,%1,%2,%3}, {%4,%5,%6,%7}, {%8,%9}, {%0,%1,%2,%3};"
        : "+f"(c[0]), "+f"(c[1]), "+f"(c[2]), "+f"(c[3])
        : "r"(a[0]), "r"(a[1]), "r"(a[2]), "r"(a[3]), "r"(b0), "r"(b1));
}

__device__ __forceinline__ uint32_t pack_h2(__half x, __half y) {
    __half2 h = __halves2half2(x, y);
    return *(uint32_t*)&h;
}

struct __align__(8) half4 { __half a, b, c, d; };

// ---------------- prep mega-kernel: x split + weight rounds + bias concat ----
__global__ __launch_bounds__(256) void prep_kernel(
    const float* __restrict__ x,
    const float* __restrict__ Wq, const float* __restrict__ Wk,
    const float* __restrict__ Wv, const float* __restrict__ Wo,
    const float* __restrict__ bq, const float* __restrict__ bk,
    const float* __restrict__ bv,
    __half* __restrict__ xh, __half* __restrict__ xl,
    __half* __restrict__ Wqkvh, __half* __restrict__ Woh,
    float* __restrict__ bqkv)
{
    int t = blockIdx.x;
    int tid = threadIdx.x;
    if (t < 4096) {
        int i = t * 256 + tid;
        float4 v = ((const float4*)x)[i];
        __half h0 = __float2half_rn(v.x);
        __half h1 = __float2half_rn(v.y);
        __half h2 = __float2half_rn(v.z);
        __half h3 = __float2half_rn(v.w);
        half4 hv = {h0, h1, h2, h3};
        half4 lv = {__float2half_rn(v.x - __half2float(h0)),
                    __float2half_rn(v.y - __half2float(h1)),
                    __float2half_rn(v.z - __half2float(h2)),
                    __float2half_rn(v.w - __half2float(h3))};
        ((half4*)xh)[i] = hv;
        ((half4*)xl)[i] = lv;
    } else if (t < 8192) {
        int wsel = (t - 4096) >> 10;
        int blk = (t - 4096) & 1023;
        const float* src = (wsel == 0) ? Wq : (wsel == 1) ? Wk
                         : (wsel == 2) ? Wv : Wo;
        __half* dst = (wsel < 3) ? (Wqkvh + (size_t)wsel * DD * DD) : Woh;
        int i = blk * 256 + tid;
        float4 v = ((const float4*)src)[i];
        half4 hv = {__float2half_rn(v.x), __float2half_rn(v.y),
                    __float2half_rn(v.z), __float2half_rn(v.w)};
        ((half4*)dst)[i] = hv;
    } else {
        int i = (t - 8192) * 256 + tid;
        if (i < RS3) {
            const float* src = (i < DD) ? bq : (i < 2 * DD) ? bk : bv;
            bqkv[i] = src[i & (DD - 1)];
        }
    }
}

// ---------------- GEMM body ---------------------------------------------------
#define GPITCH 144
#define GTILE  (128 * GPITCH)
#define GBUF   (2 * GTILE)
#define GSMEM  (3 * GBUF)       // 110592 B

__device__ __forceinline__ void gemm_body(
    const __half* __restrict__ Ah, const __half* __restrict__ Al,
    const __half* __restrict__ Bh, const float* __restrict__ bias,
    float* __restrict__ C, float* __restrict__ Cpart,
    __half* __restrict__ Ch, __half* __restrict__ Cl,
    float qscale, int qcols, int locols,
    int lda, int Ksl, int N, int M,
    int bx, int by, int split, int nsplit, char* smem)
{
    const uint32_t sbase = smem_u32(smem);
    const int tid = threadIdx.x;
    const int lane = tid & 31;
    const int wid = tid >> 5;
    const int wm = wid >> 2;
    const int wn = wid & 3;

    const __half* pA[2] = {Ah, Al};
    const int Kc = Ksl >> 6;
    const int total = 2 * Kc;

    float c[4][4][4];
#pragma unroll
    for (int i = 0; i < 4; i++)
#pragma unroll
        for (int j = 0; j < 4; j++)
#pragma unroll
            for (int f = 0; f < 4; f++) c[i][j][f] = 0.0f;

    auto load_chunk = [&](int g, int buf) {
        int p = (g >= Kc) ? 1 : 0;
        int kk = g - p * Kc;
        const __half* Abase = pA[p] + (size_t)by * 128 * lda + split * Ksl + kk * 64;
        const __half* Bbase = Bh + (size_t)bx * 128 * lda + split * Ksl + kk * 64;
        uint32_t aS = sbase + buf * GBUF;
        uint32_t bS = aS + GTILE;
#pragma unroll
        for (int j = 0; j < 4; j++) {
            int lin = tid + j * 256;
            int row = lin >> 3;
            int seg = lin & 7;
            cp_async16(aS + row * GPITCH + seg * 16,
                       Abase + (size_t)row * lda + seg * 8);
            cp_async16(bS + row * GPITCH + seg * 16,
                       Bbase + (size_t)row * lda + seg * 8);
        }
        cp_commit();
    };

    load_chunk(0, 0);
    load_chunk(1, 1);

    int buf = 0;
    for (int g = 0; g < total; g++) {
        if (g == total - 1) cp_wait<0>(); else cp_wait<1>();
        __syncthreads();
        if (g + 2 < total) {
            int nb = buf + 2; if (nb >= 3) nb -= 3;
            load_chunk(g + 2, nb);
        }

        const uint32_t aS = sbase + buf * GBUF;
        const uint32_t bS = aS + GTILE;
#pragma unroll
        for (int s = 0; s < 4; s++) {
            uint32_t a[4][4];
#pragma unroll
            for (int i = 0; i < 4; i++) {
                int row = wm * 64 + i * 16 + (lane & 15);
                ldm_x4(a[i], aS + row * GPITCH + s * 32 + ((lane >> 4) * 16));
            }
            uint32_t b[2][4];
#pragma unroll
            for (int j = 0; j < 2; j++) {
                int row = wn * 32 + j * 16 + ((lane >> 4) << 3) + (lane & 7);
                int off = ((lane >> 3) & 1) * 16;
                ldm_x4(b[j], bS + row * GPITCH + s * 32 + off);
            }
#pragma unroll
            for (int i = 0; i < 4; i++) {
#pragma unroll
                for (int j = 0; j < 2; j++) {
                    mma16816(c[i][2 * j], a[i], b[j][0], b[j][1]);
                    mma16816(c[i][2 * j + 1], a[i], b[j][2], b[j][3]);
                }
            }
        }
        if (++buf == 3) buf = 0;
    }

    const bool addb = (bias != nullptr) && (nsplit == 1);
#pragma unroll
    for (int i = 0; i < 4; i++) {
        int r0 = by * 128 + wm * 64 + i * 16 + (lane >> 2);
#pragma unroll
        for (int nt = 0; nt < 4; nt++) {
            int col = bx * 128 + wn * 32 + nt * 8 + (lane & 3) * 2;
            float bx0 = 0.0f, bx1 = 0.0f;
            if (addb) { bx0 = bias[col]; bx1 = bias[col + 1]; }
            float a0 = c[i][nt][0] + bx0, a1 = c[i][nt][1] + bx1;
            float a2 = c[i][nt][2] + bx0, a3 = c[i][nt][3] + bx1;
            if (Ch) {
                float sc = (col < qcols) ? qscale : 1.0f;
                a0 *= sc; a1 *= sc; a2 *= sc; a3 *= sc;
                __half h0 = __float2half_rn(a0), h1 = __float2half_rn(a1);
                __half h2 = __float2half_rn(a2), h3 = __float2half_rn(a3);
                *(__half2*)(Ch + (size_t)r0 * N + col) = __halves2half2(h0, h1);
                *(__half2*)(Ch + (size_t)(r0 + 8) * N + col) = __halves2half2(h2, h3);
                if (col < locols) {     // lo split only where consumed
                    *(__half2*)(Cl + (size_t)r0 * N + col) =
                        __halves2half2(__float2half_rn(a0 - __half2float(h0)),
                                       __float2half_rn(a1 - __half2float(h1)));
                    *(__half2*)(Cl + (size_t)(r0 + 8) * N + col) =
                        __halves2half2(__float2half_rn(a2 - __half2float(h2)),
                                       __float2half_rn(a3 - __half2float(h3)));
                }
            } else {
                float* dst = (nsplit == 1) ? C : (Cpart + (size_t)split * M * N);
                float2 v0 = {a0, a1}, v1 = {a2, a3};
                *(float2*)(dst + (size_t)r0 * N + col) = v0;
                *(float2*)(dst + (size_t)(r0 + 8) * N + col) = v1;
            }
        }
    }
}

// ---------------- QKV GEMM kernel --------------------------------------------
__global__ __launch_bounds__(256, 2) void gemm2(
    const __half* __restrict__ Ah, const __half* __restrict__ Al,
    const __half* __restrict__ Bh, const float* __restrict__ bias,
    __half* __restrict__ Ch, __half* __restrict__ Cl,
    float qscale, int qcols, int locols, int lda, int Ksl, int N)
{
    extern __shared__ __align__(16) char smem[];
    gemm_body(Ah, Al, Bh, bias, nullptr, nullptr, Ch, Cl, qscale, qcols,
              locols, lda, Ksl, N, gridDim.y * 128,
              blockIdx.x, blockIdx.y, 0, 1, smem);
}

// ---------------- fused mid: out-proj + symmetric SYRK sk4 + colmean ---------
// grid: 256 out-proj | 144 syrk (36 tri-tiles x 4 splits) | 64 colmean = 464
__global__ __launch_bounds__(256, 2) void fused_mid(
    const __half* __restrict__ Mh, const __half* __restrict__ Ml,
    const __half* __restrict__ Woh, const float* __restrict__ bo,
    float* __restrict__ out,
    const __half* __restrict__ Mth, const __half* __restrict__ Mtl,
    float* __restrict__ Gpart, float* __restrict__ meanpart)
{
    extern __shared__ __align__(16) char smem[];
    int t = blockIdx.x;
    if (t < 256) {
        // out projection (unsplit, direct write + bias)
        gemm_body(Mh, Ml, Woh, bo, out, nullptr, nullptr, nullptr, 1.0f, 0, 0,
                  DD, DD, DD, MTOT, t & 7, t >> 3, 0, 1, smem);
    } else if (t < 400) {
        int t2 = t - 256;
        int split = t2 / 36;
        int pair = t2 % 36;
        int ti = 0, s = pair;
        while (s >= 8 - ti) { s -= 8 - ti; ti++; }
        int tj = ti + s;
        gemm_body(Mth, Mtl, Mth, nullptr, nullptr, Gpart, nullptr, nullptr,
                  1.0f, 0, 0, NBL, NBL / 4, DD, DD,
                  tj, ti, split, 4, smem);
    } else {
        int idx = t - 400;
        int col = (idx & 3) * 256 + threadIdx.x;
        int seg = idx >> 2;
        float s = 0.0f;
        size_t base = (size_t)seg * 256 * DD + col;
#pragma unroll 4
        for (int r = 0; r < 256; r++) {
            size_t o = base + (size_t)r * DD;
            s += __half2float(Mh[o]) + __half2float(Ml[o]);
        }
        meanpart[seg * DD + col] = s;
    }
}

// ---------------- decov per-tile: reduce 4 Gpart slices + cov + square -------
// grid 144: 36 tri-tile pairs x 4 row-quarters. Means computed inline.
__global__ __launch_bounds__(256) void decov_tiles(
    const float* __restrict__ Gpart, const float* __restrict__ meanpart,
    float* __restrict__ partial)
{
    __shared__ float smrow[32];
    __shared__ float smcol[128];
    __shared__ float red[256];
    int pair = blockIdx.x % 36;
    int q = blockIdx.x / 36;
    int ti = 0, s0 = pair;
    while (s0 >= 8 - ti) { s0 -= 8 - ti; ti++; }
    int tj = ti + s0;
    const float w = (ti == tj) ? 1.0f : 2.0f;
    const float invN = 1.0f / (float)NBL;

    if (threadIdx.x < 160) {
        bool isRow = threadIdx.x < 32;
        int col = isRow ? (ti * 128 + q * 32 + threadIdx.x)
                        : (tj * 128 + threadIdx.x - 32);
        float ms = 0.0f;
#pragma unroll
        for (int seg = 0; seg < 16; seg++) ms += meanpart[seg * DD + col];
        ms *= invN;
        if (isRow) smrow[threadIdx.x] = ms;
        else smcol[threadIdx.x - 32] = ms;
    }
    __syncthreads();

    int row = ti * 128 + q * 32 + (threadIdx.x >> 3);
    int c0 = tj * 128 + (threadIdx.x & 7) * 16;
    float mi = smrow[threadIdx.x >> 3];
    float acc = 0.0f;
    size_t base = (size_t)row * DD + c0;
#pragma unroll
    for (int c4 = 0; c4 < 4; c4++) {
        int col = c0 + c4 * 4;
        float4 g = *(const float4*)(Gpart + base + c4 * 4);
#pragma unroll
        for (int p = 1; p < 4; p++) {
            float4 v = *(const float4*)(Gpart + (size_t)p * DD * DD + base + c4 * 4);
            g.x += v.x; g.y += v.y; g.z += v.z; g.w += v.w;
        }
        int lc = col - tj * 128;
        float cx = g.x * invN - mi * smcol[lc];
        float cy = g.y * invN - mi * smcol[lc + 1];
        float cz = g.z * invN - mi * smcol[lc + 2];
        float cw = g.w * invN - mi * smcol[lc + 3];
        if (row == col) cx = 0.0f;
        if (row == col + 1) cy = 0.0f;
        if (row == col + 2) cz = 0.0f;
        if (row == col + 3) cw = 0.0f;
        acc += cx * cx + cy * cy + cz * cz + cw * cw;
    }
    red[threadIdx.x] = acc * w;
    __syncthreads();
    for (int off = 128; off > 0; off >>= 1) {
        if (threadIdx.x < off) red[threadIdx.x] += red[threadIdx.x + off];
        __syncthreads();
    }
    if (threadIdx.x == 0) partial[blockIdx.x] = red[0];
}

__global__ void decov_final(const float* __restrict__ partial, float* __restrict__ out)
{
    if (threadIdx.x == 0) {
        float t = 0.0f;
        for (int i = 0; i < 144; i++) t += partial[i];
        out[0] = 0.5f * t;
    }
}

// ---------------- Attention: flash + mma.sync, fp16 inputs, cp.async ring ----
#define AP 72
#define APB 144
#define KTB (64 * APB)
#define ASTG (3 * KTB)
#define ASMEM (3 * ASTG)        // 82944 B

__global__ __launch_bounds__(256, 2) void attn_mma(
    const __half* __restrict__ QKVh, const __half* __restrict__ QKVl,
    __half* __restrict__ Oh, __half* __restrict__ Ol)
{
    extern __shared__ __align__(16) char smem[];
    const uint32_t sbase = smem_u32(smem);

    const int tid = threadIdx.x;
    const int lane = tid & 31;
    const int w = tid >> 5;
    const int q0 = blockIdx.x * 128;
    const int h = blockIdx.y;
    const int b = blockIdx.z;

    uint32_t Qah[4][4], Qal[4][4];
    {
        int r0 = b * LL + q0 + w * 16 + (lane >> 2);
        int cb = h * DK + (lane & 3) * 2;
#pragma unroll
        for (int s = 0; s < 4; s++)
#pragma unroll
            for (int t2 = 0; t2 < 4; t2++) {
                size_t off = (size_t)(r0 + (t2 & 1) * 8) * RS3 + cb + s * 16 + (t2 >> 1) * 8;
                Qah[s][t2] = *(const uint32_t*)(QKVh + off);
                Qal[s][t2] = *(const uint32_t*)(QKVl + off);
            }
    }

    auto load_tile = [&](int kt, int stg) {
        uint32_t sb = sbase + stg * ASTG;
#pragma unroll
        for (int it = 0; it < 2; it++) {
            int lin = tid + it * 256;
            int row = lin >> 3;
            int seg = lin & 7;
            size_t goff = (size_t)(b * LL + kt + row) * RS3 + DD + h * DK + seg * 8;
            cp_async16(sb + row * APB + seg * 16, QKVh + goff);
            cp_async16(sb + KTB + row * APB + seg * 16, QKVl + goff);
            cp_async16(sb + 2 * KTB + row * APB + seg * 16, QKVh + goff + DD);
        }
        cp_commit();
    };

    float m0 = -1e30f, m1 = -1e30f, l0 = 0.0f, l1 = 0.0f;
    float co[8][4];
#pragma unroll
    for (int j = 0; j < 8; j++)
#pragma unroll
        for (int f = 0; f < 4; f++) co[j][f] = 0.0f;

    load_tile(0, 0);
    load_tile(64, 1);

    int buf = 0;
    for (int g = 0; g < 16; g++) {
        if (g == 15) cp_wait<0>(); else cp_wait<1>();
        __syncthreads();
        if (g + 2 < 16) {
            int nb = buf + 2; if (nb >= 3) nb -= 3;
            load_tile((g + 2) * 64, nb);
        }
        const uint32_t khs = sbase + buf * ASTG;
        const uint32_t kls = khs + KTB;
        const uint32_t vhs = khs + 2 * KTB;

        float sc[8][4];
#pragma unroll
        for (int j = 0; j < 8; j++)
#pragma unroll
            for (int f = 0; f < 4; f++) sc[j][f] = 0.0f;

#pragma unroll
        for (int s = 0; s < 4; s++) {
#pragma unroll
            for (int j = 0; j < 4; j++) {
                uint32_t roff = (j * 16 + ((lane >> 4) << 3) + (lane & 7)) * APB
                              + s * 32 + ((lane >> 3) & 1) * 16;
                uint32_t bh[4], bl[4];
                ldm_x4(bh, khs + roff);
                ldm_x4(bl, kls + roff);
                mma16816(sc[2 * j],     Qah[s], bh[0], bh[1]);
                mma16816(sc[2 * j + 1], Qah[s], bh[2], bh[3]);
                mma16816(sc[2 * j],     Qal[s], bh[0], bh[1]);
                mma16816(sc[2 * j + 1], Qal[s], bh[2], bh[3]);
                mma16816(sc[2 * j],     Qah[s], bl[0], bl[1]);
                mma16816(sc[2 * j + 1], Qah[s], bl[2], bl[3]);
            }
        }

        float t0 = -1e30f, t1 = -1e30f;
#pragma unroll
        for (int j = 0; j < 8; j++) {
            t0 = fmaxf(t0, fmaxf(sc[j][0], sc[j][1]));
            t1 = fmaxf(t1, fmaxf(sc[j][2], sc[j][3]));
        }
        t0 = fmaxf(t0, __shfl_xor_sync(0xffffffffu, t0, 1));
        t0 = fmaxf(t0, __shfl_xor_sync(0xffffffffu, t0, 2));
        t1 = fmaxf(t1, __shfl_xor_sync(0xffffffffu, t1, 1));
        t1 = fmaxf(t1, __shfl_xor_sync(0xffffffffu, t1, 2));
        float mn0 = fmaxf(m0, t0), mn1 = fmaxf(m1, t1);
        float f0 = __expf(m0 - mn0), f1 = __expf(m1 - mn1);
        float rs0 = 0.0f, rs1 = 0.0f;
#pragma unroll
        for (int j = 0; j < 8; j++) {
            sc[j][0] = __expf(sc[j][0] - mn0);
            sc[j][1] = __expf(sc[j][1] - mn0);
            sc[j][2] = __expf(sc[j][2] - mn1);
            sc[j][3] = __expf(sc[j][3] - mn1);
            rs0 += sc[j][0] + sc[j][1];
            rs1 += sc[j][2] + sc[j][3];
        }
        rs0 += __shfl_xor_sync(0xffffffffu, rs0, 1);
        rs0 += __shfl_xor_sync(0xffffffffu, rs0, 2);
        rs1 += __shfl_xor_sync(0xffffffffu, rs1, 1);
        rs1 += __shfl_xor_sync(0xffffffffu, rs1, 2);
        l0 = l0 * f0 + rs0;
        l1 = l1 * f1 + rs1;
        m0 = mn0; m1 = mn1;
#pragma unroll
        for (int j = 0; j < 8; j++) {
            co[j][0] *= f0; co[j][1] *= f0;
            co[j][2] *= f1; co[j][3] *= f1;
        }

#pragma unroll
        for (int s = 0; s < 4; s++) {
            uint32_t pah[4], pal[4];
#pragma unroll
            for (int t2 = 0; t2 < 4; t2++) {
                int bk = 2 * s + (t2 >> 1);
                float p0 = sc[bk][(t2 & 1) * 2];
                float p1 = sc[bk][(t2 & 1) * 2 + 1];
                __half h0 = __float2half_rn(p0), h1 = __float2half_rn(p1);
                pah[t2] = pack_h2(h0, h1);
                pal[t2] = pack_h2(__float2half_rn(p0 - __half2float(h0)),
                                  __float2half_rn(p1 - __half2float(h1)));
            }
#pragma unroll
            for (int j = 0; j < 4; j++) {
                uint32_t roff = (s * 16 + ((lane >> 3) & 1) * 8 + (lane & 7)) * APB
                              + (j * 16 + ((lane >> 4) & 1) * 8) * 2;
                uint32_t vbh[4];
                ldm_x4_trans(vbh, vhs + roff);
                mma16816(co[2 * j],     pah, vbh[0], vbh[1]);
                mma16816(co[2 * j + 1], pah, vbh[2], vbh[3]);
                mma16816(co[2 * j],     pal, vbh[0], vbh[1]);
                mma16816(co[2 * j + 1], pal, vbh[2], vbh[3]);
            }
        }
        if (++buf == 3) buf = 0;
    }

    float inv0 = 1.0f / l0, inv1 = 1.0f / l1;
    int grow = q0 + w * 16 + (lane >> 2);
    size_t base0 = (size_t)(b * LL + grow) * DD + h * DK;
    size_t base1 = base0 + (size_t)8 * DD;
#pragma unroll
    for (int j = 0; j < 8; j++) {
        int col = j * 8 + (lane & 3) * 2;
        float a0 = co[j][0] * inv0, a1 = co[j][1] * inv0;
        float a2 = co[j][2] * inv1, a3 = co[j][3] * inv1;
        __half h0 = __float2half_rn(a0), h1 = __float2half_rn(a1);
        __half h2 = __float2half_rn(a2), h3 = __float2half_rn(a3);
        *(__half2*)(Oh + base0 + col) = __halves2half2(h0, h1);
        *(__half2*)(Oh + base1 + col) = __halves2half2(h2, h3);
        *(__half2*)(Ol + base0 + col) =
            __halves2half2(__float2half_rn(a0 - __half2float(h0)),
                           __float2half_rn(a1 - __half2float(h1)));
        *(__half2*)(Ol + base1 + col) =
            __halves2half2(__float2half_rn(a2 - __half2float(h2)),
                           __float2half_rn(a3 - __half2float(h3)));
    }
}

// ---------------- transpose + split: (Mh+Ml)[NBL][DD] -> T[DD][NBL] ----------
__global__ __launch_bounds__(256) void transpose_split_fp16(
    const __half* __restrict__ Msh, const __half* __restrict__ Msl,
    __half* __restrict__ Th, __half* __restrict__ Tl)
{
    __shared__ float tile[32][33];
    int bx = blockIdx.x;
    int by = blockIdx.y;
    int tx = threadIdx.x;
    int ty = threadIdx.y;
#pragma unroll
    for (int j = 0; j < 32; j += 8) {
        size_t off = (size_t)(by * 32 + ty + j) * DD + bx * 32 + tx;
        tile[ty + j][tx] = __half2float(Msh[off]) + __half2float(Msl[off]);
    }
    __syncthreads();
#pragma unroll
    for (int j = 0; j < 32; j += 8) {
        float v = tile[tx][ty + j];
        __half h = __float2half_rn(v);
        __half l = __float2half_rn(v - __half2float(h));
        size_t off = (size_t)(bx * 32 + ty + j) * NBL + by * 32 + tx;
        Th[off] = h;
        Tl[off] = l;
    }
}

// ---------------- launch ------------------------------------------------------
extern "C" void kernel_launch(void* const* d_in, const int* in_sizes, int n_in,
                              void* d_out, int out_size)
{
    const float* x  = (const float*)d_in[0];
    const float* Wq = (const float*)d_in[1];
    const float* bq = (const float*)d_in[2];
    const float* Wk = (const float*)d_in[3];
    const float* bk = (const float*)d_in[4];
    const float* Wv = (const float*)d_in[5];
    const float* bv = (const float*)d_in[6];
    const float* Wo = (const float*)d_in[7];
    const float* bo = (const float*)d_in[8];
    float* out = (float*)d_out;

    float *meanpartp, *partp, *Gpart, *bqkv;
    cudaGetSymbolAddress((void**)&meanpartp, g_meanpart);
    cudaGetSymbolAddress((void**)&partp, g_partial);
    cudaGetSymbolAddress((void**)&Gpart, g_Gpart);
    cudaGetSymbolAddress((void**)&bqkv, g_bqkv);

    __half *QKVh, *QKVl, *xh, *xl, *Mh, *Ml, *Mth, *Mtl, *Wqkvh, *Woh;
    cudaGetSymbolAddress((void**)&QKVh, g_QKVh);
    cudaGetSymbolAddress((void**)&QKVl, g_QKVl);
    cudaGetSymbolAddress((void**)&xh, g_xh);
    cudaGetSymbolAddress((void**)&xl, g_xl);
    cudaGetSymbolAddress((void**)&Mh, g_Mh);
    cudaGetSymbolAddress((void**)&Ml, g_Ml);
    cudaGetSymbolAddress((void**)&Mth, g_Mth);
    cudaGetSymbolAddress((void**)&Mtl, g_Mtl);
    cudaGetSymbolAddress((void**)&Wqkvh, g_Wqkvh);
    cudaGetSymbolAddress((void**)&Woh, g_Woh);

    cudaFuncSetAttribute(gemm2, cudaFuncAttributeMaxDynamicSharedMemorySize,
                         GSMEM);
    cudaFuncSetAttribute(fused_mid, cudaFuncAttributeMaxDynamicSharedMemorySize,
                         GSMEM);
    cudaFuncSetAttribute(attn_mma, cudaFuncAttributeMaxDynamicSharedMemorySize,
                         ASMEM);

    // 1. prep
    prep_kernel<<<8204, 256>>>(x, Wq, Wk, Wv, Wo, bq, bk, bv,
                               xh, xl, Wqkvh, Woh, bqkv);

    // 2. fused QKV projection (lo split skipped for V columns >= 2048)
    dim3 gQKV(RS3 / 128, MTOT / 128, 1);
    gemm2<<<gQKV, 256, GSMEM>>>(xh, xl, Wqkvh, bqkv,
                                QKVh, QKVl, 0.125f, DD, 2 * DD, DD, DD, RS3);

    // 3. attention
    dim3 gAttn(LL / 128, HH, BB);
    attn_mma<<<gAttn, 256, ASMEM>>>(QKVh, QKVl, Mh, Ml);

    // 4. transposed split of M
    transpose_split_fp16<<<dim3(DD / 32, NBL / 32), dim3(32, 8)>>>(Mh, Ml, Mth, Mtl);

    // 5. fused: out-proj (256) + SYRK sk4 (144) + colmean-part (64)
    fused_mid<<<464, 256, GSMEM>>>(Mh, Ml, Woh, bo, out,
                                   Mth, Mtl, Gpart, meanpartp);

    // 6. decov tiles (reduce 4 Gpart slices + inline means + cov + square)
    decov_tiles<<<144, 256>>>(Gpart, meanpartp, partp);

    // 7. final scalar
    decov_final<<<1, 32>>>(partp, out + (out_size - 1));
}

// round 13
// speedup vs baseline: 1.1865x; 1.1109x over previous
#include <cuda_runtime.h>
#include <cuda_fp16.h>
#include <math.h>
#include <stdint.h>

// Problem constants
#define BB 4
#define LL 1024
#define DD 1024
#define HH 16
#define DK 64
#define MTOT (BB * LL)          // 4096
#define NBL  (BB * LL)          // 4096
#define RS3  (3 * DD)           // 3072

// ---------------- scratch (static device memory; no allocations) -------------
__device__ float g_meanpart[16 * DD];
__device__ float g_partial[160];
__device__ float g_Gpart[4 * DD * DD];    // syrk split-K=4 partials
__device__ float g_bqkv[3 * DD];

__device__ __align__(16) __half g_QKVh[MTOT * RS3];
__device__ __align__(16) __half g_QKVl[MTOT * RS3];
__device__ __align__(16) __half g_xh[MTOT * DD];
__device__ __align__(16) __half g_xl[MTOT * DD];
__device__ __align__(16) __half g_Mh[MTOT * DD];
__device__ __align__(16) __half g_Ml[MTOT * DD];
__device__ __align__(16) __half g_Mth[DD * NBL];
__device__ __align__(16) __half g_Mtl[DD * NBL];
__device__ __align__(16) __half g_Wqkvh[3 * DD * DD];
__device__ __align__(16) __half g_Woh[DD * DD];

// ---------------- small PTX helpers ------------------------------------------
__device__ __forceinline__ uint32_t smem_u32(const void* p) {
    uint32_t a;
    asm("{ .reg .u64 t; cvta.to.shared.u64 t, %1; cvt.u32.u64 %0, t; }"
        : "=r"(a) : "l"(p));
    return a;
}

__device__ __forceinline__ void cp_async16(uint32_t saddr, const void* gptr) {
    asm volatile("cp.async.ca.shared.global [%0], [%1], 16;"
                 :: "r"(saddr), "l"(gptr));
}
__device__ __forceinline__ void cp_commit() {
    asm volatile("cp.async.commit_group;" ::: "memory");
}
template <int N>
__device__ __forceinline__ void cp_wait() {
    asm volatile("cp.async.wait_group %0;" :: "n"(N) : "memory");
}

__device__ __forceinline__ void ldm_x4(uint32_t (&r)[4], uint32_t addr) {
    asm volatile("ldmatrix.sync.aligned.m8n8.x4.shared.b16 {%0,%1,%2,%3}, [%4];"
                 : "=r"(r[0]), "=r"(r[1]), "=r"(r[2]), "=r"(r[3]) : "r"(addr));
}
__device__ __forceinline__ void ldm_x4_trans(uint32_t (&r)[4], uint32_t addr) {
    asm volatile("ldmatrix.sync.aligned.m8n8.x4.trans.shared.b16 {%0,%1,%2,%3}, [%4];"
                 : "=r"(r[0]), "=r"(r[1]), "=r"(r[2]), "=r"(r[3]) : "r"(addr));
}

__device__ __forceinline__ void mma16816(float (&c)[4], const uint32_t (&a)[4],
                                         uint32_t b0, uint32_t b1) {
    asm volatile(
        "mma.sync.aligned.m16n8k16.row.col.f32.f16.f16.f32 "
        "{%0,%1,%2,%3}, {%4,%5,%6,%7}, {%8,%9}, {%0,%1,%2,%3};"
        : "+f"(c[0]), "+f"(c[1]), "+f"(c[2]), "+f"(c[3])
        : "r"(a[0]), "r"(a[1]), "r"(a[2]), "r"(a[3]), "r"(b0), "r"(b1));
}

__device__ __forceinline__ uint32_t pack_h2(__half x, __half y) {
    __half2 h = __halves2half2(x, y);
    return *(uint32_t*)&h;
}

struct __align__(8) half4 { __half a, b, c, d; };

// ---------------- prep mega-kernel: x split + weight rounds + bias concat ----
__global__ __launch_bounds__(256) void prep_kernel(
    const float* __restrict__ x,
    const float* __restrict__ Wq, const float* __restrict__ Wk,
    const float* __restrict__ Wv, const float* __restrict__ Wo,
    const float* __restrict__ bq, const float* __restrict__ bk,
    const float* __restrict__ bv,
    __half* __restrict__ xh, __half* __restrict__ xl,
    __half* __restrict__ Wqkvh, __half* __restrict__ Woh,
    float* __restrict__ bqkv)
{
    int t = blockIdx.x;
    int tid = threadIdx.x;
    if (t < 4096) {
        int i = t * 256 + tid;
        float4 v = ((const float4*)x)[i];
        __half h0 = __float2half_rn(v.x);
        __half h1 = __float2half_rn(v.y);
        __half h2 = __float2half_rn(v.z);
        __half h3 = __float2half_rn(v.w);
        half4 hv = {h0, h1, h2, h3};
        half4 lv = {__float2half_rn(v.x - __half2float(h0)),
                    __float2half_rn(v.y - __half2float(h1)),
                    __float2half_rn(v.z - __half2float(h2)),
                    __float2half_rn(v.w - __half2float(h3))};
        ((half4*)xh)[i] = hv;
        ((half4*)xl)[i] = lv;
    } else if (t < 8192) {
        int wsel = (t - 4096) >> 10;
        int blk = (t - 4096) & 1023;
        const float* src = (wsel == 0) ? Wq : (wsel == 1) ? Wk
                         : (wsel == 2) ? Wv : Wo;
        __half* dst = (wsel < 3) ? (Wqkvh + (size_t)wsel * DD * DD) : Woh;
        int i = blk * 256 + tid;
        float4 v = ((const float4*)src)[i];
        half4 hv = {__float2half_rn(v.x), __float2half_rn(v.y),
                    __float2half_rn(v.z), __float2half_rn(v.w)};
        ((half4*)dst)[i] = hv;
    } else {
        int i = (t - 8192) * 256 + tid;
        if (i < RS3) {
            const float* src = (i < DD) ? bq : (i < 2 * DD) ? bk : bv;
            bqkv[i] = src[i & (DD - 1)];
        }
    }
}

// ---------------- GEMM body ---------------------------------------------------
#define GPITCH 144
#define GTILE  (128 * GPITCH)
#define GBUF   (2 * GTILE)
#define GSMEM  (3 * GBUF)       // 110592 B

__device__ __forceinline__ void gemm_body(
    const __half* __restrict__ Ah, const __half* __restrict__ Al,
    const __half* __restrict__ Bh, const float* __restrict__ bias,
    float* __restrict__ C, float* __restrict__ Cpart,
    __half* __restrict__ Ch, __half* __restrict__ Cl,
    float qscale, int qcols, int locols, int npass,
    int lda, int Ksl, int N, int M,
    int bx, int by, int split, int nsplit, char* smem)
{
    const uint32_t sbase = smem_u32(smem);
    const int tid = threadIdx.x;
    const int lane = tid & 31;
    const int wid = tid >> 5;
    const int wm = wid >> 2;
    const int wn = wid & 3;

    const __half* pA[2] = {Ah, Al};
    const int Kc = Ksl >> 6;
    const int total = npass * Kc;

    float c[4][4][4];
#pragma unroll
    for (int i = 0; i < 4; i++)
#pragma unroll
        for (int j = 0; j < 4; j++)
#pragma unroll
            for (int f = 0; f < 4; f++) c[i][j][f] = 0.0f;

    auto load_chunk = [&](int g, int buf) {
        int p = (g >= Kc) ? 1 : 0;
        int kk = g - p * Kc;
        const __half* Abase = pA[p] + (size_t)by * 128 * lda + split * Ksl + kk * 64;
        const __half* Bbase = Bh + (size_t)bx * 128 * lda + split * Ksl + kk * 64;
        uint32_t aS = sbase + buf * GBUF;
        uint32_t bS = aS + GTILE;
#pragma unroll
        for (int j = 0; j < 4; j++) {
            int lin = tid + j * 256;
            int row = lin >> 3;
            int seg = lin & 7;
            cp_async16(aS + row * GPITCH + seg * 16,
                       Abase + (size_t)row * lda + seg * 8);
            cp_async16(bS + row * GPITCH + seg * 16,
                       Bbase + (size_t)row * lda + seg * 8);
        }
        cp_commit();
    };

    load_chunk(0, 0);
    load_chunk(1, 1);

    int buf = 0;
    for (int g = 0; g < total; g++) {
        if (g == total - 1) cp_wait<0>(); else cp_wait<1>();
        __syncthreads();
        if (g + 2 < total) {
            int nb = buf + 2; if (nb >= 3) nb -= 3;
            load_chunk(g + 2, nb);
        }

        const uint32_t aS = sbase + buf * GBUF;
        const uint32_t bS = aS + GTILE;
#pragma unroll
        for (int s = 0; s < 4; s++) {
            uint32_t a[4][4];
#pragma unroll
            for (int i = 0; i < 4; i++) {
                int row = wm * 64 + i * 16 + (lane & 15);
                ldm_x4(a[i], aS + row * GPITCH + s * 32 + ((lane >> 4) * 16));
            }
            uint32_t b[2][4];
#pragma unroll
            for (int j = 0; j < 2; j++) {
                int row = wn * 32 + j * 16 + ((lane >> 4) << 3) + (lane & 7);
                int off = ((lane >> 3) & 1) * 16;
                ldm_x4(b[j], bS + row * GPITCH + s * 32 + off);
            }
#pragma unroll
            for (int i = 0; i < 4; i++) {
#pragma unroll
                for (int j = 0; j < 2; j++) {
                    mma16816(c[i][2 * j], a[i], b[j][0], b[j][1]);
                    mma16816(c[i][2 * j + 1], a[i], b[j][2], b[j][3]);
                }
            }
        }
        if (++buf == 3) buf = 0;
    }

    const bool addb = (bias != nullptr) && (nsplit == 1);
#pragma unroll
    for (int i = 0; i < 4; i++) {
        int r0 = by * 128 + wm * 64 + i * 16 + (lane >> 2);
#pragma unroll
        for (int nt = 0; nt < 4; nt++) {
            int col = bx * 128 + wn * 32 + nt * 8 + (lane & 3) * 2;
            float bx0 = 0.0f, bx1 = 0.0f;
            if (addb) { bx0 = bias[col]; bx1 = bias[col + 1]; }
            float a0 = c[i][nt][0] + bx0, a1 = c[i][nt][1] + bx1;
            float a2 = c[i][nt][2] + bx0, a3 = c[i][nt][3] + bx1;
            if (Ch) {
                float sc = (col < qcols) ? qscale : 1.0f;
                a0 *= sc; a1 *= sc; a2 *= sc; a3 *= sc;
                __half h0 = __float2half_rn(a0), h1 = __float2half_rn(a1);
                __half h2 = __float2half_rn(a2), h3 = __float2half_rn(a3);
                *(__half2*)(Ch + (size_t)r0 * N + col) = __halves2half2(h0, h1);
                *(__half2*)(Ch + (size_t)(r0 + 8) * N + col) = __halves2half2(h2, h3);
                if (col < locols) {     // lo split only where consumed
                    *(__half2*)(Cl + (size_t)r0 * N + col) =
                        __halves2half2(__float2half_rn(a0 - __half2float(h0)),
                                       __float2half_rn(a1 - __half2float(h1)));
                    *(__half2*)(Cl + (size_t)(r0 + 8) * N + col) =
                        __halves2half2(__float2half_rn(a2 - __half2float(h2)),
                                       __float2half_rn(a3 - __half2float(h3)));
                }
            } else {
                float* dst = (nsplit == 1) ? C : (Cpart + (size_t)split * M * N);
                float2 v0 = {a0, a1}, v1 = {a2, a3};
                *(float2*)(dst + (size_t)r0 * N + col) = v0;
                *(float2*)(dst + (size_t)(r0 + 8) * N + col) = v1;
            }
        }
    }
}

// ---------------- QKV GEMM kernel --------------------------------------------
// V column tiles (bx >= vcut) use a single A pass (xh only).
__global__ __launch_bounds__(256, 2) void gemm2(
    const __half* __restrict__ Ah, const __half* __restrict__ Al,
    const __half* __restrict__ Bh, const float* __restrict__ bias,
    __half* __restrict__ Ch, __half* __restrict__ Cl,
    float qscale, int qcols, int locols, int vcut, int lda, int Ksl, int N)
{
    extern __shared__ __align__(16) char smem[];
    int npass = (blockIdx.x >= vcut) ? 1 : 2;
    gemm_body(Ah, Al, Bh, bias, nullptr, nullptr, Ch, Cl, qscale, qcols,
              locols, npass, lda, Ksl, N, gridDim.y * 128,
              blockIdx.x, blockIdx.y, 0, 1, smem);
}

// ---------------- fused mid: out-proj + symmetric SYRK sk4 + colmean ---------
// grid: 256 out-proj | 144 syrk (36 tri-tiles x 4 splits) | 64 colmean = 464
__global__ __launch_bounds__(256, 2) void fused_mid(
    const __half* __restrict__ Mh, const __half* __restrict__ Ml,
    const __half* __restrict__ Woh, const float* __restrict__ bo,
    float* __restrict__ out,
    const __half* __restrict__ Mth, const __half* __restrict__ Mtl,
    float* __restrict__ Gpart, float* __restrict__ meanpart)
{
    extern __shared__ __align__(16) char smem[];
    int t = blockIdx.x;
    if (t < 256) {
        // out projection (unsplit, direct write + bias)
        gemm_body(Mh, Ml, Woh, bo, out, nullptr, nullptr, nullptr,
                  1.0f, 0, 0, 2, DD, DD, DD, MTOT, t & 7, t >> 3, 0, 1, smem);
    } else if (t < 400) {
        int t2 = t - 256;
        int split = t2 / 36;
        int pair = t2 % 36;
        int ti = 0, s = pair;
        while (s >= 8 - ti) { s -= 8 - ti; ti++; }
        int tj = ti + s;
        gemm_body(Mth, Mtl, Mth, nullptr, nullptr, Gpart, nullptr, nullptr,
                  1.0f, 0, 0, 2, NBL, NBL / 4, DD, DD,
                  tj, ti, split, 4, smem);
    } else {
        int idx = t - 400;
        int col = (idx & 3) * 256 + threadIdx.x;
        int seg = idx >> 2;
        float s = 0.0f;
        size_t base = (size_t)seg * 256 * DD + col;
#pragma unroll 4
        for (int r = 0; r < 256; r++) {
            size_t o = base + (size_t)r * DD;
            s += __half2float(Mh[o]) + __half2float(Ml[o]);
        }
        meanpart[seg * DD + col] = s;
    }
}

// ---------------- decov per-tile: reduce 4 Gpart slices + cov + square -------
__global__ __launch_bounds__(256) void decov_tiles(
    const float* __restrict__ Gpart, const float* __restrict__ meanpart,
    float* __restrict__ partial)
{
    __shared__ float smrow[32];
    __shared__ float smcol[128];
    __shared__ float red[256];
    int pair = blockIdx.x % 36;
    int q = blockIdx.x / 36;
    int ti = 0, s0 = pair;
    while (s0 >= 8 - ti) { s0 -= 8 - ti; ti++; }
    int tj = ti + s0;
    const float w = (ti == tj) ? 1.0f : 2.0f;
    const float invN = 1.0f / (float)NBL;

    if (threadIdx.x < 160) {
        bool isRow = threadIdx.x < 32;
        int col = isRow ? (ti * 128 + q * 32 + threadIdx.x)
                        : (tj * 128 + threadIdx.x - 32);
        float ms = 0.0f;
#pragma unroll
        for (int seg = 0; seg < 16; seg++) ms += meanpart[seg * DD + col];
        ms *= invN;
        if (isRow) smrow[threadIdx.x] = ms;
        else smcol[threadIdx.x - 32] = ms;
    }
    __syncthreads();

    int row = ti * 128 + q * 32 + (threadIdx.x >> 3);
    int c0 = tj * 128 + (threadIdx.x & 7) * 16;
    float mi = smrow[threadIdx.x >> 3];
    float acc = 0.0f;
    size_t base = (size_t)row * DD + c0;
#pragma unroll
    for (int c4 = 0; c4 < 4; c4++) {
        int col = c0 + c4 * 4;
        float4 g = *(const float4*)(Gpart + base + c4 * 4);
#pragma unroll
        for (int p = 1; p < 4; p++) {
            float4 v = *(const float4*)(Gpart + (size_t)p * DD * DD + base + c4 * 4);
            g.x += v.x; g.y += v.y; g.z += v.z; g.w += v.w;
        }
        int lc = col - tj * 128;
        float cx = g.x * invN - mi * smcol[lc];
        float cy = g.y * invN - mi * smcol[lc + 1];
        float cz = g.z * invN - mi * smcol[lc + 2];
        float cw = g.w * invN - mi * smcol[lc + 3];
        if (row == col) cx = 0.0f;
        if (row == col + 1) cy = 0.0f;
        if (row == col + 2) cz = 0.0f;
        if (row == col + 3) cw = 0.0f;
        acc += cx * cx + cy * cy + cz * cz + cw * cw;
    }
    red[threadIdx.x] = acc * w;
    __syncthreads();
    for (int off = 128; off > 0; off >>= 1) {
        if (threadIdx.x < off) red[threadIdx.x] += red[threadIdx.x + off];
        __syncthreads();
    }
    if (threadIdx.x == 0) partial[blockIdx.x] = red[0];
}

__global__ void decov_final(const float* __restrict__ partial, float* __restrict__ out)
{
    if (threadIdx.x == 0) {
        float t = 0.0f;
        for (int i = 0; i < 144; i++) t += partial[i];
        out[0] = 0.5f * t;
    }
}

// ---------------- Attention: flash + mma.sync, fp16 inputs, cp.async ring ----
// S = Qh*Kh + Ql*Kh + Qh*Kl;  O = Ph*Vh (single pass)
#define AP 72
#define APB 144
#define KTB (64 * APB)
#define ASTG (3 * KTB)
#define ASMEM (3 * ASTG)        // 82944 B

__global__ __launch_bounds__(256, 2) void attn_mma(
    const __half* __restrict__ QKVh, const __half* __restrict__ QKVl,
    __half* __restrict__ Oh, __half* __restrict__ Ol)
{
    extern __shared__ __align__(16) char smem[];
    const uint32_t sbase = smem_u32(smem);

    const int tid = threadIdx.x;
    const int lane = tid & 31;
    const int w = tid >> 5;
    const int q0 = blockIdx.x * 128;
    const int h = blockIdx.y;
    const int b = blockIdx.z;

    uint32_t Qah[4][4], Qal[4][4];
    {
        int r0 = b * LL + q0 + w * 16 + (lane >> 2);
        int cb = h * DK + (lane & 3) * 2;
#pragma unroll
        for (int s = 0; s < 4; s++)
#pragma unroll
            for (int t2 = 0; t2 < 4; t2++) {
                size_t off = (size_t)(r0 + (t2 & 1) * 8) * RS3 + cb + s * 16 + (t2 >> 1) * 8;
                Qah[s][t2] = *(const uint32_t*)(QKVh + off);
                Qal[s][t2] = *(const uint32_t*)(QKVl + off);
            }
    }

    auto load_tile = [&](int kt, int stg) {
        uint32_t sb = sbase + stg * ASTG;
#pragma unroll
        for (int it = 0; it < 2; it++) {
            int lin = tid + it * 256;
            int row = lin >> 3;
            int seg = lin & 7;
            size_t goff = (size_t)(b * LL + kt + row) * RS3 + DD + h * DK + seg * 8;
            cp_async16(sb + row * APB + seg * 16, QKVh + goff);
            cp_async16(sb + KTB + row * APB + seg * 16, QKVl + goff);
            cp_async16(sb + 2 * KTB + row * APB + seg * 16, QKVh + goff + DD);
        }
        cp_commit();
    };

    float m0 = -1e30f, m1 = -1e30f, l0 = 0.0f, l1 = 0.0f;
    float co[8][4];
#pragma unroll
    for (int j = 0; j < 8; j++)
#pragma unroll
        for (int f = 0; f < 4; f++) co[j][f] = 0.0f;

    load_tile(0, 0);
    load_tile(64, 1);

    int buf = 0;
    for (int g = 0; g < 16; g++) {
        if (g == 15) cp_wait<0>(); else cp_wait<1>();
        __syncthreads();
        if (g + 2 < 16) {
            int nb = buf + 2; if (nb >= 3) nb -= 3;
            load_tile((g + 2) * 64, nb);
        }
        const uint32_t khs = sbase + buf * ASTG;
        const uint32_t kls = khs + KTB;
        const uint32_t vhs = khs + 2 * KTB;

        float sc[8][4];
#pragma unroll
        for (int j = 0; j < 8; j++)
#pragma unroll
            for (int f = 0; f < 4; f++) sc[j][f] = 0.0f;

#pragma unroll
        for (int s = 0; s < 4; s++) {
#pragma unroll
            for (int j = 0; j < 4; j++) {
                uint32_t roff = (j * 16 + ((lane >> 4) << 3) + (lane & 7)) * APB
                              + s * 32 + ((lane >> 3) & 1) * 16;
                uint32_t bh[4], bl[4];
                ldm_x4(bh, khs + roff);
                ldm_x4(bl, kls + roff);
                mma16816(sc[2 * j],     Qah[s], bh[0], bh[1]);
                mma16816(sc[2 * j + 1], Qah[s], bh[2], bh[3]);
                mma16816(sc[2 * j],     Qal[s], bh[0], bh[1]);
                mma16816(sc[2 * j + 1], Qal[s], bh[2], bh[3]);
                mma16816(sc[2 * j],     Qah[s], bl[0], bl[1]);
                mma16816(sc[2 * j + 1], Qah[s], bl[2], bl[3]);
            }
        }

        float t0 = -1e30f, t1 = -1e30f;
#pragma unroll
        for (int j = 0; j < 8; j++) {
            t0 = fmaxf(t0, fmaxf(sc[j][0], sc[j][1]));
            t1 = fmaxf(t1, fmaxf(sc[j][2], sc[j][3]));
        }
        t0 = fmaxf(t0, __shfl_xor_sync(0xffffffffu, t0, 1));
        t0 = fmaxf(t0, __shfl_xor_sync(0xffffffffu, t0, 2));
        t1 = fmaxf(t1, __shfl_xor_sync(0xffffffffu, t1, 1));
        t1 = fmaxf(t1, __shfl_xor_sync(0xffffffffu, t1, 2));
        float mn0 = fmaxf(m0, t0), mn1 = fmaxf(m1, t1);
        float f0 = __expf(m0 - mn0), f1 = __expf(m1 - mn1);
        float rs0 = 0.0f, rs1 = 0.0f;
#pragma unroll
        for (int j = 0; j < 8; j++) {
            sc[j][0] = __expf(sc[j][0] - mn0);
            sc[j][1] = __expf(sc[j][1] - mn0);
            sc[j][2] = __expf(sc[j][2] - mn1);
            sc[j][3] = __expf(sc[j][3] - mn1);
            rs0 += sc[j][0] + sc[j][1];
            rs1 += sc[j][2] + sc[j][3];
        }
        rs0 += __shfl_xor_sync(0xffffffffu, rs0, 1);
        rs0 += __shfl_xor_sync(0xffffffffu, rs0, 2);
        rs1 += __shfl_xor_sync(0xffffffffu, rs1, 1);
        rs1 += __shfl_xor_sync(0xffffffffu, rs1, 2);
        l0 = l0 * f0 + rs0;
        l1 = l1 * f1 + rs1;
        m0 = mn0; m1 = mn1;
#pragma unroll
        for (int j = 0; j < 8; j++) {
            co[j][0] *= f0; co[j][1] *= f0;
            co[j][2] *= f1; co[j][3] *= f1;
        }

        // ---- PV single pass: O += Ph @ Vh ----
#pragma unroll
        for (int s = 0; s < 4; s++) {
            uint32_t pah[4];
#pragma unroll
            for (int t2 = 0; t2 < 4; t2++) {
                int bk = 2 * s + (t2 >> 1);
                float p0 = sc[bk][(t2 & 1) * 2];
                float p1 = sc[bk][(t2 & 1) * 2 + 1];
                pah[t2] = pack_h2(__float2half_rn(p0), __float2half_rn(p1));
            }
#pragma unroll
            for (int j = 0; j < 4; j++) {
                uint32_t roff = (s * 16 + ((lane >> 3) & 1) * 8 + (lane & 7)) * APB
                              + (j * 16 + ((lane >> 4) & 1) * 8) * 2;
                uint32_t vbh[4];
                ldm_x4_trans(vbh, vhs + roff);
                mma16816(co[2 * j],     pah, vbh[0], vbh[1]);
                mma16816(co[2 * j + 1], pah, vbh[2], vbh[3]);
            }
        }
        if (++buf == 3) buf = 0;
    }

    float inv0 = 1.0f / l0, inv1 = 1.0f / l1;
    int grow = q0 + w * 16 + (lane >> 2);
    size_t base0 = (size_t)(b * LL + grow) * DD + h * DK;
    size_t base1 = base0 + (size_t)8 * DD;
#pragma unroll
    for (int j = 0; j < 8; j++) {
        int col = j * 8 + (lane & 3) * 2;
        float a0 = co[j][0] * inv0, a1 = co[j][1] * inv0;
        float a2 = co[j][2] * inv1, a3 = co[j][3] * inv1;
        __half h0 = __float2half_rn(a0), h1 = __float2half_rn(a1);
        __half h2 = __float2half_rn(a2), h3 = __float2half_rn(a3);
        *(__half2*)(Oh + base0 + col) = __halves2half2(h0, h1);
        *(__half2*)(Oh + base1 + col) = __halves2half2(h2, h3);
        *(__half2*)(Ol + base0 + col) =
            __halves2half2(__float2half_rn(a0 - __half2float(h0)),
                           __float2half_rn(a1 - __half2float(h1)));
        *(__half2*)(Ol + base1 + col) =
            __halves2half2(__float2half_rn(a2 - __half2float(h2)),
                           __float2half_rn(a3 - __half2float(h3)));
    }
}

// ---------------- transpose + split: (Mh+Ml)[NBL][DD] -> T[DD][NBL] ----------
__global__ __launch_bounds__(256) void transpose_split_fp16(
    const __half* __restrict__ Msh, const __half* __restrict__ Msl,
    __half* __restrict__ Th, __half* __restrict__ Tl)
{
    __shared__ float tile[32][33];
    int bx = blockIdx.x;
    int by = blockIdx.y;
    int tx = threadIdx.x;
    int ty = threadIdx.y;
#pragma unroll
    for (int j = 0; j < 32; j += 8) {
        size_t off = (size_t)(by * 32 + ty + j) * DD + bx * 32 + tx;
        tile[ty + j][tx] = __half2float(Msh[off]) + __half2float(Msl[off]);
    }
    __syncthreads();
#pragma unroll
    for (int j = 0; j < 32; j += 8) {
        float v = tile[tx][ty + j];
        __half h = __float2half_rn(v);
        __half l = __float2half_rn(v - __half2float(h));
        size_t off = (size_t)(bx * 32 + ty + j) * NBL + by * 32 + tx;
        Th[off] = h;
        Tl[off] = l;
    }
}

// ---------------- launch ------------------------------------------------------
extern "C" void kernel_launch(void* const* d_in, const int* in_sizes, int n_in,
                              void* d_out, int out_size)
{
    const float* x  = (const float*)d_in[0];
    const float* Wq = (const float*)d_in[1];
    const float* bq = (const float*)d_in[2];
    const float* Wk = (const float*)d_in[3];
    const float* bk = (const float*)d_in[4];
    const float* Wv = (const float*)d_in[5];
    const float* bv = (const float*)d_in[6];
    const float* Wo = (const float*)d_in[7];
    const float* bo = (const float*)d_in[8];
    float* out = (float*)d_out;

    float *meanpartp, *partp, *Gpart, *bqkv;
    cudaGetSymbolAddress((void**)&meanpartp, g_meanpart);
    cudaGetSymbolAddress((void**)&partp, g_partial);
    cudaGetSymbolAddress((void**)&Gpart, g_Gpart);
    cudaGetSymbolAddress((void**)&bqkv, g_bqkv);

    __half *QKVh, *QKVl, *xh, *xl, *Mh, *Ml, *Mth, *Mtl, *Wqkvh, *Woh;
    cudaGetSymbolAddress((void**)&QKVh, g_QKVh);
    cudaGetSymbolAddress((void**)&QKVl, g_QKVl);
    cudaGetSymbolAddress((void**)&xh, g_xh);
    cudaGetSymbolAddress((void**)&xl, g_xl);
    cudaGetSymbolAddress((void**)&Mh, g_Mh);
    cudaGetSymbolAddress((void**)&Ml, g_Ml);
    cudaGetSymbolAddress((void**)&Mth, g_Mth);
    cudaGetSymbolAddress((void**)&Mtl, g_Mtl);
    cudaGetSymbolAddress((void**)&Wqkvh, g_Wqkvh);
    cudaGetSymbolAddress((void**)&Woh, g_Woh);

    cudaFuncSetAttribute(gemm2, cudaFuncAttributeMaxDynamicSharedMemorySize,
                         GSMEM);
    cudaFuncSetAttribute(fused_mid, cudaFuncAttributeMaxDynamicSharedMemorySize,
                         GSMEM);
    cudaFuncSetAttribute(attn_mma, cudaFuncAttributeMaxDynamicSharedMemorySize,
                         ASMEM);

    // 1. prep
    prep_kernel<<<8204, 256>>>(x, Wq, Wk, Wv, Wo, bq, bk, bv,
                               xh, xl, Wqkvh, Woh, bqkv);

    // 2. fused QKV projection (V tiles: 1 A-pass; lo split skipped for V cols)
    dim3 gQKV(RS3 / 128, MTOT / 128, 1);
    gemm2<<<gQKV, 256, GSMEM>>>(xh, xl, Wqkvh, bqkv,
                                QKVh, QKVl, 0.125f, DD, 2 * DD, 16, DD, DD, RS3);

    // 3. attention
    dim3 gAttn(LL / 128, HH, BB);
    attn_mma<<<gAttn, 256, ASMEM>>>(QKVh, QKVl, Mh, Ml);

    // 4. transposed split of M
    transpose_split_fp16<<<dim3(DD / 32, NBL / 32), dim3(32, 8)>>>(Mh, Ml, Mth, Mtl);

    // 5. fused: out-proj (256) + SYRK sk4 (144) + colmean-part (64)
    fused_mid<<<464, 256, GSMEM>>>(Mh, Ml, Woh, bo, out,
                                   Mth, Mtl, Gpart, meanpartp);

    // 6. decov tiles (reduce 4 Gpart slices + inline means + cov + square)
    decov_tiles<<<144, 256>>>(Gpart, meanpartp, partp);

    // 7. final scalar
    decov_final<<<1, 32>>>(partp, out + (out_size - 1));
}

// round 14
// speedup vs baseline: 1.3284x; 1.1196x over previous
#include <cuda_runtime.h>
#include <cuda_fp16.h>
#include <math.h>
#include <stdint.h>

// Problem constants
#define BB 4
#define LL 1024
#define DD 1024
#define HH 16
#define DK 64
#define MTOT (BB * LL)          // 4096
#define NBL  (BB * LL)          // 4096
#define RS3  (3 * DD)           // 3072

// ---------------- scratch (static device memory; no allocations) -------------
__device__ float g_meanpart[16 * DD];
__device__ float g_partial[160];
__device__ float g_Gpart[4 * DD * DD];    // syrk split-K=4 partials
__device__ float g_bqkv[3 * DD];

__device__ __align__(16) __half g_QKVh[MTOT * RS3];
__device__ __align__(16) __half g_QKVl[MTOT * DD];   // lo split: Q cols only
__device__ __align__(16) __half g_xh[MTOT * DD];
__device__ __align__(16) __half g_xl[MTOT * DD];
__device__ __align__(16) __half g_Mh[MTOT * DD];
__device__ __align__(16) __half g_Ml[MTOT * DD];
__device__ __align__(16) __half g_Mth[DD * NBL];
__device__ __align__(16) __half g_Mtl[DD * NBL];
__device__ __align__(16) __half g_Wqkvh[3 * DD * DD];
__device__ __align__(16) __half g_Woh[DD * DD];

// ---------------- small PTX helpers ------------------------------------------
__device__ __forceinline__ uint32_t smem_u32(const void* p) {
    uint32_t a;
    asm("{ .reg .u64 t; cvta.to.shared.u64 t, %1; cvt.u32.u64 %0, t; }"
        : "=r"(a) : "l"(p));
    return a;
}

__device__ __forceinline__ void cp_async16(uint32_t saddr, const void* gptr) {
    asm volatile("cp.async.ca.shared.global [%0], [%1], 16;"
                 :: "r"(saddr), "l"(gptr));
}
__device__ __forceinline__ void cp_commit() {
    asm volatile("cp.async.commit_group;" ::: "memory");
}
template <int N>
__device__ __forceinline__ void cp_wait() {
    asm volatile("cp.async.wait_group %0;" :: "n"(N) : "memory");
}

__device__ __forceinline__ void ldm_x4(uint32_t (&r)[4], uint32_t addr) {
    asm volatile("ldmatrix.sync.aligned.m8n8.x4.shared.b16 {%0,%1,%2,%3}, [%4];"
                 : "=r"(r[0]), "=r"(r[1]), "=r"(r[2]), "=r"(r[3]) : "r"(addr));
}
__device__ __forceinline__ void ldm_x4_trans(uint32_t (&r)[4], uint32_t addr) {
    asm volatile("ldmatrix.sync.aligned.m8n8.x4.trans.shared.b16 {%0,%1,%2,%3}, [%4];"
                 : "=r"(r[0]), "=r"(r[1]), "=r"(r[2]), "=r"(r[3]) : "r"(addr));
}

__device__ __forceinline__ void mma16816(float (&c)[4], const uint32_t (&a)[4],
                                         uint32_t b0, uint32_t b1) {
    asm volatile(
        "mma.sync.aligned.m16n8k16.row.col.f32.f16.f16.f32 "
        "{%0,%1,%2,%3}, {%4,%5,%6,%7}, {%8,%9}, {%0,%1,%2,%3};"
        : "+f"(c[0]), "+f"(c[1]), "+f"(c[2]), "+f"(c[3])
        : "r"(a[0]), "r"(a[1]), "r"(a[2]), "r"(a[3]), "r"(b0), "r"(b1));
}

__device__ __forceinline__ uint32_t pack_h2(__half x, __half y) {
    __half2 h = __halves2half2(x, y);
    return *(uint32_t*)&h;
}

struct __align__(8) half4 { __half a, b, c, d; };

// ---------------- prep mega-kernel: x split + weight rounds + bias concat ----
__global__ __launch_bounds__(256) void prep_kernel(
    const float* __restrict__ x,
    const float* __restrict__ Wq, const float* __restrict__ Wk,
    const float* __restrict__ Wv, const float* __restrict__ Wo,
    const float* __restrict__ bq, const float* __restrict__ bk,
    const float* __restrict__ bv,
    __half* __restrict__ xh, __half* __restrict__ xl,
    __half* __restrict__ Wqkvh, __half* __restrict__ Woh,
    float* __restrict__ bqkv)
{
    int t = blockIdx.x;
    int tid = threadIdx.x;
    if (t < 4096) {
        int i = t * 256 + tid;
        float4 v = ((const float4*)x)[i];
        __half h0 = __float2half_rn(v.x);
        __half h1 = __float2half_rn(v.y);
        __half h2 = __float2half_rn(v.z);
        __half h3 = __float2half_rn(v.w);
        half4 hv = {h0, h1, h2, h3};
        half4 lv = {__float2half_rn(v.x - __half2float(h0)),
                    __float2half_rn(v.y - __half2float(h1)),
                    __float2half_rn(v.z - __half2float(h2)),
                    __float2half_rn(v.w - __half2float(h3))};
        ((half4*)xh)[i] = hv;
        ((half4*)xl)[i] = lv;
    } else if (t < 8192) {
        int wsel = (t - 4096) >> 10;
        int blk = (t - 4096) & 1023;
        const float* src = (wsel == 0) ? Wq : (wsel == 1) ? Wk
                         : (wsel == 2) ? Wv : Wo;
        __half* dst = (wsel < 3) ? (Wqkvh + (size_t)wsel * DD * DD) : Woh;
        int i = blk * 256 + tid;
        float4 v = ((const float4*)src)[i];
        half4 hv = {__float2half_rn(v.x), __float2half_rn(v.y),
                    __float2half_rn(v.z), __float2half_rn(v.w)};
        ((half4*)dst)[i] = hv;
    } else {
        int i = (t - 8192) * 256 + tid;
        if (i < RS3) {
            const float* src = (i < DD) ? bq : (i < 2 * DD) ? bk : bv;
            bqkv[i] = src[i & (DD - 1)];
        }
    }
}

// ---------------- GEMM body ---------------------------------------------------
#define GPITCH 144
#define GTILE  (128 * GPITCH)
#define GBUF   (2 * GTILE)
#define GSMEM  (3 * GBUF)       // 110592 B

__device__ __forceinline__ void gemm_body(
    const __half* __restrict__ Ah, const __half* __restrict__ Al,
    const __half* __restrict__ Bh, const float* __restrict__ bias,
    float* __restrict__ C, float* __restrict__ Cpart,
    __half* __restrict__ Ch, __half* __restrict__ Cl,
    float qscale, int qcols, int locols, int npass, int Nlo,
    int lda, int Ksl, int N, int M,
    int bx, int by, int split, int nsplit, char* smem)
{
    const uint32_t sbase = smem_u32(smem);
    const int tid = threadIdx.x;
    const int lane = tid & 31;
    const int wid = tid >> 5;
    const int wm = wid >> 2;
    const int wn = wid & 3;

    const __half* pA[2] = {Ah, Al};
    const int Kc = Ksl >> 6;
    const int total = npass * Kc;

    float c[4][4][4];
#pragma unroll
    for (int i = 0; i < 4; i++)
#pragma unroll
        for (int j = 0; j < 4; j++)
#pragma unroll
            for (int f = 0; f < 4; f++) c[i][j][f] = 0.0f;

    auto load_chunk = [&](int g, int buf) {
        int p = (g >= Kc) ? 1 : 0;
        int kk = g - p * Kc;
        const __half* Abase = pA[p] + (size_t)by * 128 * lda + split * Ksl + kk * 64;
        const __half* Bbase = Bh + (size_t)bx * 128 * lda + split * Ksl + kk * 64;
        uint32_t aS = sbase + buf * GBUF;
        uint32_t bS = aS + GTILE;
#pragma unroll
        for (int j = 0; j < 4; j++) {
            int lin = tid + j * 256;
            int row = lin >> 3;
            int seg = lin & 7;
            cp_async16(aS + row * GPITCH + seg * 16,
                       Abase + (size_t)row * lda + seg * 8);
            cp_async16(bS + row * GPITCH + seg * 16,
                       Bbase + (size_t)row * lda + seg * 8);
        }
        cp_commit();
    };

    load_chunk(0, 0);
    load_chunk(1, 1);

    int buf = 0;
    for (int g = 0; g < total; g++) {
        if (g == total - 1) cp_wait<0>(); else cp_wait<1>();
        __syncthreads();
        if (g + 2 < total) {
            int nb = buf + 2; if (nb >= 3) nb -= 3;
            load_chunk(g + 2, nb);
        }

        const uint32_t aS = sbase + buf * GBUF;
        const uint32_t bS = aS + GTILE;
#pragma unroll
        for (int s = 0; s < 4; s++) {
            uint32_t a[4][4];
#pragma unroll
            for (int i = 0; i < 4; i++) {
                int row = wm * 64 + i * 16 + (lane & 15);
                ldm_x4(a[i], aS + row * GPITCH + s * 32 + ((lane >> 4) * 16));
            }
            uint32_t b[2][4];
#pragma unroll
            for (int j = 0; j < 2; j++) {
                int row = wn * 32 + j * 16 + ((lane >> 4) << 3) + (lane & 7);
                int off = ((lane >> 3) & 1) * 16;
                ldm_x4(b[j], bS + row * GPITCH + s * 32 + off);
            }
#pragma unroll
            for (int i = 0; i < 4; i++) {
#pragma unroll
                for (int j = 0; j < 2; j++) {
                    mma16816(c[i][2 * j], a[i], b[j][0], b[j][1]);
                    mma16816(c[i][2 * j + 1], a[i], b[j][2], b[j][3]);
                }
            }
        }
        if (++buf == 3) buf = 0;
    }

    const bool addb = (bias != nullptr) && (nsplit == 1);
#pragma unroll
    for (int i = 0; i < 4; i++) {
        int r0 = by * 128 + wm * 64 + i * 16 + (lane >> 2);
#pragma unroll
        for (int nt = 0; nt < 4; nt++) {
            int col = bx * 128 + wn * 32 + nt * 8 + (lane & 3) * 2;
            float bx0 = 0.0f, bx1 = 0.0f;
            if (addb) { bx0 = bias[col]; bx1 = bias[col + 1]; }
            float a0 = c[i][nt][0] + bx0, a1 = c[i][nt][1] + bx1;
            float a2 = c[i][nt][2] + bx0, a3 = c[i][nt][3] + bx1;
            if (Ch) {
                float sc = (col < qcols) ? qscale : 1.0f;
                a0 *= sc; a1 *= sc; a2 *= sc; a3 *= sc;
                __half h0 = __float2half_rn(a0), h1 = __float2half_rn(a1);
                __half h2 = __float2half_rn(a2), h3 = __float2half_rn(a3);
                *(__half2*)(Ch + (size_t)r0 * N + col) = __halves2half2(h0, h1);
                *(__half2*)(Ch + (size_t)(r0 + 8) * N + col) = __halves2half2(h2, h3);
                if (col < locols) {     // lo split only where consumed
                    *(__half2*)(Cl + (size_t)r0 * Nlo + col) =
                        __halves2half2(__float2half_rn(a0 - __half2float(h0)),
                                       __float2half_rn(a1 - __half2float(h1)));
                    *(__half2*)(Cl + (size_t)(r0 + 8) * Nlo + col) =
                        __halves2half2(__float2half_rn(a2 - __half2float(h2)),
                                       __float2half_rn(a3 - __half2float(h3)));
                }
            } else {
                float* dst = (nsplit == 1) ? C : (Cpart + (size_t)split * M * N);
                float2 v0 = {a0, a1}, v1 = {a2, a3};
                *(float2*)(dst + (size_t)r0 * N + col) = v0;
                *(float2*)(dst + (size_t)(r0 + 8) * N + col) = v1;
            }
        }
    }
}

// ---------------- QKV GEMM kernel --------------------------------------------
// K/V column tiles (bx >= vcut) use a single A pass (xh only).
__global__ __launch_bounds__(256, 2) void gemm2(
    const __half* __restrict__ Ah, const __half* __restrict__ Al,
    const __half* __restrict__ Bh, const float* __restrict__ bias,
    __half* __restrict__ Ch, __half* __restrict__ Cl,
    float qscale, int qcols, int locols, int vcut, int Nlo,
    int lda, int Ksl, int N)
{
    extern __shared__ __align__(16) char smem[];
    int npass = (blockIdx.x >= vcut) ? 1 : 2;
    gemm_body(Ah, Al, Bh, bias, nullptr, nullptr, Ch, Cl, qscale, qcols,
              locols, npass, Nlo, lda, Ksl, N, gridDim.y * 128,
              blockIdx.x, blockIdx.y, 0, 1, smem);
}

// ---------------- fused mid: out-proj + symmetric SYRK sk4 + colmean ---------
// grid: 256 out-proj | 144 syrk (36 tri-tiles x 4 splits) | 64 colmean = 464
__global__ __launch_bounds__(256, 2) void fused_mid(
    const __half* __restrict__ Mh, const __half* __restrict__ Ml,
    const __half* __restrict__ Woh, const float* __restrict__ bo,
    float* __restrict__ out,
    const __half* __restrict__ Mth, const __half* __restrict__ Mtl,
    float* __restrict__ Gpart, float* __restrict__ meanpart)
{
    extern __shared__ __align__(16) char smem[];
    int t = blockIdx.x;
    if (t < 256) {
        // out projection (unsplit, direct write + bias)
        gemm_body(Mh, Ml, Woh, bo, out, nullptr, nullptr, nullptr,
                  1.0f, 0, 0, 2, DD, DD, DD, DD, MTOT, t & 7, t >> 3, 0, 1, smem);
    } else if (t < 400) {
        int t2 = t - 256;
        int split = t2 / 36;
        int pair = t2 % 36;
        int ti = 0, s = pair;
        while (s >= 8 - ti) { s -= 8 - ti; ti++; }
        int tj = ti + s;
        gemm_body(Mth, Mtl, Mth, nullptr, nullptr, Gpart, nullptr, nullptr,
                  1.0f, 0, 0, 2, DD, NBL, NBL / 4, DD, DD,
                  tj, ti, split, 4, smem);
    } else {
        int idx = t - 400;
        int col = (idx & 3) * 256 + threadIdx.x;
        int seg = idx >> 2;
        float s = 0.0f;
        size_t base = (size_t)seg * 256 * DD + col;
#pragma unroll 4
        for (int r = 0; r < 256; r++) {
            size_t o = base + (size_t)r * DD;
            s += __half2float(Mh[o]) + __half2float(Ml[o]);
        }
        meanpart[seg * DD + col] = s;
    }
}

// ---------------- decov per-tile: reduce 4 Gpart slices + cov + square -------
__global__ __launch_bounds__(256) void decov_tiles(
    const float* __restrict__ Gpart, const float* __restrict__ meanpart,
    float* __restrict__ partial)
{
    __shared__ float smrow[32];
    __shared__ float smcol[128];
    __shared__ float red[256];
    int pair = blockIdx.x % 36;
    int q = blockIdx.x / 36;
    int ti = 0, s0 = pair;
    while (s0 >= 8 - ti) { s0 -= 8 - ti; ti++; }
    int tj = ti + s0;
    const float w = (ti == tj) ? 1.0f : 2.0f;
    const float invN = 1.0f / (float)NBL;

    if (threadIdx.x < 160) {
        bool isRow = threadIdx.x < 32;
        int col = isRow ? (ti * 128 + q * 32 + threadIdx.x)
                        : (tj * 128 + threadIdx.x - 32);
        float ms = 0.0f;
#pragma unroll
        for (int seg = 0; seg < 16; seg++) ms += meanpart[seg * DD + col];
        ms *= invN;
        if (isRow) smrow[threadIdx.x] = ms;
        else smcol[threadIdx.x - 32] = ms;
    }
    __syncthreads();

    int row = ti * 128 + q * 32 + (threadIdx.x >> 3);
    int c0 = tj * 128 + (threadIdx.x & 7) * 16;
    float mi = smrow[threadIdx.x >> 3];
    float acc = 0.0f;
    size_t base = (size_t)row * DD + c0;
#pragma unroll
    for (int c4 = 0; c4 < 4; c4++) {
        int col = c0 + c4 * 4;
        float4 g = *(const float4*)(Gpart + base + c4 * 4);
#pragma unroll
        for (int p = 1; p < 4; p++) {
            float4 v = *(const float4*)(Gpart + (size_t)p * DD * DD + base + c4 * 4);
            g.x += v.x; g.y += v.y; g.z += v.z; g.w += v.w;
        }
        int lc = col - tj * 128;
        float cx = g.x * invN - mi * smcol[lc];
        float cy = g.y * invN - mi * smcol[lc + 1];
        float cz = g.z * invN - mi * smcol[lc + 2];
        float cw = g.w * invN - mi * smcol[lc + 3];
        if (row == col) cx = 0.0f;
        if (row == col + 1) cy = 0.0f;
        if (row == col + 2) cz = 0.0f;
        if (row == col + 3) cw = 0.0f;
        acc += cx * cx + cy * cy + cz * cz + cw * cw;
    }
    red[threadIdx.x] = acc * w;
    __syncthreads();
    for (int off = 128; off > 0; off >>= 1) {
        if (threadIdx.x < off) red[threadIdx.x] += red[threadIdx.x + off];
        __syncthreads();
    }
    if (threadIdx.x == 0) partial[blockIdx.x] = red[0];
}

__global__ void decov_final(const float* __restrict__ partial, float* __restrict__ out)
{
    if (threadIdx.x == 0) {
        float t = 0.0f;
        for (int i = 0; i < 144; i++) t += partial[i];
        out[0] = 0.5f * t;
    }
}

// ---------------- Attention: flash + mma.sync, fp16 inputs, cp.async ring ----
// S = Qh*Kh + Ql*Kh;  O = Ph*Vh.  Stage tiles: Kh, Vh only.
#define AP 72
#define APB 144
#define KTB (64 * APB)
#define ASTG (2 * KTB)
#define ASMEM (3 * ASTG)        // 55296 B

__global__ __launch_bounds__(256, 2) void attn_mma(
    const __half* __restrict__ QKVh, const __half* __restrict__ QKVl,
    __half* __restrict__ Oh, __half* __restrict__ Ol)
{
    extern __shared__ __align__(16) char smem[];
    const uint32_t sbase = smem_u32(smem);

    const int tid = threadIdx.x;
    const int lane = tid & 31;
    const int w = tid >> 5;
    const int q0 = blockIdx.x * 128;
    const int h = blockIdx.y;
    const int b = blockIdx.z;

    uint32_t Qah[4][4], Qal[4][4];
    {
        int r0 = b * LL + q0 + w * 16 + (lane >> 2);
        int cb = h * DK + (lane & 3) * 2;
#pragma unroll
        for (int s = 0; s < 4; s++)
#pragma unroll
            for (int t2 = 0; t2 < 4; t2++) {
                int rr = r0 + (t2 & 1) * 8;
                int cc = cb + s * 16 + (t2 >> 1) * 8;
                Qah[s][t2] = *(const uint32_t*)(QKVh + (size_t)rr * RS3 + cc);
                Qal[s][t2] = *(const uint32_t*)(QKVl + (size_t)rr * DD + cc);
            }
    }

    auto load_tile = [&](int kt, int stg) {
        uint32_t sb = sbase + stg * ASTG;
#pragma unroll
        for (int it = 0; it < 2; it++) {
            int lin = tid + it * 256;
            int row = lin >> 3;
            int seg = lin & 7;
            size_t goff = (size_t)(b * LL + kt + row) * RS3 + DD + h * DK + seg * 8;
            cp_async16(sb + row * APB + seg * 16, QKVh + goff);              // Kh
            cp_async16(sb + KTB + row * APB + seg * 16, QKVh + goff + DD);   // Vh
        }
        cp_commit();
    };

    float m0 = -1e30f, m1 = -1e30f, l0 = 0.0f, l1 = 0.0f;
    float co[8][4];
#pragma unroll
    for (int j = 0; j < 8; j++)
#pragma unroll
        for (int f = 0; f < 4; f++) co[j][f] = 0.0f;

    load_tile(0, 0);
    load_tile(64, 1);

    int buf = 0;
    for (int g = 0; g < 16; g++) {
        if (g == 15) cp_wait<0>(); else cp_wait<1>();
        __syncthreads();
        if (g + 2 < 16) {
            int nb = buf + 2; if (nb >= 3) nb -= 3;
            load_tile((g + 2) * 64, nb);
        }
        const uint32_t khs = sbase + buf * ASTG;
        const uint32_t vhs = khs + KTB;

        float sc[8][4];
#pragma unroll
        for (int j = 0; j < 8; j++)
#pragma unroll
            for (int f = 0; f < 4; f++) sc[j][f] = 0.0f;

#pragma unroll
        for (int s = 0; s < 4; s++) {
#pragma unroll
            for (int j = 0; j < 4; j++) {
                uint32_t roff = (j * 16 + ((lane >> 4) << 3) + (lane & 7)) * APB
                              + s * 32 + ((lane >> 3) & 1) * 16;
                uint32_t bh[4];
                ldm_x4(bh, khs + roff);
                mma16816(sc[2 * j],     Qah[s], bh[0], bh[1]);
                mma16816(sc[2 * j + 1], Qah[s], bh[2], bh[3]);
                mma16816(sc[2 * j],     Qal[s], bh[0], bh[1]);
                mma16816(sc[2 * j + 1], Qal[s], bh[2], bh[3]);
            }
        }

        float t0 = -1e30f, t1 = -1e30f;
#pragma unroll
        for (int j = 0; j < 8; j++) {
            t0 = fmaxf(t0, fmaxf(sc[j][0], sc[j][1]));
            t1 = fmaxf(t1, fmaxf(sc[j][2], sc[j][3]));
        }
        t0 = fmaxf(t0, __shfl_xor_sync(0xffffffffu, t0, 1));
        t0 = fmaxf(t0, __shfl_xor_sync(0xffffffffu, t0, 2));
        t1 = fmaxf(t1, __shfl_xor_sync(0xffffffffu, t1, 1));
        t1 = fmaxf(t1, __shfl_xor_sync(0xffffffffu, t1, 2));
        float mn0 = fmaxf(m0, t0), mn1 = fmaxf(m1, t1);
        float f0 = __expf(m0 - mn0), f1 = __expf(m1 - mn1);
        float rs0 = 0.0f, rs1 = 0.0f;
#pragma unroll
        for (int j = 0; j < 8; j++) {
            sc[j][0] = __expf(sc[j][0] - mn0);
            sc[j][1] = __expf(sc[j][1] - mn0);
            sc[j][2] = __expf(sc[j][2] - mn1);
            sc[j][3] = __expf(sc[j][3] - mn1);
            rs0 += sc[j][0] + sc[j][1];
            rs1 += sc[j][2] + sc[j][3];
        }
        rs0 += __shfl_xor_sync(0xffffffffu, rs0, 1);
        rs0 += __shfl_xor_sync(0xffffffffu, rs0, 2);
        rs1 += __shfl_xor_sync(0xffffffffu, rs1, 1);
        rs1 += __shfl_xor_sync(0xffffffffu, rs1, 2);
        l0 = l0 * f0 + rs0;
        l1 = l1 * f1 + rs1;
        m0 = mn0; m1 = mn1;
#pragma unroll
        for (int j = 0; j < 8; j++) {
            co[j][0] *= f0; co[j][1] *= f0;
            co[j][2] *= f1; co[j][3] *= f1;
        }

        // ---- PV single pass: O += Ph @ Vh ----
#pragma unroll
        for (int s = 0; s < 4; s++) {
            uint32_t pah[4];
#pragma unroll
            for (int t2 = 0; t2 < 4; t2++) {
                int bk = 2 * s + (t2 >> 1);
                float p0 = sc[bk][(t2 & 1) * 2];
                float p1 = sc[bk][(t2 & 1) * 2 + 1];
                pah[t2] = pack_h2(__float2half_rn(p0), __float2half_rn(p1));
            }
#pragma unroll
            for (int j = 0; j < 4; j++) {
                uint32_t roff = (s * 16 + ((lane >> 3) & 1) * 8 + (lane & 7)) * APB
                              + (j * 16 + ((lane >> 4) & 1) * 8) * 2;
                uint32_t vbh[4];
                ldm_x4_trans(vbh, vhs + roff);
                mma16816(co[2 * j],     pah, vbh[0], vbh[1]);
                mma16816(co[2 * j + 1], pah, vbh[2], vbh[3]);
            }
        }
        if (++buf == 3) buf = 0;
    }

    float inv0 = 1.0f / l0, inv1 = 1.0f / l1;
    int grow = q0 + w * 16 + (lane >> 2);
    size_t base0 = (size_t)(b * LL + grow) * DD + h * DK;
    size_t base1 = base0 + (size_t)8 * DD;
#pragma unroll
    for (int j = 0; j < 8; j++) {
        int col = j * 8 + (lane & 3) * 2;
        float a0 = co[j][0] * inv0, a1 = co[j][1] * inv0;
        float a2 = co[j][2] * inv1, a3 = co[j][3] * inv1;
        __half h0 = __float2half_rn(a0), h1 = __float2half_rn(a1);
        __half h2 = __float2half_rn(a2), h3 = __float2half_rn(a3);
        *(__half2*)(Oh + base0 + col) = __halves2half2(h0, h1);
        *(__half2*)(Oh + base1 + col) = __halves2half2(h2, h3);
        *(__half2*)(Ol + base0 + col) =
            __halves2half2(__float2half_rn(a0 - __half2float(h0)),
                           __float2half_rn(a1 - __half2float(h1)));
        *(__half2*)(Ol + base1 + col) =
            __halves2half2(__float2half_rn(a2 - __half2float(h2)),
                           __float2half_rn(a3 - __half2float(h3)));
    }
}

// ---------------- transpose + split: (Mh+Ml)[NBL][DD] -> T[DD][NBL] ----------
__global__ __launch_bounds__(256) void transpose_split_fp16(
    const __half* __restrict__ Msh, const __half* __restrict__ Msl,
    __half* __restrict__ Th, __half* __restrict__ Tl)
{
    __shared__ float tile[32][33];
    int bx = blockIdx.x;
    int by = blockIdx.y;
    int tx = threadIdx.x;
    int ty = threadIdx.y;
#pragma unroll
    for (int j = 0; j < 32; j += 8) {
        size_t off = (size_t)(by * 32 + ty + j) * DD + bx * 32 + tx;
        tile[ty + j][tx] = __half2float(Msh[off]) + __half2float(Msl[off]);
    }
    __syncthreads();
#pragma unroll
    for (int j = 0; j < 32; j += 8) {
        float v = tile[tx][ty + j];
        __half h = __float2half_rn(v);
        __half l = __float2half_rn(v - __half2float(h));
        size_t off = (size_t)(bx * 32 + ty + j) * NBL + by * 32 + tx;
        Th[off] = h;
        Tl[off] = l;
    }
}

// ---------------- launch ------------------------------------------------------
extern "C" void kernel_launch(void* const* d_in, const int* in_sizes, int n_in,
                              void* d_out, int out_size)
{
    const float* x  = (const float*)d_in[0];
    const float* Wq = (const float*)d_in[1];
    const float* bq = (const float*)d_in[2];
    const float* Wk = (const float*)d_in[3];
    const float* bk = (const float*)d_in[4];
    const float* Wv = (const float*)d_in[5];
    const float* bv = (const float*)d_in[6];
    const float* Wo = (const float*)d_in[7];
    const float* bo = (const float*)d_in[8];
    float* out = (float*)d_out;

    float *meanpartp, *partp, *Gpart, *bqkv;
    cudaGetSymbolAddress((void**)&meanpartp, g_meanpart);
    cudaGetSymbolAddress((void**)&partp, g_partial);
    cudaGetSymbolAddress((void**)&Gpart, g_Gpart);
    cudaGetSymbolAddress((void**)&bqkv, g_bqkv);

    __half *QKVh, *QKVl, *xh, *xl, *Mh, *Ml, *Mth, *Mtl, *Wqkvh, *Woh;
    cudaGetSymbolAddress((void**)&QKVh, g_QKVh);
    cudaGetSymbolAddress((void**)&QKVl, g_QKVl);
    cudaGetSymbolAddress((void**)&xh, g_xh);
    cudaGetSymbolAddress((void**)&xl, g_xl);
    cudaGetSymbolAddress((void**)&Mh, g_Mh);
    cudaGetSymbolAddress((void**)&Ml, g_Ml);
    cudaGetSymbolAddress((void**)&Mth, g_Mth);
    cudaGetSymbolAddress((void**)&Mtl, g_Mtl);
    cudaGetSymbolAddress((void**)&Wqkvh, g_Wqkvh);
    cudaGetSymbolAddress((void**)&Woh, g_Woh);

    cudaFuncSetAttribute(gemm2, cudaFuncAttributeMaxDynamicSharedMemorySize,
                         GSMEM);
    cudaFuncSetAttribute(fused_mid, cudaFuncAttributeMaxDynamicSharedMemorySize,
                         GSMEM);
    cudaFuncSetAttribute(attn_mma, cudaFuncAttributeMaxDynamicSharedMemorySize,
                         ASMEM);

    // 1. prep
    prep_kernel<<<8204, 256>>>(x, Wq, Wk, Wv, Wo, bq, bk, bv,
                               xh, xl, Wqkvh, Woh, bqkv);

    // 2. fused QKV projection (K/V tiles: 1 A-pass; lo split only for Q cols)
    dim3 gQKV(RS3 / 128, MTOT / 128, 1);
    gemm2<<<gQKV, 256, GSMEM>>>(xh, xl, Wqkvh, bqkv,
                                QKVh, QKVl, 0.125f, DD, DD, 8, DD, DD, DD, RS3);

    // 3. attention
    dim3 gAttn(LL / 128, HH, BB);
    attn_mma<<<gAttn, 256, ASMEM>>>(QKVh, QKVl, Mh, Ml);

    // 4. transposed split of M
    transpose_split_fp16<<<dim3(DD / 32, NBL / 32), dim3(32, 8)>>>(Mh, Ml, Mth, Mtl);

    // 5. fused: out-proj (256) + SYRK sk4 (144) + colmean-part (64)
    fused_mid<<<464, 256, GSMEM>>>(Mh, Ml, Woh, bo, out,
                                   Mth, Mtl, Gpart, meanpartp);

    // 6. decov tiles (reduce 4 Gpart slices + inline means + cov + square)
    decov_tiles<<<144, 256>>>(Gpart, meanpartp, partp);

    // 7. final scalar
    decov_final<<<1, 32>>>(partp, out + (out_size - 1));
}

// round 15
// speedup vs baseline: 1.9201x; 1.4455x over previous
#include <cuda_runtime.h>
#include <cuda_fp16.h>
#include <math.h>
#include <stdint.h>

// Problem constants
#define BB 4
#define LL 1024
#define DD 1024
#define HH 16
#define DK 64
#define MTOT (BB * LL)          // 4096
#define NBL  (BB * LL)          // 4096
#define RS3  (3 * DD)           // 3072

// ---------------- scratch (static device memory; no allocations) -------------
__device__ float g_meanpart[16 * DD];
__device__ float g_partial[160];
__device__ float g_Gpart[4 * DD * DD];    // syrk split-K=4 partials
__device__ float g_bqkv[3 * DD];

__device__ __align__(16) __half g_QKVh[MTOT * RS3];
__device__ __align__(16) __half g_xh[MTOT * DD];
__device__ __align__(16) __half g_Mh[MTOT * DD];
__device__ __align__(16) __half g_Ml[MTOT * DD];
__device__ __align__(16) __half g_Mth[DD * NBL];
__device__ __align__(16) __half g_Wqkvh[3 * DD * DD];
__device__ __align__(16) __half g_Woh[DD * DD];

// ---------------- small PTX helpers ------------------------------------------
__device__ __forceinline__ uint32_t smem_u32(const void* p) {
    uint32_t a;
    asm("{ .reg .u64 t; cvta.to.shared.u64 t, %1; cvt.u32.u64 %0, t; }"
        : "=r"(a) : "l"(p));
    return a;
}

__device__ __forceinline__ void cp_async16(uint32_t saddr, const void* gptr) {
    asm volatile("cp.async.ca.shared.global [%0], [%1], 16;"
                 :: "r"(saddr), "l"(gptr));
}
__device__ __forceinline__ void cp_commit() {
    asm volatile("cp.async.commit_group;" ::: "memory");
}
template <int N>
__device__ __forceinline__ void cp_wait() {
    asm volatile("cp.async.wait_group %0;" :: "n"(N) : "memory");
}

__device__ __forceinline__ void ldm_x4(uint32_t (&r)[4], uint32_t addr) {
    asm volatile("ldmatrix.sync.aligned.m8n8.x4.shared.b16 {%0,%1,%2,%3}, [%4];"
                 : "=r"(r[0]), "=r"(r[1]), "=r"(r[2]), "=r"(r[3]) : "r"(addr));
}
__device__ __forceinline__ void ldm_x4_trans(uint32_t (&r)[4], uint32_t addr) {
    asm volatile("ldmatrix.sync.aligned.m8n8.x4.trans.shared.b16 {%0,%1,%2,%3}, [%4];"
                 : "=r"(r[0]), "=r"(r[1]), "=r"(r[2]), "=r"(r[3]) : "r"(addr));
}

__device__ __forceinline__ void mma16816(float (&c)[4], const uint32_t (&a)[4],
                                         uint32_t b0, uint32_t b1) {
    asm volatile(
        "mma.sync.aligned.m16n8k16.row.col.f32.f16.f16.f32 "
        "{%0,%1,%2,%3}, {%4,%5,%6,%7}, {%8,%9}, {%0,%1,%2,%3};"
        : "+f"(c[0]), "+f"(c[1]), "+f"(c[2]), "+f"(c[3])
        : "r"(a[0]), "r"(a[1]), "r"(a[2]), "r"(a[3]), "r"(b0), "r"(b1));
}

__device__ __forceinline__ uint32_t pack_h2(__half x, __half y) {
    __half2 h = __halves2half2(x, y);
    return *(uint32_t*)&h;
}

struct __align__(8) half4 { __half a, b, c, d; };

// ---------------- prep mega-kernel: x round + weight rounds + bias concat ----
__global__ __launch_bounds__(256) void prep_kernel(
    const float* __restrict__ x,
    const float* __restrict__ Wq, const float* __restrict__ Wk,
    const float* __restrict__ Wv, const float* __restrict__ Wo,
    const float* __restrict__ bq, const float* __restrict__ bk,
    const float* __restrict__ bv,
    __half* __restrict__ xh,
    __half* __restrict__ Wqkvh, __half* __restrict__ Woh,
    float* __restrict__ bqkv)
{
    int t = blockIdx.x;
    int tid = threadIdx.x;
    if (t < 4096) {
        int i = t * 256 + tid;
        float4 v = ((const float4*)x)[i];
        half4 hv = {__float2half_rn(v.x), __float2half_rn(v.y),
                    __float2half_rn(v.z), __float2half_rn(v.w)};
        ((half4*)xh)[i] = hv;
    } else if (t < 8192) {
        int wsel = (t - 4096) >> 10;
        int blk = (t - 4096) & 1023;
        const float* src = (wsel == 0) ? Wq : (wsel == 1) ? Wk
                         : (wsel == 2) ? Wv : Wo;
        __half* dst = (wsel < 3) ? (Wqkvh + (size_t)wsel * DD * DD) : Woh;
        int i = blk * 256 + tid;
        float4 v = ((const float4*)src)[i];
        half4 hv = {__float2half_rn(v.x), __float2half_rn(v.y),
                    __float2half_rn(v.z), __float2half_rn(v.w)};
        ((half4*)dst)[i] = hv;
    } else {
        int i = (t - 8192) * 256 + tid;
        if (i < RS3) {
            const float* src = (i < DD) ? bq : (i < 2 * DD) ? bk : bv;
            bqkv[i] = src[i & (DD - 1)];
        }
    }
}

// ---------------- GEMM body ---------------------------------------------------
#define GPITCH 144
#define GTILE  (128 * GPITCH)
#define GBUF   (2 * GTILE)
#define GSMEM  (3 * GBUF)       // 110592 B

__device__ __forceinline__ void gemm_body(
    const __half* __restrict__ Ah, const __half* __restrict__ Al,
    const __half* __restrict__ Bh, const float* __restrict__ bias,
    float* __restrict__ C, float* __restrict__ Cpart,
    __half* __restrict__ Ch,
    float qscale, int qcols, int npass,
    int lda, int Ksl, int N, int M,
    int bx, int by, int split, int nsplit, char* smem)
{
    const uint32_t sbase = smem_u32(smem);
    const int tid = threadIdx.x;
    const int lane = tid & 31;
    const int wid = tid >> 5;
    const int wm = wid >> 2;
    const int wn = wid & 3;

    const __half* pA[2] = {Ah, Al};
    const int Kc = Ksl >> 6;
    const int total = npass * Kc;

    float c[4][4][4];
#pragma unroll
    for (int i = 0; i < 4; i++)
#pragma unroll
        for (int j = 0; j < 4; j++)
#pragma unroll
            for (int f = 0; f < 4; f++) c[i][j][f] = 0.0f;

    auto load_chunk = [&](int g, int buf) {
        int p = (g >= Kc) ? 1 : 0;
        int kk = g - p * Kc;
        const __half* Abase = pA[p] + (size_t)by * 128 * lda + split * Ksl + kk * 64;
        const __half* Bbase = Bh + (size_t)bx * 128 * lda + split * Ksl + kk * 64;
        uint32_t aS = sbase + buf * GBUF;
        uint32_t bS = aS + GTILE;
#pragma unroll
        for (int j = 0; j < 4; j++) {
            int lin = tid + j * 256;
            int row = lin >> 3;
            int seg = lin & 7;
            cp_async16(aS + row * GPITCH + seg * 16,
                       Abase + (size_t)row * lda + seg * 8);
            cp_async16(bS + row * GPITCH + seg * 16,
                       Bbase + (size_t)row * lda + seg * 8);
        }
        cp_commit();
    };

    load_chunk(0, 0);
    load_chunk(1, 1);

    int buf = 0;
    for (int g = 0; g < total; g++) {
        if (g == total - 1) cp_wait<0>(); else cp_wait<1>();
        __syncthreads();
        if (g + 2 < total) {
            int nb = buf + 2; if (nb >= 3) nb -= 3;
            load_chunk(g + 2, nb);
        }

        const uint32_t aS = sbase + buf * GBUF;
        const uint32_t bS = aS + GTILE;
#pragma unroll
        for (int s = 0; s < 4; s++) {
            uint32_t a[4][4];
#pragma unroll
            for (int i = 0; i < 4; i++) {
                int row = wm * 64 + i * 16 + (lane & 15);
                ldm_x4(a[i], aS + row * GPITCH + s * 32 + ((lane >> 4) * 16));
            }
            uint32_t b[2][4];
#pragma unroll
            for (int j = 0; j < 2; j++) {
                int row = wn * 32 + j * 16 + ((lane >> 4) << 3) + (lane & 7);
                int off = ((lane >> 3) & 1) * 16;
                ldm_x4(b[j], bS + row * GPITCH + s * 32 + off);
            }
#pragma unroll
            for (int i = 0; i < 4; i++) {
#pragma unroll
                for (int j = 0; j < 2; j++) {
                    mma16816(c[i][2 * j], a[i], b[j][0], b[j][1]);
                    mma16816(c[i][2 * j + 1], a[i], b[j][2], b[j][3]);
                }
            }
        }
        if (++buf == 3) buf = 0;
    }

    const bool addb = (bias != nullptr) && (nsplit == 1);
#pragma unroll
    for (int i = 0; i < 4; i++) {
        int r0 = by * 128 + wm * 64 + i * 16 + (lane >> 2);
#pragma unroll
        for (int nt = 0; nt < 4; nt++) {
            int col = bx * 128 + wn * 32 + nt * 8 + (lane & 3) * 2;
            float bx0 = 0.0f, bx1 = 0.0f;
            if (addb) { bx0 = bias[col]; bx1 = bias[col + 1]; }
            float a0 = c[i][nt][0] + bx0, a1 = c[i][nt][1] + bx1;
            float a2 = c[i][nt][2] + bx0, a3 = c[i][nt][3] + bx1;
            if (Ch) {
                float sc = (col < qcols) ? qscale : 1.0f;
                a0 *= sc; a1 *= sc; a2 *= sc; a3 *= sc;
                *(__half2*)(Ch + (size_t)r0 * N + col) =
                    __halves2half2(__float2half_rn(a0), __float2half_rn(a1));
                *(__half2*)(Ch + (size_t)(r0 + 8) * N + col) =
                    __halves2half2(__float2half_rn(a2), __float2half_rn(a3));
            } else {
                float* dst = (nsplit == 1) ? C : (Cpart + (size_t)split * M * N);
                float2 v0 = {a0, a1}, v1 = {a2, a3};
                *(float2*)(dst + (size_t)r0 * N + col) = v0;
                *(float2*)(dst + (size_t)(r0 + 8) * N + col) = v1;
            }
        }
    }
}

// ---------------- QKV GEMM kernel (single pass, fp16 out) --------------------
__global__ __launch_bounds__(256, 2) void gemm2(
    const __half* __restrict__ Ah, const __half* __restrict__ Bh,
    const float* __restrict__ bias, __half* __restrict__ Ch,
    float qscale, int qcols, int lda, int Ksl, int N)
{
    extern __shared__ __align__(16) char smem[];
    gemm_body(Ah, Ah, Bh, bias, nullptr, nullptr, Ch, qscale, qcols,
              1, lda, Ksl, N, gridDim.y * 128,
              blockIdx.x, blockIdx.y, 0, 1, smem);
}

// ---------------- fused mid: out-proj + symmetric SYRK sk4 + colmean ---------
// grid: 256 out-proj (1-pass) | 144 syrk (36 tri-tiles x 4, 1-pass) | 64 colmean
__global__ __launch_bounds__(256, 2) void fused_mid(
    const __half* __restrict__ Mh, const __half* __restrict__ Ml,
    const __half* __restrict__ Woh, const float* __restrict__ bo,
    float* __restrict__ out,
    const __half* __restrict__ Mth,
    float* __restrict__ Gpart, float* __restrict__ meanpart)
{
    extern __shared__ __align__(16) char smem[];
    int t = blockIdx.x;
    if (t < 256) {
        gemm_body(Mh, Mh, Woh, bo, out, nullptr, nullptr,
                  1.0f, 0, 1, DD, DD, DD, MTOT, t & 7, t >> 3, 0, 1, smem);
    } else if (t < 400) {
        int t2 = t - 256;
        int split = t2 / 36;
        int pair = t2 % 36;
        int ti = 0, s = pair;
        while (s >= 8 - ti) { s -= 8 - ti; ti++; }
        int tj = ti + s;
        gemm_body(Mth, Mth, Mth, nullptr, nullptr, Gpart, nullptr,
                  1.0f, 0, 1, NBL, NBL / 4, DD, DD,
                  tj, ti, split, 4, smem);
    } else {
        int idx = t - 400;
        int col = (idx & 3) * 256 + threadIdx.x;
        int seg = idx >> 2;
        float s = 0.0f;
        size_t base = (size_t)seg * 256 * DD + col;
#pragma unroll 4
        for (int r = 0; r < 256; r++) {
            size_t o = base + (size_t)r * DD;
            s += __half2float(Mh[o]) + __half2float(Ml[o]);
        }
        meanpart[seg * DD + col] = s;
    }
}

// ---------------- decov per-tile: reduce 4 Gpart slices + cov + square -------
__global__ __launch_bounds__(256) void decov_tiles(
    const float* __restrict__ Gpart, const float* __restrict__ meanpart,
    float* __restrict__ partial)
{
    __shared__ float smrow[32];
    __shared__ float smcol[128];
    __shared__ float red[256];
    int pair = blockIdx.x % 36;
    int q = blockIdx.x / 36;
    int ti = 0, s0 = pair;
    while (s0 >= 8 - ti) { s0 -= 8 - ti; ti++; }
    int tj = ti + s0;
    const float w = (ti == tj) ? 1.0f : 2.0f;
    const float invN = 1.0f / (float)NBL;

    if (threadIdx.x < 160) {
        bool isRow = threadIdx.x < 32;
        int col = isRow ? (ti * 128 + q * 32 + threadIdx.x)
                        : (tj * 128 + threadIdx.x - 32);
        float ms = 0.0f;
#pragma unroll
        for (int seg = 0; seg < 16; seg++) ms += meanpart[seg * DD + col];
        ms *= invN;
        if (isRow) smrow[threadIdx.x] = ms;
        else smcol[threadIdx.x - 32] = ms;
    }
    __syncthreads();

    int row = ti * 128 + q * 32 + (threadIdx.x >> 3);
    int c0 = tj * 128 + (threadIdx.x & 7) * 16;
    float mi = smrow[threadIdx.x >> 3];
    float acc = 0.0f;
    size_t base = (size_t)row * DD + c0;
#pragma unroll
    for (int c4 = 0; c4 < 4; c4++) {
        int col = c0 + c4 * 4;
        float4 g = *(const float4*)(Gpart + base + c4 * 4);
#pragma unroll
        for (int p = 1; p < 4; p++) {
            float4 v = *(const float4*)(Gpart + (size_t)p * DD * DD + base + c4 * 4);
            g.x += v.x; g.y += v.y; g.z += v.z; g.w += v.w;
        }
        int lc = col - tj * 128;
        float cx = g.x * invN - mi * smcol[lc];
        float cy = g.y * invN - mi * smcol[lc + 1];
        float cz = g.z * invN - mi * smcol[lc + 2];
        float cw = g.w * invN - mi * smcol[lc + 3];
        if (row == col) cx = 0.0f;
        if (row == col + 1) cy = 0.0f;
        if (row == col + 2) cz = 0.0f;
        if (row == col + 3) cw = 0.0f;
        acc += cx * cx + cy * cy + cz * cz + cw * cw;
    }
    red[threadIdx.x] = acc * w;
    __syncthreads();
    for (int off = 128; off > 0; off >>= 1) {
        if (threadIdx.x < off) red[threadIdx.x] += red[threadIdx.x + off];
        __syncthreads();
    }
    if (threadIdx.x == 0) partial[blockIdx.x] = red[0];
}

__global__ void decov_final(const float* __restrict__ partial, float* __restrict__ out)
{
    if (threadIdx.x == 0) {
        float t = 0.0f;
        for (int i = 0; i < 144; i++) t += partial[i];
        out[0] = 0.5f * t;
    }
}

// ---------------- Attention: flash + mma.sync, fp16, single-pass QK/PV -------
// S = Qh*Kh;  O = Ph*Vh.  Stage tiles: Kh, Vh.
#define AP 72
#define APB 144
#define KTB (64 * APB)
#define ASTG (2 * KTB)
#define ASMEM (3 * ASTG)        // 55296 B

__global__ __launch_bounds__(256, 2) void attn_mma(
    const __half* __restrict__ QKVh,
    __half* __restrict__ Oh, __half* __restrict__ Ol)
{
    extern __shared__ __align__(16) char smem[];
    const uint32_t sbase = smem_u32(smem);

    const int tid = threadIdx.x;
    const int lane = tid & 31;
    const int w = tid >> 5;
    const int q0 = blockIdx.x * 128;
    const int h = blockIdx.y;
    const int b = blockIdx.z;

    uint32_t Qah[4][4];
    {
        int r0 = b * LL + q0 + w * 16 + (lane >> 2);
        int cb = h * DK + (lane & 3) * 2;
#pragma unroll
        for (int s = 0; s < 4; s++)
#pragma unroll
            for (int t2 = 0; t2 < 4; t2++) {
                int rr = r0 + (t2 & 1) * 8;
                int cc = cb + s * 16 + (t2 >> 1) * 8;
                Qah[s][t2] = *(const uint32_t*)(QKVh + (size_t)rr * RS3 + cc);
            }
    }

    auto load_tile = [&](int kt, int stg) {
        uint32_t sb = sbase + stg * ASTG;
#pragma unroll
        for (int it = 0; it < 2; it++) {
            int lin = tid + it * 256;
            int row = lin >> 3;
            int seg = lin & 7;
            size_t goff = (size_t)(b * LL + kt + row) * RS3 + DD + h * DK + seg * 8;
            cp_async16(sb + row * APB + seg * 16, QKVh + goff);              // Kh
            cp_async16(sb + KTB + row * APB + seg * 16, QKVh + goff + DD);   // Vh
        }
        cp_commit();
    };

    float m0 = -1e30f, m1 = -1e30f, l0 = 0.0f, l1 = 0.0f;
    float co[8][4];
#pragma unroll
    for (int j = 0; j < 8; j++)
#pragma unroll
        for (int f = 0; f < 4; f++) co[j][f] = 0.0f;

    load_tile(0, 0);
    load_tile(64, 1);

    int buf = 0;
    for (int g = 0; g < 16; g++) {
        if (g == 15) cp_wait<0>(); else cp_wait<1>();
        __syncthreads();
        if (g + 2 < 16) {
            int nb = buf + 2; if (nb >= 3) nb -= 3;
            load_tile((g + 2) * 64, nb);
        }
        const uint32_t khs = sbase + buf * ASTG;
        const uint32_t vhs = khs + KTB;

        float sc[8][4];
#pragma unroll
        for (int j = 0; j < 8; j++)
#pragma unroll
            for (int f = 0; f < 4; f++) sc[j][f] = 0.0f;

#pragma unroll
        for (int s = 0; s < 4; s++) {
#pragma unroll
            for (int j = 0; j < 4; j++) {
                uint32_t roff = (j * 16 + ((lane >> 4) << 3) + (lane & 7)) * APB
                              + s * 32 + ((lane >> 3) & 1) * 16;
                uint32_t bh[4];
                ldm_x4(bh, khs + roff);
                mma16816(sc[2 * j],     Qah[s], bh[0], bh[1]);
                mma16816(sc[2 * j + 1], Qah[s], bh[2], bh[3]);
            }
        }

        float t0 = -1e30f, t1 = -1e30f;
#pragma unroll
        for (int j = 0; j < 8; j++) {
            t0 = fmaxf(t0, fmaxf(sc[j][0], sc[j][1]));
            t1 = fmaxf(t1, fmaxf(sc[j][2], sc[j][3]));
        }
        t0 = fmaxf(t0, __shfl_xor_sync(0xffffffffu, t0, 1));
        t0 = fmaxf(t0, __shfl_xor_sync(0xffffffffu, t0, 2));
        t1 = fmaxf(t1, __shfl_xor_sync(0xffffffffu, t1, 1));
        t1 = fmaxf(t1, __shfl_xor_sync(0xffffffffu, t1, 2));
        float mn0 = fmaxf(m0, t0), mn1 = fmaxf(m1, t1);
        float f0 = __expf(m0 - mn0), f1 = __expf(m1 - mn1);
        float rs0 = 0.0f, rs1 = 0.0f;
#pragma unroll
        for (int j = 0; j < 8; j++) {
            sc[j][0] = __expf(sc[j][0] - mn0);
            sc[j][1] = __expf(sc[j][1] - mn0);
            sc[j][2] = __expf(sc[j][2] - mn1);
            sc[j][3] = __expf(sc[j][3] - mn1);
            rs0 += sc[j][0] + sc[j][1];
            rs1 += sc[j][2] + sc[j][3];
        }
        rs0 += __shfl_xor_sync(0xffffffffu, rs0, 1);
        rs0 += __shfl_xor_sync(0xffffffffu, rs0, 2);
        rs1 += __shfl_xor_sync(0xffffffffu, rs1, 1);
        rs1 += __shfl_xor_sync(0xffffffffu, rs1, 2);
        l0 = l0 * f0 + rs0;
        l1 = l1 * f1 + rs1;
        m0 = mn0; m1 = mn1;
#pragma unroll
        for (int j = 0; j < 8; j++) {
            co[j][0] *= f0; co[j][1] *= f0;
            co[j][2] *= f1; co[j][3] *= f1;
        }

        // ---- PV single pass: O += Ph @ Vh ----
#pragma unroll
        for (int s = 0; s < 4; s++) {
            uint32_t pah[4];
#pragma unroll
            for (int t2 = 0; t2 < 4; t2++) {
                int bk = 2 * s + (t2 >> 1);
                float p0 = sc[bk][(t2 & 1) * 2];
                float p1 = sc[bk][(t2 & 1) * 2 + 1];
                pah[t2] = pack_h2(__float2half_rn(p0), __float2half_rn(p1));
            }
#pragma unroll
            for (int j = 0; j < 4; j++) {
                uint32_t roff = (s * 16 + ((lane >> 3) & 1) * 8 + (lane & 7)) * APB
                              + (j * 16 + ((lane >> 4) & 1) * 8) * 2;
                uint32_t vbh[4];
                ldm_x4_trans(vbh, vhs + roff);
                mma16816(co[2 * j],     pah, vbh[0], vbh[1]);
                mma16816(co[2 * j + 1], pah, vbh[2], vbh[3]);
            }
        }
        if (++buf == 3) buf = 0;
    }

    float inv0 = 1.0f / l0, inv1 = 1.0f / l1;
    int grow = q0 + w * 16 + (lane >> 2);
    size_t base0 = (size_t)(b * LL + grow) * DD + h * DK;
    size_t base1 = base0 + (size_t)8 * DD;
#pragma unroll
    for (int j = 0; j < 8; j++) {
        int col = j * 8 + (lane & 3) * 2;
        float a0 = co[j][0] * inv0, a1 = co[j][1] * inv0;
        float a2 = co[j][2] * inv1, a3 = co[j][3] * inv1;
        __half h0 = __float2half_rn(a0), h1 = __float2half_rn(a1);
        __half h2 = __float2half_rn(a2), h3 = __float2half_rn(a3);
        *(__half2*)(Oh + base0 + col) = __halves2half2(h0, h1);
        *(__half2*)(Oh + base1 + col) = __halves2half2(h2, h3);
        *(__half2*)(Ol + base0 + col) =
            __halves2half2(__float2half_rn(a0 - __half2float(h0)),
                           __float2half_rn(a1 - __half2float(h1)));
        *(__half2*)(Ol + base1 + col) =
            __halves2half2(__float2half_rn(a2 - __half2float(h2)),
                           __float2half_rn(a3 - __half2float(h3)));
    }
}

// ---------------- transpose: round(Mh+Ml)[NBL][DD] -> T[DD][NBL] -------------
__global__ __launch_bounds__(256) void transpose_fp16(
    const __half* __restrict__ Msh, const __half* __restrict__ Msl,
    __half* __restrict__ Th)
{
    __shared__ float tile[32][33];
    int bx = blockIdx.x;
    int by = blockIdx.y;
    int tx = threadIdx.x;
    int ty = threadIdx.y;
#pragma unroll
    for (int j = 0; j < 32; j += 8) {
        size_t off = (size_t)(by * 32 + ty + j) * DD + bx * 32 + tx;
        tile[ty + j][tx] = __half2float(Msh[off]) + __half2float(Msl[off]);
    }
    __syncthreads();
#pragma unroll
    for (int j = 0; j < 32; j += 8) {
        float v = tile[tx][ty + j];
        size_t off = (size_t)(bx * 32 + ty + j) * NBL + by * 32 + tx;
        Th[off] = __float2half_rn(v);
    }
}

// ---------------- launch ------------------------------------------------------
extern "C" void kernel_launch(void* const* d_in, const int* in_sizes, int n_in,
                              void* d_out, int out_size)
{
    const float* x  = (const float*)d_in[0];
    const float* Wq = (const float*)d_in[1];
    const float* bq = (const float*)d_in[2];
    const float* Wk = (const float*)d_in[3];
    const float* bk = (const float*)d_in[4];
    const float* Wv = (const float*)d_in[5];
    const float* bv = (const float*)d_in[6];
    const float* Wo = (const float*)d_in[7];
    const float* bo = (const float*)d_in[8];
    float* out = (float*)d_out;

    float *meanpartp, *partp, *Gpart, *bqkv;
    cudaGetSymbolAddress((void**)&meanpartp, g_meanpart);
    cudaGetSymbolAddress((void**)&partp, g_partial);
    cudaGetSymbolAddress((void**)&Gpart, g_Gpart);
    cudaGetSymbolAddress((void**)&bqkv, g_bqkv);

    __half *QKVh, *xh, *Mh, *Ml, *Mth, *Wqkvh, *Woh;
    cudaGetSymbolAddress((void**)&QKVh, g_QKVh);
    cudaGetSymbolAddress((void**)&xh, g_xh);
    cudaGetSymbolAddress((void**)&Mh, g_Mh);
    cudaGetSymbolAddress((void**)&Ml, g_Ml);
    cudaGetSymbolAddress((void**)&Mth, g_Mth);
    cudaGetSymbolAddress((void**)&Wqkvh, g_Wqkvh);
    cudaGetSymbolAddress((void**)&Woh, g_Woh);

    cudaFuncSetAttribute(gemm2, cudaFuncAttributeMaxDynamicSharedMemorySize,
                         GSMEM);
    cudaFuncSetAttribute(fused_mid, cudaFuncAttributeMaxDynamicSharedMemorySize,
                         GSMEM);
    cudaFuncSetAttribute(attn_mma, cudaFuncAttributeMaxDynamicSharedMemorySize,
                         ASMEM);

    // 1. prep
    prep_kernel<<<8204, 256>>>(x, Wq, Wk, Wv, Wo, bq, bk, bv,
                               xh, Wqkvh, Woh, bqkv);

    // 2. fused QKV projection (single pass, fp16 out; Q pre-scaled by 1/8)
    dim3 gQKV(RS3 / 128, MTOT / 128, 1);
    gemm2<<<gQKV, 256, GSMEM>>>(xh, Wqkvh, bqkv, QKVh,
                                0.125f, DD, DD, DD, RS3);

    // 3. attention
    dim3 gAttn(LL / 128, HH, BB);
    attn_mma<<<gAttn, 256, ASMEM>>>(QKVh, Mh, Ml);

    // 4. transpose of M (hi only)
    transpose_fp16<<<dim3(DD / 32, NBL / 32), dim3(32, 8)>>>(Mh, Ml, Mth);

    // 5. fused: out-proj (256, 1-pass) + SYRK sk4 (144, 1-pass) + colmean (64)
    fused_mid<<<464, 256, GSMEM>>>(Mh, Ml, Woh, bo, out,
                                   Mth, Gpart, meanpartp);

    // 6. decov tiles (reduce 4 Gpart slices + inline means + cov + square)
    decov_tiles<<<144, 256>>>(Gpart, meanpartp, partp);

    // 7. final scalar
    decov_final<<<1, 32>>>(partp, out + (out_size - 1));
}

// round 16
// speedup vs baseline: 1.9807x; 1.0316x over previous
#include <cuda_runtime.h>
#include <cuda_fp16.h>
#include <math.h>
#include <stdint.h>

// Problem constants
#define BB 4
#define LL 1024
#define DD 1024
#define HH 16
#define DK 64
#define MTOT (BB * LL)          // 4096
#define NBL  (BB * LL)          // 4096
#define RS3  (3 * DD)           // 3072

// ---------------- scratch (static device memory; no allocations) -------------
__device__ float g_meanpart[16 * DD];
__device__ float g_partial[160];
__device__ float g_Gpart[4 * DD * DD];    // syrk split-K=4 partials
__device__ float g_bqkv[3 * DD];

__device__ __align__(16) __half g_QKVh[MTOT * RS3];
__device__ __align__(16) __half g_xh[MTOT * DD];
__device__ __align__(16) __half g_Mh[MTOT * DD];
__device__ __align__(16) __half g_Mth[DD * NBL];
__device__ __align__(16) __half g_Wqkvh[3 * DD * DD];
__device__ __align__(16) __half g_Woh[DD * DD];

// ---------------- small PTX helpers ------------------------------------------
__device__ __forceinline__ uint32_t smem_u32(const void* p) {
    uint32_t a;
    asm("{ .reg .u64 t; cvta.to.shared.u64 t, %1; cvt.u32.u64 %0, t; }"
        : "=r"(a) : "l"(p));
    return a;
}

__device__ __forceinline__ void cp_async16(uint32_t saddr, const void* gptr) {
    asm volatile("cp.async.ca.shared.global [%0], [%1], 16;"
                 :: "r"(saddr), "l"(gptr));
}
__device__ __forceinline__ void cp_commit() {
    asm volatile("cp.async.commit_group;" ::: "memory");
}
template <int N>
__device__ __forceinline__ void cp_wait() {
    asm volatile("cp.async.wait_group %0;" :: "n"(N) : "memory");
}

__device__ __forceinline__ void ldm_x4(uint32_t (&r)[4], uint32_t addr) {
    asm volatile("ldmatrix.sync.aligned.m8n8.x4.shared.b16 {%0,%1,%2,%3}, [%4];"
                 : "=r"(r[0]), "=r"(r[1]), "=r"(r[2]), "=r"(r[3]) : "r"(addr));
}
__device__ __forceinline__ void ldm_x4_trans(uint32_t (&r)[4], uint32_t addr) {
    asm volatile("ldmatrix.sync.aligned.m8n8.x4.trans.shared.b16 {%0,%1,%2,%3}, [%4];"
                 : "=r"(r[0]), "=r"(r[1]), "=r"(r[2]), "=r"(r[3]) : "r"(addr));
}

__device__ __forceinline__ void mma16816(float (&c)[4], const uint32_t (&a)[4],
                                         uint32_t b0, uint32_t b1) {
    asm volatile(
        "mma.sync.aligned.m16n8k16.row.col.f32.f16.f16.f32 "
        "{%0,%1,%2,%3}, {%4,%5,%6,%7}, {%8,%9}, {%0,%1,%2,%3};"
        : "+f"(c[0]), "+f"(c[1]), "+f"(c[2]), "+f"(c[3])
        : "r"(a[0]), "r"(a[1]), "r"(a[2]), "r"(a[3]), "r"(b0), "r"(b1));
}

__device__ __forceinline__ uint32_t pack_h2(__half x, __half y) {
    __half2 h = __halves2half2(x, y);
    return *(uint32_t*)&h;
}

struct __align__(8) half4 { __half a, b, c, d; };

// ---------------- prep mega-kernel: x round + weight rounds + bias concat ----
__global__ __launch_bounds__(256) void prep_kernel(
    const float* __restrict__ x,
    const float* __restrict__ Wq, const float* __restrict__ Wk,
    const float* __restrict__ Wv, const float* __restrict__ Wo,
    const float* __restrict__ bq, const float* __restrict__ bk,
    const float* __restrict__ bv,
    __half* __restrict__ xh,
    __half* __restrict__ Wqkvh, __half* __restrict__ Woh,
    float* __restrict__ bqkv)
{
    int t = blockIdx.x;
    int tid = threadIdx.x;
    if (t < 4096) {
        int i = t * 256 + tid;
        float4 v = ((const float4*)x)[i];
        half4 hv = {__float2half_rn(v.x), __float2half_rn(v.y),
                    __float2half_rn(v.z), __float2half_rn(v.w)};
        ((half4*)xh)[i] = hv;
    } else if (t < 8192) {
        int wsel = (t - 4096) >> 10;
        int blk = (t - 4096) & 1023;
        const float* src = (wsel == 0) ? Wq : (wsel == 1) ? Wk
                         : (wsel == 2) ? Wv : Wo;
        __half* dst = (wsel < 3) ? (Wqkvh + (size_t)wsel * DD * DD) : Woh;
        int i = blk * 256 + tid;
        float4 v = ((const float4*)src)[i];
        half4 hv = {__float2half_rn(v.x), __float2half_rn(v.y),
                    __float2half_rn(v.z), __float2half_rn(v.w)};
        ((half4*)dst)[i] = hv;
    } else {
        int i = (t - 8192) * 256 + tid;
        if (i < RS3) {
            const float* src = (i < DD) ? bq : (i < 2 * DD) ? bk : bv;
            bqkv[i] = src[i & (DD - 1)];
        }
    }
}

// ---------------- GEMM body ---------------------------------------------------
#define GPITCH 144
#define GTILE  (128 * GPITCH)
#define GBUF   (2 * GTILE)
#define GSMEM  (3 * GBUF)       // 110592 B

__device__ __forceinline__ void gemm_body(
    const __half* __restrict__ Ah,
    const __half* __restrict__ Bh, const float* __restrict__ bias,
    float* __restrict__ C, float* __restrict__ Cpart,
    __half* __restrict__ Ch,
    float qscale, int qcols,
    int lda, int Ksl, int N, int M,
    int bx, int by, int split, int nsplit, char* smem)
{
    const uint32_t sbase = smem_u32(smem);
    const int tid = threadIdx.x;
    const int lane = tid & 31;
    const int wid = tid >> 5;
    const int wm = wid >> 2;
    const int wn = wid & 3;

    const int Kc = Ksl >> 6;
    const int total = Kc;

    float c[4][4][4];
#pragma unroll
    for (int i = 0; i < 4; i++)
#pragma unroll
        for (int j = 0; j < 4; j++)
#pragma unroll
            for (int f = 0; f < 4; f++) c[i][j][f] = 0.0f;

    auto load_chunk = [&](int g, int buf) {
        const __half* Abase = Ah + (size_t)by * 128 * lda + split * Ksl + g * 64;
        const __half* Bbase = Bh + (size_t)bx * 128 * lda + split * Ksl + g * 64;
        uint32_t aS = sbase + buf * GBUF;
        uint32_t bS = aS + GTILE;
#pragma unroll
        for (int j = 0; j < 4; j++) {
            int lin = tid + j * 256;
            int row = lin >> 3;
            int seg = lin & 7;
            cp_async16(aS + row * GPITCH + seg * 16,
                       Abase + (size_t)row * lda + seg * 8);
            cp_async16(bS + row * GPITCH + seg * 16,
                       Bbase + (size_t)row * lda + seg * 8);
        }
        cp_commit();
    };

    load_chunk(0, 0);
    load_chunk(1, 1);

    int buf = 0;
    for (int g = 0; g < total; g++) {
        if (g == total - 1) cp_wait<0>(); else cp_wait<1>();
        __syncthreads();
        if (g + 2 < total) {
            int nb = buf + 2; if (nb >= 3) nb -= 3;
            load_chunk(g + 2, nb);
        }

        const uint32_t aS = sbase + buf * GBUF;
        const uint32_t bS = aS + GTILE;
#pragma unroll
        for (int s = 0; s < 4; s++) {
            uint32_t a[4][4];
#pragma unroll
            for (int i = 0; i < 4; i++) {
                int row = wm * 64 + i * 16 + (lane & 15);
                ldm_x4(a[i], aS + row * GPITCH + s * 32 + ((lane >> 4) * 16));
            }
            uint32_t b[2][4];
#pragma unroll
            for (int j = 0; j < 2; j++) {
                int row = wn * 32 + j * 16 + ((lane >> 4) << 3) + (lane & 7);
                int off = ((lane >> 3) & 1) * 16;
                ldm_x4(b[j], bS + row * GPITCH + s * 32 + off);
            }
#pragma unroll
            for (int i = 0; i < 4; i++) {
#pragma unroll
                for (int j = 0; j < 2; j++) {
                    mma16816(c[i][2 * j], a[i], b[j][0], b[j][1]);
                    mma16816(c[i][2 * j + 1], a[i], b[j][2], b[j][3]);
                }
            }
        }
        if (++buf == 3) buf = 0;
    }

    const bool addb = (bias != nullptr) && (nsplit == 1);
#pragma unroll
    for (int i = 0; i < 4; i++) {
        int r0 = by * 128 + wm * 64 + i * 16 + (lane >> 2);
#pragma unroll
        for (int nt = 0; nt < 4; nt++) {
            int col = bx * 128 + wn * 32 + nt * 8 + (lane & 3) * 2;
            float bx0 = 0.0f, bx1 = 0.0f;
            if (addb) { bx0 = bias[col]; bx1 = bias[col + 1]; }
            float a0 = c[i][nt][0] + bx0, a1 = c[i][nt][1] + bx1;
            float a2 = c[i][nt][2] + bx0, a3 = c[i][nt][3] + bx1;
            if (Ch) {
                float sc = (col < qcols) ? qscale : 1.0f;
                a0 *= sc; a1 *= sc; a2 *= sc; a3 *= sc;
                *(__half2*)(Ch + (size_t)r0 * N + col) =
                    __halves2half2(__float2half_rn(a0), __float2half_rn(a1));
                *(__half2*)(Ch + (size_t)(r0 + 8) * N + col) =
                    __halves2half2(__float2half_rn(a2), __float2half_rn(a3));
            } else {
                float* dst = (nsplit == 1) ? C : (Cpart + (size_t)split * M * N);
                float2 v0 = {a0, a1}, v1 = {a2, a3};
                *(float2*)(dst + (size_t)r0 * N + col) = v0;
                *(float2*)(dst + (size_t)(r0 + 8) * N + col) = v1;
            }
        }
    }
}

// ---------------- QKV GEMM kernel (single pass, fp16 out) --------------------
__global__ __launch_bounds__(256, 2) void gemm2(
    const __half* __restrict__ Ah, const __half* __restrict__ Bh,
    const float* __restrict__ bias, __half* __restrict__ Ch,
    float qscale, int qcols, int lda, int Ksl, int N)
{
    extern __shared__ __align__(16) char smem[];
    gemm_body(Ah, Bh, bias, nullptr, nullptr, Ch, qscale, qcols,
              lda, Ksl, N, gridDim.y * 128,
              blockIdx.x, blockIdx.y, 0, 1, smem);
}

// ---------------- fused mid: out-proj + symmetric SYRK sk4 + colmean ---------
// grid: 256 out-proj | 144 syrk (36 tri-tiles x 4 splits) | 64 colmean = 464
__global__ __launch_bounds__(256, 2) void fused_mid(
    const __half* __restrict__ Mh,
    const __half* __restrict__ Woh, const float* __restrict__ bo,
    float* __restrict__ out,
    const __half* __restrict__ Mth,
    float* __restrict__ Gpart, float* __restrict__ meanpart)
{
    extern __shared__ __align__(16) char smem[];
    int t = blockIdx.x;
    if (t < 256) {
        gemm_body(Mh, Woh, bo, out, nullptr, nullptr,
                  1.0f, 0, DD, DD, DD, MTOT, t & 7, t >> 3, 0, 1, smem);
    } else if (t < 400) {
        int t2 = t - 256;
        int split = t2 / 36;
        int pair = t2 % 36;
        int ti = 0, s = pair;
        while (s >= 8 - ti) { s -= 8 - ti; ti++; }
        int tj = ti + s;
        gemm_body(Mth, Mth, nullptr, nullptr, Gpart, nullptr,
                  1.0f, 0, NBL, NBL / 4, DD, DD,
                  tj, ti, split, 4, smem);
    } else {
        int idx = t - 400;
        int col = (idx & 3) * 256 + threadIdx.x;
        int seg = idx >> 2;
        float s = 0.0f;
        size_t base = (size_t)seg * 256 * DD + col;
#pragma unroll 4
        for (int r = 0; r < 256; r++) {
            s += __half2float(Mh[base + (size_t)r * DD]);
        }
        meanpart[seg * DD + col] = s;
    }
}

// ---------------- decov per-tile: reduce 4 Gpart slices + cov + square -------
__global__ __launch_bounds__(256) void decov_tiles(
    const float* __restrict__ Gpart, const float* __restrict__ meanpart,
    float* __restrict__ partial)
{
    __shared__ float smrow[32];
    __shared__ float smcol[128];
    __shared__ float red[256];
    int pair = blockIdx.x % 36;
    int q = blockIdx.x / 36;
    int ti = 0, s0 = pair;
    while (s0 >= 8 - ti) { s0 -= 8 - ti; ti++; }
    int tj = ti + s0;
    const float w = (ti == tj) ? 1.0f : 2.0f;
    const float invN = 1.0f / (float)NBL;

    if (threadIdx.x < 160) {
        bool isRow = threadIdx.x < 32;
        int col = isRow ? (ti * 128 + q * 32 + threadIdx.x)
                        : (tj * 128 + threadIdx.x - 32);
        float ms = 0.0f;
#pragma unroll
        for (int seg = 0; seg < 16; seg++) ms += meanpart[seg * DD + col];
        ms *= invN;
        if (isRow) smrow[threadIdx.x] = ms;
        else smcol[threadIdx.x - 32] = ms;
    }
    __syncthreads();

    int row = ti * 128 + q * 32 + (threadIdx.x >> 3);
    int c0 = tj * 128 + (threadIdx.x & 7) * 16;
    float mi = smrow[threadIdx.x >> 3];
    float acc = 0.0f;
    size_t base = (size_t)row * DD + c0;
#pragma unroll
    for (int c4 = 0; c4 < 4; c4++) {
        int col = c0 + c4 * 4;
        float4 g = *(const float4*)(Gpart + base + c4 * 4);
#pragma unroll
        for (int p = 1; p < 4; p++) {
            float4 v = *(const float4*)(Gpart + (size_t)p * DD * DD + base + c4 * 4);
            g.x += v.x; g.y += v.y; g.z += v.z; g.w += v.w;
        }
        int lc = col - tj * 128;
        float cx = g.x * invN - mi * smcol[lc];
        float cy = g.y * invN - mi * smcol[lc + 1];
        float cz = g.z * invN - mi * smcol[lc + 2];
        float cw = g.w * invN - mi * smcol[lc + 3];
        if (row == col) cx = 0.0f;
        if (row == col + 1) cy = 0.0f;
        if (row == col + 2) cz = 0.0f;
        if (row == col + 3) cw = 0.0f;
        acc += cx * cx + cy * cy + cz * cz + cw * cw;
    }
    red[threadIdx.x] = acc * w;
    __syncthreads();
    for (int off = 128; off > 0; off >>= 1) {
        if (threadIdx.x < off) red[threadIdx.x] += red[threadIdx.x + off];
        __syncthreads();
    }
    if (threadIdx.x == 0) partial[blockIdx.x] = red[0];
}

__global__ void decov_final(const float* __restrict__ partial, float* __restrict__ out)
{
    if (threadIdx.x == 0) {
        float t = 0.0f;
        for (int i = 0; i < 144; i++) t += partial[i];
        out[0] = 0.5f * t;
    }
}

// ---------------- Attention: flash + mma.sync, fp16, single-pass QK/PV -------
// S = Qh*Kh;  O = Ph*Vh.  Writes Mh (row-major) and Mth (transposed) directly.
#define AP 72
#define APB 144
#define KTB (64 * APB)
#define ASTG (2 * KTB)
#define ASMEM (3 * ASTG)        // 55296 B

__global__ __launch_bounds__(256, 2) void attn_mma(
    const __half* __restrict__ QKVh,
    __half* __restrict__ Oh, __half* __restrict__ Ot)
{
    extern __shared__ __align__(16) char smem[];
    const uint32_t sbase = smem_u32(smem);

    const int tid = threadIdx.x;
    const int lane = tid & 31;
    const int w = tid >> 5;
    const int q0 = blockIdx.x * 128;
    const int h = blockIdx.y;
    const int b = blockIdx.z;

    uint32_t Qah[4][4];
    {
        int r0 = b * LL + q0 + w * 16 + (lane >> 2);
        int cb = h * DK + (lane & 3) * 2;
#pragma unroll
        for (int s = 0; s < 4; s++)
#pragma unroll
            for (int t2 = 0; t2 < 4; t2++) {
                int rr = r0 + (t2 & 1) * 8;
                int cc = cb + s * 16 + (t2 >> 1) * 8;
                Qah[s][t2] = *(const uint32_t*)(QKVh + (size_t)rr * RS3 + cc);
            }
    }

    auto load_tile = [&](int kt, int stg) {
        uint32_t sb = sbase + stg * ASTG;
#pragma unroll
        for (int it = 0; it < 2; it++) {
            int lin = tid + it * 256;
            int row = lin >> 3;
            int seg = lin & 7;
            size_t goff = (size_t)(b * LL + kt + row) * RS3 + DD + h * DK + seg * 8;
            cp_async16(sb + row * APB + seg * 16, QKVh + goff);              // Kh
            cp_async16(sb + KTB + row * APB + seg * 16, QKVh + goff + DD);   // Vh
        }
        cp_commit();
    };

    float m0 = -1e30f, m1 = -1e30f, l0 = 0.0f, l1 = 0.0f;
    float co[8][4];
#pragma unroll
    for (int j = 0; j < 8; j++)
#pragma unroll
        for (int f = 0; f < 4; f++) co[j][f] = 0.0f;

    load_tile(0, 0);
    load_tile(64, 1);

    int buf = 0;
    for (int g = 0; g < 16; g++) {
        if (g == 15) cp_wait<0>(); else cp_wait<1>();
        __syncthreads();
        if (g + 2 < 16) {
            int nb = buf + 2; if (nb >= 3) nb -= 3;
            load_tile((g + 2) * 64, nb);
        }
        const uint32_t khs = sbase + buf * ASTG;
        const uint32_t vhs = khs + KTB;

        float sc[8][4];
#pragma unroll
        for (int j = 0; j < 8; j++)
#pragma unroll
            for (int f = 0; f < 4; f++) sc[j][f] = 0.0f;

#pragma unroll
        for (int s = 0; s < 4; s++) {
#pragma unroll
            for (int j = 0; j < 4; j++) {
                uint32_t roff = (j * 16 + ((lane >> 4) << 3) + (lane & 7)) * APB
                              + s * 32 + ((lane >> 3) & 1) * 16;
                uint32_t bh[4];
                ldm_x4(bh, khs + roff);
                mma16816(sc[2 * j],     Qah[s], bh[0], bh[1]);
                mma16816(sc[2 * j + 1], Qah[s], bh[2], bh[3]);
            }
        }

        float t0 = -1e30f, t1 = -1e30f;
#pragma unroll
        for (int j = 0; j < 8; j++) {
            t0 = fmaxf(t0, fmaxf(sc[j][0], sc[j][1]));
            t1 = fmaxf(t1, fmaxf(sc[j][2], sc[j][3]));
        }
        t0 = fmaxf(t0, __shfl_xor_sync(0xffffffffu, t0, 1));
        t0 = fmaxf(t0, __shfl_xor_sync(0xffffffffu, t0, 2));
        t1 = fmaxf(t1, __shfl_xor_sync(0xffffffffu, t1, 1));
        t1 = fmaxf(t1, __shfl_xor_sync(0xffffffffu, t1, 2));
        float mn0 = fmaxf(m0, t0), mn1 = fmaxf(m1, t1);
        float f0 = __expf(m0 - mn0), f1 = __expf(m1 - mn1);
        float rs0 = 0.0f, rs1 = 0.0f;
#pragma unroll
        for (int j = 0; j < 8; j++) {
            sc[j][0] = __expf(sc[j][0] - mn0);
            sc[j][1] = __expf(sc[j][1] - mn0);
            sc[j][2] = __expf(sc[j][2] - mn1);
            sc[j][3] = __expf(sc[j][3] - mn1);
            rs0 += sc[j][0] + sc[j][1];
            rs1 += sc[j][2] + sc[j][3];
        }
        rs0 += __shfl_xor_sync(0xffffffffu, rs0, 1);
        rs0 += __shfl_xor_sync(0xffffffffu, rs0, 2);
        rs1 += __shfl_xor_sync(0xffffffffu, rs1, 1);
        rs1 += __shfl_xor_sync(0xffffffffu, rs1, 2);
        l0 = l0 * f0 + rs0;
        l1 = l1 * f1 + rs1;
        m0 = mn0; m1 = mn1;
#pragma unroll
        for (int j = 0; j < 8; j++) {
            co[j][0] *= f0; co[j][1] *= f0;
            co[j][2] *= f1; co[j][3] *= f1;
        }

        // ---- PV single pass: O += Ph @ Vh ----
#pragma unroll
        for (int s = 0; s < 4; s++) {
            uint32_t pah[4];
#pragma unroll
            for (int t2 = 0; t2 < 4; t2++) {
                int bk = 2 * s + (t2 >> 1);
                float p0 = sc[bk][(t2 & 1) * 2];
                float p1 = sc[bk][(t2 & 1) * 2 + 1];
                pah[t2] = pack_h2(__float2half_rn(p0), __float2half_rn(p1));
            }
#pragma unroll
            for (int j = 0; j < 4; j++) {
                uint32_t roff = (s * 16 + ((lane >> 3) & 1) * 8 + (lane & 7)) * APB
                              + (j * 16 + ((lane >> 4) & 1) * 8) * 2;
                uint32_t vbh[4];
                ldm_x4_trans(vbh, vhs + roff);
                mma16816(co[2 * j],     pah, vbh[0], vbh[1]);
                mma16816(co[2 * j + 1], pah, vbh[2], vbh[3]);
            }
        }
        if (++buf == 3) buf = 0;
    }

    // epilogue: normalize, write Mh (coalesced) + Mth (transposed scatter)
    float inv0 = 1.0f / l0, inv1 = 1.0f / l1;
    int grow = q0 + w * 16 + (lane >> 2);
    int row0 = b * LL + grow;
    int row1 = row0 + 8;
    size_t base0 = (size_t)row0 * DD + h * DK;
    size_t base1 = (size_t)row1 * DD + h * DK;
#pragma unroll
    for (int j = 0; j < 8; j++) {
        int col = j * 8 + (lane & 3) * 2;
        float a0 = co[j][0] * inv0, a1 = co[j][1] * inv0;
        float a2 = co[j][2] * inv1, a3 = co[j][3] * inv1;
        __half h0 = __float2half_rn(a0), h1 = __float2half_rn(a1);
        __half h2 = __float2half_rn(a2), h3 = __float2half_rn(a3);
        *(__half2*)(Oh + base0 + col) = __halves2half2(h0, h1);
        *(__half2*)(Oh + base1 + col) = __halves2half2(h2, h3);
        // transposed store: Ot[gcol * NBL + row]
        int gc = h * DK + col;
        Ot[(size_t)gc * NBL + row0] = h0;
        Ot[(size_t)(gc + 1) * NBL + row0] = h1;
        Ot[(size_t)gc * NBL + row1] = h2;
        Ot[(size_t)(gc + 1) * NBL + row1] = h3;
    }
}

// ---------------- launch ------------------------------------------------------
extern "C" void kernel_launch(void* const* d_in, const int* in_sizes, int n_in,
                              void* d_out, int out_size)
{
    const float* x  = (const float*)d_in[0];
    const float* Wq = (const float*)d_in[1];
    const float* bq = (const float*)d_in[2];
    const float* Wk = (const float*)d_in[3];
    const float* bk = (const float*)d_in[4];
    const float* Wv = (const float*)d_in[5];
    const float* bv = (const float*)d_in[6];
    const float* Wo = (const float*)d_in[7];
    const float* bo = (const float*)d_in[8];
    float* out = (float*)d_out;

    float *meanpartp, *partp, *Gpart, *bqkv;
    cudaGetSymbolAddress((void**)&meanpartp, g_meanpart);
    cudaGetSymbolAddress((void**)&partp, g_partial);
    cudaGetSymbolAddress((void**)&Gpart, g_Gpart);
    cudaGetSymbolAddress((void**)&bqkv, g_bqkv);

    __half *QKVh, *xh, *Mh, *Mth, *Wqkvh, *Woh;
    cudaGetSymbolAddress((void**)&QKVh, g_QKVh);
    cudaGetSymbolAddress((void**)&xh, g_xh);
    cudaGetSymbolAddress((void**)&Mh, g_Mh);
    cudaGetSymbolAddress((void**)&Mth, g_Mth);
    cudaGetSymbolAddress((void**)&Wqkvh, g_Wqkvh);
    cudaGetSymbolAddress((void**)&Woh, g_Woh);

    cudaFuncSetAttribute(gemm2, cudaFuncAttributeMaxDynamicSharedMemorySize,
                         GSMEM);
    cudaFuncSetAttribute(fused_mid, cudaFuncAttributeMaxDynamicSharedMemorySize,
                         GSMEM);
    cudaFuncSetAttribute(attn_mma, cudaFuncAttributeMaxDynamicSharedMemorySize,
                         ASMEM);

    // 1. prep
    prep_kernel<<<8204, 256>>>(x, Wq, Wk, Wv, Wo, bq, bk, bv,
                               xh, Wqkvh, Woh, bqkv);

    // 2. fused QKV projection (single pass, fp16 out; Q pre-scaled by 1/8)
    dim3 gQKV(RS3 / 128, MTOT / 128, 1);
    gemm2<<<gQKV, 256, GSMEM>>>(xh, Wqkvh, bqkv, QKVh,
                                0.125f, DD, DD, DD, RS3);

    // 3. attention (writes Mh + transposed Mth)
    dim3 gAttn(LL / 128, HH, BB);
    attn_mma<<<gAttn, 256, ASMEM>>>(QKVh, Mh, Mth);

    // 4. fused: out-proj (256) + SYRK sk4 (144) + colmean (64)
    fused_mid<<<464, 256, GSMEM>>>(Mh, Woh, bo, out, Mth, Gpart, meanpartp);

    // 5. decov tiles
    decov_tiles<<<144, 256>>>(Gpart, meanpartp, partp);

    // 6. final scalar
    decov_final<<<1, 32>>>(partp, out + (out_size - 1));
}

// round 17
// speedup vs baseline: 1.9865x; 1.0030x over previous
#include <cuda_runtime.h>
#include <cuda_fp16.h>
#include <math.h>
#include <stdint.h>

// Problem constants
#define BB 4
#define LL 1024
#define DD 1024
#define HH 16
#define DK 64
#define MTOT (BB * LL)          // 4096
#define NBL  (BB * LL)          // 4096
#define RS3  (3 * DD)           // 3072

// ---------------- scratch (static device memory; no allocations) -------------
__device__ float g_meanpart[16 * DD];
__device__ float g_partial[160];
__device__ float g_Gpart[4 * DD * DD];    // syrk split-K=4 partials
__device__ float g_bqkv[3 * DD];

__device__ __align__(16) __half g_QKVh[MTOT * RS3];
__device__ __align__(16) __half g_xh[MTOT * DD];
__device__ __align__(16) __half g_Mh[MTOT * DD];
__device__ __align__(16) __half g_Mth[DD * NBL];
__device__ __align__(16) __half g_Wqkvh[3 * DD * DD];
__device__ __align__(16) __half g_Woh[DD * DD];

// ---------------- small PTX helpers ------------------------------------------
__device__ __forceinline__ uint32_t smem_u32(const void* p) {
    uint32_t a;
    asm("{ .reg .u64 t; cvta.to.shared.u64 t, %1; cvt.u32.u64 %0, t; }"
        : "=r"(a) : "l"(p));
    return a;
}

__device__ __forceinline__ void cp_async16(uint32_t saddr, const void* gptr) {
    asm volatile("cp.async.ca.shared.global [%0], [%1], 16;"
                 :: "r"(saddr), "l"(gptr));
}
__device__ __forceinline__ void cp_commit() {
    asm volatile("cp.async.commit_group;" ::: "memory");
}
template <int N>
__device__ __forceinline__ void cp_wait() {
    asm volatile("cp.async.wait_group %0;" :: "n"(N) : "memory");
}

__device__ __forceinline__ void ldm_x4(uint32_t (&r)[4], uint32_t addr) {
    asm volatile("ldmatrix.sync.aligned.m8n8.x4.shared.b16 {%0,%1,%2,%3}, [%4];"
                 : "=r"(r[0]), "=r"(r[1]), "=r"(r[2]), "=r"(r[3]) : "r"(addr));
}
__device__ __forceinline__ void ldm_x4_trans(uint32_t (&r)[4], uint32_t addr) {
    asm volatile("ldmatrix.sync.aligned.m8n8.x4.trans.shared.b16 {%0,%1,%2,%3}, [%4];"
                 : "=r"(r[0]), "=r"(r[1]), "=r"(r[2]), "=r"(r[3]) : "r"(addr));
}

__device__ __forceinline__ void mma16816(float (&c)[4], const uint32_t (&a)[4],
                                         uint32_t b0, uint32_t b1) {
    asm volatile(
        "mma.sync.aligned.m16n8k16.row.col.f32.f16.f16.f32 "
        "{%0,%1,%2,%3}, {%4,%5,%6,%7}, {%8,%9}, {%0,%1,%2,%3};"
        : "+f"(c[0]), "+f"(c[1]), "+f"(c[2]), "+f"(c[3])
        : "r"(a[0]), "r"(a[1]), "r"(a[2]), "r"(a[3]), "r"(b0), "r"(b1));
}

__device__ __forceinline__ uint32_t pack_h2(__half x, __half y) {
    __half2 h = __halves2half2(x, y);
    return *(uint32_t*)&h;
}

struct __align__(8) half4 { __half a, b, c, d; };

// ---------------- prep: high-MLP fp32->fp16 conversion ------------------------
// blocks 0..511: x (1M float4, 8/thread). blocks 512..1023: weights
// (Wq|Wk|Wv -> Wqkvh, Wo -> Woh; 128 blocks each). block 1024: bias concat.
__global__ __launch_bounds__(256) void prep_kernel(
    const float* __restrict__ x,
    const float* __restrict__ Wq, const float* __restrict__ Wk,
    const float* __restrict__ Wv, const float* __restrict__ Wo,
    const float* __restrict__ bq, const float* __restrict__ bk,
    const float* __restrict__ bv,
    __half* __restrict__ xh,
    __half* __restrict__ Wqkvh, __half* __restrict__ Woh,
    float* __restrict__ bqkv)
{
    int blk = blockIdx.x;
    int tid = threadIdx.x;

    if (blk >= 1024) {
        // bias concat: 3072 floats, 12 per thread
#pragma unroll
        for (int k = 0; k < 12; k++) {
            int i = k * 256 + tid;
            const float* src = (i < DD) ? bq : (i < 2 * DD) ? bk : bv;
            bqkv[i] = src[i & (DD - 1)];
        }
        return;
    }

    const float4* src;
    half4* dst;
    int base;
    if (blk < 512) {
        src = (const float4*)x;
        dst = (half4*)xh;
        base = blk * 2048;
    } else {
        int wblk = blk - 512;
        int wsel = wblk >> 7;         // 0..3
        int rel = wblk & 127;
        src = (const float4*)((wsel == 0) ? Wq : (wsel == 1) ? Wk
                              : (wsel == 2) ? Wv : Wo);
        dst = (half4*)((wsel < 3) ? (Wqkvh + (size_t)wsel * DD * DD) : Woh);
        base = rel * 2048;
    }

    float4 v[8];
#pragma unroll
    for (int k = 0; k < 8; k++)
        v[k] = src[base + k * 256 + tid];
#pragma unroll
    for (int k = 0; k < 8; k++) {
        half4 hv = {__float2half_rn(v[k].x), __float2half_rn(v[k].y),
                    __float2half_rn(v[k].z), __float2half_rn(v[k].w)};
        dst[base + k * 256 + tid] = hv;
    }
}

// ---------------- GEMM body ---------------------------------------------------
#define GPITCH 144
#define GTILE  (128 * GPITCH)
#define GBUF   (2 * GTILE)
#define GSMEM  (3 * GBUF)       // 110592 B

__device__ __forceinline__ void gemm_body(
    const __half* __restrict__ Ah,
    const __half* __restrict__ Bh, const float* __restrict__ bias,
    float* __restrict__ C, float* __restrict__ Cpart,
    __half* __restrict__ Ch,
    float qscale, int qcols,
    int lda, int Ksl, int N, int M,
    int bx, int by, int split, int nsplit, char* smem)
{
    const uint32_t sbase = smem_u32(smem);
    const int tid = threadIdx.x;
    const int lane = tid & 31;
    const int wid = tid >> 5;
    const int wm = wid >> 2;
    const int wn = wid & 3;

    const int Kc = Ksl >> 6;
    const int total = Kc;

    float c[4][4][4];
#pragma unroll
    for (int i = 0; i < 4; i++)
#pragma unroll
        for (int j = 0; j < 4; j++)
#pragma unroll
            for (int f = 0; f < 4; f++) c[i][j][f] = 0.0f;

    auto load_chunk = [&](int g, int buf) {
        const __half* Abase = Ah + (size_t)by * 128 * lda + split * Ksl + g * 64;
        const __half* Bbase = Bh + (size_t)bx * 128 * lda + split * Ksl + g * 64;
        uint32_t aS = sbase + buf * GBUF;
        uint32_t bS = aS + GTILE;
#pragma unroll
        for (int j = 0; j < 4; j++) {
            int lin = tid + j * 256;
            int row = lin >> 3;
            int seg = lin & 7;
            cp_async16(aS + row * GPITCH + seg * 16,
                       Abase + (size_t)row * lda + seg * 8);
            cp_async16(bS + row * GPITCH + seg * 16,
                       Bbase + (size_t)row * lda + seg * 8);
        }
        cp_commit();
    };

    load_chunk(0, 0);
    load_chunk(1, 1);

    int buf = 0;
    for (int g = 0; g < total; g++) {
        if (g == total - 1) cp_wait<0>(); else cp_wait<1>();
        __syncthreads();
        if (g + 2 < total) {
            int nb = buf + 2; if (nb >= 3) nb -= 3;
            load_chunk(g + 2, nb);
        }

        const uint32_t aS = sbase + buf * GBUF;
        const uint32_t bS = aS + GTILE;
#pragma unroll
        for (int s = 0; s < 4; s++) {
            uint32_t a[4][4];
#pragma unroll
            for (int i = 0; i < 4; i++) {
                int row = wm * 64 + i * 16 + (lane & 15);
                ldm_x4(a[i], aS + row * GPITCH + s * 32 + ((lane >> 4) * 16));
            }
            uint32_t b[2][4];
#pragma unroll
            for (int j = 0; j < 2; j++) {
                int row = wn * 32 + j * 16 + ((lane >> 4) << 3) + (lane & 7);
                int off = ((lane >> 3) & 1) * 16;
                ldm_x4(b[j], bS + row * GPITCH + s * 32 + off);
            }
#pragma unroll
            for (int i = 0; i < 4; i++) {
#pragma unroll
                for (int j = 0; j < 2; j++) {
                    mma16816(c[i][2 * j], a[i], b[j][0], b[j][1]);
                    mma16816(c[i][2 * j + 1], a[i], b[j][2], b[j][3]);
                }
            }
        }
        if (++buf == 3) buf = 0;
    }

    const bool addb = (bias != nullptr) && (nsplit == 1);
#pragma unroll
    for (int i = 0; i < 4; i++) {
        int r0 = by * 128 + wm * 64 + i * 16 + (lane >> 2);
#pragma unroll
        for (int nt = 0; nt < 4; nt++) {
            int col = bx * 128 + wn * 32 + nt * 8 + (lane & 3) * 2;
            float bx0 = 0.0f, bx1 = 0.0f;
            if (addb) { bx0 = bias[col]; bx1 = bias[col + 1]; }
            float a0 = c[i][nt][0] + bx0, a1 = c[i][nt][1] + bx1;
            float a2 = c[i][nt][2] + bx0, a3 = c[i][nt][3] + bx1;
            if (Ch) {
                float sc = (col < qcols) ? qscale : 1.0f;
                a0 *= sc; a1 *= sc; a2 *= sc; a3 *= sc;
                *(__half2*)(Ch + (size_t)r0 * N + col) =
                    __halves2half2(__float2half_rn(a0), __float2half_rn(a1));
                *(__half2*)(Ch + (size_t)(r0 + 8) * N + col) =
                    __halves2half2(__float2half_rn(a2), __float2half_rn(a3));
            } else {
                float* dst = (nsplit == 1) ? C : (Cpart + (size_t)split * M * N);
                float2 v0 = {a0, a1}, v1 = {a2, a3};
                *(float2*)(dst + (size_t)r0 * N + col) = v0;
                *(float2*)(dst + (size_t)(r0 + 8) * N + col) = v1;
            }
        }
    }
}

// ---------------- QKV GEMM kernel (single pass, fp16 out) --------------------
__global__ __launch_bounds__(256, 2) void gemm2(
    const __half* __restrict__ Ah, const __half* __restrict__ Bh,
    const float* __restrict__ bias, __half* __restrict__ Ch,
    float qscale, int qcols, int lda, int Ksl, int N)
{
    extern __shared__ __align__(16) char smem[];
    gemm_body(Ah, Bh, bias, nullptr, nullptr, Ch, qscale, qcols,
              lda, Ksl, N, gridDim.y * 128,
              blockIdx.x, blockIdx.y, 0, 1, smem);
}

// ---------------- fused mid: out-proj + symmetric SYRK sk4 + colmean ---------
// grid: 256 out-proj | 144 syrk (36 tri-tiles x 4 splits) | 64 colmean = 464
__global__ __launch_bounds__(256, 2) void fused_mid(
    const __half* __restrict__ Mh,
    const __half* __restrict__ Woh, const float* __restrict__ bo,
    float* __restrict__ out,
    const __half* __restrict__ Mth,
    float* __restrict__ Gpart, float* __restrict__ meanpart)
{
    extern __shared__ __align__(16) char smem[];
    int t = blockIdx.x;
    if (t < 256) {
        gemm_body(Mh, Woh, bo, out, nullptr, nullptr,
                  1.0f, 0, DD, DD, DD, MTOT, t & 7, t >> 3, 0, 1, smem);
    } else if (t < 400) {
        int t2 = t - 256;
        int split = t2 / 36;
        int pair = t2 % 36;
        int ti = 0, s = pair;
        while (s >= 8 - ti) { s -= 8 - ti; ti++; }
        int tj = ti + s;
        gemm_body(Mth, Mth, nullptr, nullptr, Gpart, nullptr,
                  1.0f, 0, NBL, NBL / 4, DD, DD,
                  tj, ti, split, 4, smem);
    } else {
        int idx = t - 400;
        int col = (idx & 3) * 256 + threadIdx.x;
        int seg = idx >> 2;
        float s = 0.0f;
        size_t base = (size_t)seg * 256 * DD + col;
#pragma unroll 4
        for (int r = 0; r < 256; r++) {
            s += __half2float(Mh[base + (size_t)r * DD]);
        }
        meanpart[seg * DD + col] = s;
    }
}

// ---------------- decov per-tile: reduce 4 Gpart slices + cov + square -------
__global__ __launch_bounds__(256) void decov_tiles(
    const float* __restrict__ Gpart, const float* __restrict__ meanpart,
    float* __restrict__ partial)
{
    __shared__ float smrow[32];
    __shared__ float smcol[128];
    __shared__ float red[256];
    int pair = blockIdx.x % 36;
    int q = blockIdx.x / 36;
    int ti = 0, s0 = pair;
    while (s0 >= 8 - ti) { s0 -= 8 - ti; ti++; }
    int tj = ti + s0;
    const float w = (ti == tj) ? 1.0f : 2.0f;
    const float invN = 1.0f / (float)NBL;

    if (threadIdx.x < 160) {
        bool isRow = threadIdx.x < 32;
        int col = isRow ? (ti * 128 + q * 32 + threadIdx.x)
                        : (tj * 128 + threadIdx.x - 32);
        float ms = 0.0f;
#pragma unroll
        for (int seg = 0; seg < 16; seg++) ms += meanpart[seg * DD + col];
        ms *= invN;
        if (isRow) smrow[threadIdx.x] = ms;
        else smcol[threadIdx.x - 32] = ms;
    }
    __syncthreads();

    int row = ti * 128 + q * 32 + (threadIdx.x >> 3);
    int c0 = tj * 128 + (threadIdx.x & 7) * 16;
    float mi = smrow[threadIdx.x >> 3];
    float acc = 0.0f;
    size_t base = (size_t)row * DD + c0;
#pragma unroll
    for (int c4 = 0; c4 < 4; c4++) {
        int col = c0 + c4 * 4;
        float4 g = *(const float4*)(Gpart + base + c4 * 4);
#pragma unroll
        for (int p = 1; p < 4; p++) {
            float4 v = *(const float4*)(Gpart + (size_t)p * DD * DD + base + c4 * 4);
            g.x += v.x; g.y += v.y; g.z += v.z; g.w += v.w;
        }
        int lc = col - tj * 128;
        float cx = g.x * invN - mi * smcol[lc];
        float cy = g.y * invN - mi * smcol[lc + 1];
        float cz = g.z * invN - mi * smcol[lc + 2];
        float cw = g.w * invN - mi * smcol[lc + 3];
        if (row == col) cx = 0.0f;
        if (row == col + 1) cy = 0.0f;
        if (row == col + 2) cz = 0.0f;
        if (row == col + 3) cw = 0.0f;
        acc += cx * cx + cy * cy + cz * cz + cw * cw;
    }
    red[threadIdx.x] = acc * w;
    __syncthreads();
    for (int off = 128; off > 0; off >>= 1) {
        if (threadIdx.x < off) red[threadIdx.x] += red[threadIdx.x + off];
        __syncthreads();
    }
    if (threadIdx.x == 0) partial[blockIdx.x] = red[0];
}

__global__ void decov_final(const float* __restrict__ partial, float* __restrict__ out)
{
    if (threadIdx.x == 0) {
        float t = 0.0f;
        for (int i = 0; i < 144; i++) t += partial[i];
        out[0] = 0.5f * t;
    }
}

// ---------------- Attention: flash + mma.sync, fp16, single-pass QK/PV -------
// S = Qh*Kh;  O = Ph*Vh.  Writes Mh (row-major) and Mth (transposed) directly.
#define AP 72
#define APB 144
#define KTB (64 * APB)
#define ASTG (2 * KTB)
#define ASMEM (3 * ASTG)        // 55296 B

__global__ __launch_bounds__(256, 2) void attn_mma(
    const __half* __restrict__ QKVh,
    __half* __restrict__ Oh, __half* __restrict__ Ot)
{
    extern __shared__ __align__(16) char smem[];
    const uint32_t sbase = smem_u32(smem);

    const int tid = threadIdx.x;
    const int lane = tid & 31;
    const int w = tid >> 5;
    const int q0 = blockIdx.x * 128;
    const int h = blockIdx.y;
    const int b = blockIdx.z;

    uint32_t Qah[4][4];
    {
        int r0 = b * LL + q0 + w * 16 + (lane >> 2);
        int cb = h * DK + (lane & 3) * 2;
#pragma unroll
        for (int s = 0; s < 4; s++)
#pragma unroll
            for (int t2 = 0; t2 < 4; t2++) {
                int rr = r0 + (t2 & 1) * 8;
                int cc = cb + s * 16 + (t2 >> 1) * 8;
                Qah[s][t2] = *(const uint32_t*)(QKVh + (size_t)rr * RS3 + cc);
            }
    }

    auto load_tile = [&](int kt, int stg) {
        uint32_t sb = sbase + stg * ASTG;
#pragma unroll
        for (int it = 0; it < 2; it++) {
            int lin = tid + it * 256;
            int row = lin >> 3;
            int seg = lin & 7;
            size_t goff = (size_t)(b * LL + kt + row) * RS3 + DD + h * DK + seg * 8;
            cp_async16(sb + row * APB + seg * 16, QKVh + goff);              // Kh
            cp_async16(sb + KTB + row * APB + seg * 16, QKVh + goff + DD);   // Vh
        }
        cp_commit();
    };

    float m0 = -1e30f, m1 = -1e30f, l0 = 0.0f, l1 = 0.0f;
    float co[8][4];
#pragma unroll
    for (int j = 0; j < 8; j++)
#pragma unroll
        for (int f = 0; f < 4; f++) co[j][f] = 0.0f;

    load_tile(0, 0);
    load_tile(64, 1);

    int buf = 0;
    for (int g = 0; g < 16; g++) {
        if (g == 15) cp_wait<0>(); else cp_wait<1>();
        __syncthreads();
        if (g + 2 < 16) {
            int nb = buf + 2; if (nb >= 3) nb -= 3;
            load_tile((g + 2) * 64, nb);
        }
        const uint32_t khs = sbase + buf * ASTG;
        const uint32_t vhs = khs + KTB;

        float sc[8][4];
#pragma unroll
        for (int j = 0; j < 8; j++)
#pragma unroll
            for (int f = 0; f < 4; f++) sc[j][f] = 0.0f;

#pragma unroll
        for (int s = 0; s < 4; s++) {
#pragma unroll
            for (int j = 0; j < 4; j++) {
                uint32_t roff = (j * 16 + ((lane >> 4) << 3) + (lane & 7)) * APB
                              + s * 32 + ((lane >> 3) & 1) * 16;
                uint32_t bh[4];
                ldm_x4(bh, khs + roff);
                mma16816(sc[2 * j],     Qah[s], bh[0], bh[1]);
                mma16816(sc[2 * j + 1], Qah[s], bh[2], bh[3]);
            }
        }

        float t0 = -1e30f, t1 = -1e30f;
#pragma unroll
        for (int j = 0; j < 8; j++) {
            t0 = fmaxf(t0, fmaxf(sc[j][0], sc[j][1]));
            t1 = fmaxf(t1, fmaxf(sc[j][2], sc[j][3]));
        }
        t0 = fmaxf(t0, __shfl_xor_sync(0xffffffffu, t0, 1));
        t0 = fmaxf(t0, __shfl_xor_sync(0xffffffffu, t0, 2));
        t1 = fmaxf(t1, __shfl_xor_sync(0xffffffffu, t1, 1));
        t1 = fmaxf(t1, __shfl_xor_sync(0xffffffffu, t1, 2));
        float mn0 = fmaxf(m0, t0), mn1 = fmaxf(m1, t1);
        float f0 = __expf(m0 - mn0), f1 = __expf(m1 - mn1);
        float rs0 = 0.0f, rs1 = 0.0f;
#pragma unroll
        for (int j = 0; j < 8; j++) {
            sc[j][0] = __expf(sc[j][0] - mn0);
            sc[j][1] = __expf(sc[j][1] - mn0);
            sc[j][2] = __expf(sc[j][2] - mn1);
            sc[j][3] = __expf(sc[j][3] - mn1);
            rs0 += sc[j][0] + sc[j][1];
            rs1 += sc[j][2] + sc[j][3];
        }
        rs0 += __shfl_xor_sync(0xffffffffu, rs0, 1);
        rs0 += __shfl_xor_sync(0xffffffffu, rs0, 2);
        rs1 += __shfl_xor_sync(0xffffffffu, rs1, 1);
        rs1 += __shfl_xor_sync(0xffffffffu, rs1, 2);
        l0 = l0 * f0 + rs0;
        l1 = l1 * f1 + rs1;
        m0 = mn0; m1 = mn1;
#pragma unroll
        for (int j = 0; j < 8; j++) {
            co[j][0] *= f0; co[j][1] *= f0;
            co[j][2] *= f1; co[j][3] *= f1;
        }

        // ---- PV single pass: O += Ph @ Vh ----
#pragma unroll
        for (int s = 0; s < 4; s++) {
            uint32_t pah[4];
#pragma unroll
            for (int t2 = 0; t2 < 4; t2++) {
                int bk = 2 * s + (t2 >> 1);
                float p0 = sc[bk][(t2 & 1) * 2];
                float p1 = sc[bk][(t2 & 1) * 2 + 1];
                pah[t2] = pack_h2(__float2half_rn(p0), __float2half_rn(p1));
            }
#pragma unroll
            for (int j = 0; j < 4; j++) {
                uint32_t roff = (s * 16 + ((lane >> 3) & 1) * 8 + (lane & 7)) * APB
                              + (j * 16 + ((lane >> 4) & 1) * 8) * 2;
                uint32_t vbh[4];
                ldm_x4_trans(vbh, vhs + roff);
                mma16816(co[2 * j],     pah, vbh[0], vbh[1]);
                mma16816(co[2 * j + 1], pah, vbh[2], vbh[3]);
            }
        }
        if (++buf == 3) buf = 0;
    }

    // epilogue: normalize, write Mh (coalesced) + Mth (transposed scatter)
    float inv0 = 1.0f / l0, inv1 = 1.0f / l1;
    int grow = q0 + w * 16 + (lane >> 2);
    int row0 = b * LL + grow;
    int row1 = row0 + 8;
    size_t base0 = (size_t)row0 * DD + h * DK;
    size_t base1 = (size_t)row1 * DD + h * DK;
#pragma unroll
    for (int j = 0; j < 8; j++) {
        int col = j * 8 + (lane & 3) * 2;
        float a0 = co[j][0] * inv0, a1 = co[j][1] * inv0;
        float a2 = co[j][2] * inv1, a3 = co[j][3] * inv1;
        __half h0 = __float2half_rn(a0), h1 = __float2half_rn(a1);
        __half h2 = __float2half_rn(a2), h3 = __float2half_rn(a3);
        *(__half2*)(Oh + base0 + col) = __halves2half2(h0, h1);
        *(__half2*)(Oh + base1 + col) = __halves2half2(h2, h3);
        // transposed store: Ot[gcol * NBL + row]
        int gc = h * DK + col;
        Ot[(size_t)gc * NBL + row0] = h0;
        Ot[(size_t)(gc + 1) * NBL + row0] = h1;
        Ot[(size_t)gc * NBL + row1] = h2;
        Ot[(size_t)(gc + 1) * NBL + row1] = h3;
    }
}

// ---------------- launch ------------------------------------------------------
extern "C" void kernel_launch(void* const* d_in, const int* in_sizes, int n_in,
                              void* d_out, int out_size)
{
    const float* x  = (const float*)d_in[0];
    const float* Wq = (const float*)d_in[1];
    const float* bq = (const float*)d_in[2];
    const float* Wk = (const float*)d_in[3];
    const float* bk = (const float*)d_in[4];
    const float* Wv = (const float*)d_in[5];
    const float* bv = (const float*)d_in[6];
    const float* Wo = (const float*)d_in[7];
    const float* bo = (const float*)d_in[8];
    float* out = (float*)d_out;

    float *meanpartp, *partp, *Gpart, *bqkv;
    cudaGetSymbolAddress((void**)&meanpartp, g_meanpart);
    cudaGetSymbolAddress((void**)&partp, g_partial);
    cudaGetSymbolAddress((void**)&Gpart, g_Gpart);
    cudaGetSymbolAddress((void**)&bqkv, g_bqkv);

    __half *QKVh, *xh, *Mh, *Mth, *Wqkvh, *Woh;
    cudaGetSymbolAddress((void**)&QKVh, g_QKVh);
    cudaGetSymbolAddress((void**)&xh, g_xh);
    cudaGetSymbolAddress((void**)&Mh, g_Mh);
    cudaGetSymbolAddress((void**)&Mth, g_Mth);
    cudaGetSymbolAddress((void**)&Wqkvh, g_Wqkvh);
    cudaGetSymbolAddress((void**)&Woh, g_Woh);

    cudaFuncSetAttribute(gemm2, cudaFuncAttributeMaxDynamicSharedMemorySize,
                         GSMEM);
    cudaFuncSetAttribute(fused_mid, cudaFuncAttributeMaxDynamicSharedMemorySize,
                         GSMEM);
    cudaFuncSetAttribute(attn_mma, cudaFuncAttributeMaxDynamicSharedMemorySize,
                         ASMEM);

    // 1. prep (high-MLP conversion)
    prep_kernel<<<1025, 256>>>(x, Wq, Wk, Wv, Wo, bq, bk, bv,
                               xh, Wqkvh, Woh, bqkv);

    // 2. fused QKV projection (single pass, fp16 out; Q pre-scaled by 1/8)
    dim3 gQKV(RS3 / 128, MTOT / 128, 1);
    gemm2<<<gQKV, 256, GSMEM>>>(xh, Wqkvh, bqkv, QKVh,
                                0.125f, DD, DD, DD, RS3);

    // 3. attention (writes Mh + transposed Mth)
    dim3 gAttn(LL / 128, HH, BB);
    attn_mma<<<gAttn, 256, ASMEM>>>(QKVh, Mh, Mth);

    // 4. fused: out-proj (256) + SYRK sk4 (144) + colmean (64)
    fused_mid<<<464, 256, GSMEM>>>(Mh, Woh, bo, out, Mth, Gpart, meanpartp);

    // 5. decov tiles
    decov_tiles<<<144, 256>>>(Gpart, meanpartp, partp);

    // 6. final scalar
    decov_final<<<1, 32>>>(partp, out + (out_size - 1));
}